// round 8
// baseline (speedup 1.0000x reference)
#include <cuda_runtime.h>
#include <cuda_bf16.h>
#include <math.h>
#include <stdint.h>

#define NB 2
#define NS 2048
#define ND 768
#define NH 12
#define NHD 64
#define NQKV 2304
#define NROWS 4096   // NB*NS

#define NEG_BIG (-1e30f)
#define PAD 68

// ---------------- scratch (device globals; allocation-free) -----------------
__device__ float g_qkv[(size_t)NROWS * NQKV];                 // 37.7 MB
__device__ __nv_bfloat16 g_xh[(size_t)NROWS * ND];            // x hi
__device__ __nv_bfloat16 g_xl[(size_t)NROWS * ND];            // x lo
__device__ __nv_bfloat16 g_ah[(size_t)NROWS * ND];            // attn hi
__device__ __nv_bfloat16 g_al[(size_t)NROWS * ND];            // attn lo
__device__ __nv_bfloat16 g_wqh[(size_t)NQKV * ND];            // Wqkv^T hi [N][K]
__device__ __nv_bfloat16 g_wql[(size_t)NQKV * ND];
__device__ __nv_bfloat16 g_woh[(size_t)ND * ND];              // Wout^T hi [N][K]
__device__ __nv_bfloat16 g_wol[(size_t)ND * ND];

__device__ __forceinline__ uint32_t smem_u32(const void* p) {
    uint32_t a;
    asm("{ .reg .u64 t; cvta.to.shared.u64 t, %1; cvt.u32.u64 %0, t; }" : "=r"(a) : "l"(p));
    return a;
}

__device__ __forceinline__ void mma_bf16(float c[4], const uint32_t a[4], const uint32_t b[2]) {
    asm volatile(
        "mma.sync.aligned.m16n8k16.row.col.f32.bf16.bf16.f32 "
        "{%0,%1,%2,%3}, {%4,%5,%6,%7}, {%8,%9}, {%0,%1,%2,%3};"
        : "+f"(c[0]), "+f"(c[1]), "+f"(c[2]), "+f"(c[3])
        : "r"(a[0]), "r"(a[1]), "r"(a[2]), "r"(a[3]), "r"(b[0]), "r"(b[1]));
}

#define LDSM4(r, addr) \
    asm volatile("ldmatrix.sync.aligned.m8n8.x4.shared.b16 {%0,%1,%2,%3}, [%4];" \
                 : "=r"((r)[0]), "=r"((r)[1]), "=r"((r)[2]), "=r"((r)[3]) : "r"(addr))

#define CP16(dst, src) \
    asm volatile("cp.async.cg.shared.global [%0], [%1], 16;" :: "r"(dst), "l"(src))
#define CP_COMMIT() asm volatile("cp.async.commit_group;")
#define CP_WAIT1()  asm volatile("cp.async.wait_group 1;")
#define CP_WAIT0()  asm volatile("cp.async.wait_group 0;")

// ---------------------------------------------------------------------------
// Convert fp32 row-major [R][C] -> bf16 hi/lo planes (same layout).
// ---------------------------------------------------------------------------
__global__ void conv_rows_kernel(const float* __restrict__ in,
                                 __nv_bfloat16* __restrict__ oh,
                                 __nv_bfloat16* __restrict__ ol, int n2)
{
    int i = blockIdx.x * blockDim.x + threadIdx.x;
    if (i >= n2) return;
    float2 v = ((const float2*)in)[i];
    __nv_bfloat16 h0 = __float2bfloat16_rn(v.x);
    __nv_bfloat16 h1 = __float2bfloat16_rn(v.y);
    __nv_bfloat16 l0 = __float2bfloat16_rn(v.x - __bfloat162float(h0));
    __nv_bfloat16 l1 = __float2bfloat16_rn(v.y - __bfloat162float(h1));
    ((__nv_bfloat162*)oh)[i] = __nv_bfloat162(h0, h1);
    ((__nv_bfloat162*)ol)[i] = __nv_bfloat162(l0, l1);
}

// ---------------------------------------------------------------------------
// Transpose-convert: W fp32 [K][N] -> out bf16 [N][K] hi/lo planes.
// grid (N/32, K/32), block (32, 8).
// ---------------------------------------------------------------------------
__global__ void convT_kernel(const float* __restrict__ W,
                             __nv_bfloat16* __restrict__ oh,
                             __nv_bfloat16* __restrict__ ol, int K, int N)
{
    __shared__ float t[32][33];
    const int n0 = blockIdx.x * 32, k0 = blockIdx.y * 32;
#pragma unroll
    for (int i = 0; i < 4; i++) {
        int k = threadIdx.y + i * 8;
        t[k][threadIdx.x] = W[(size_t)(k0 + k) * N + n0 + threadIdx.x];
    }
    __syncthreads();
#pragma unroll
    for (int i = 0; i < 4; i++) {
        int n = threadIdx.y + i * 8;
        float x = t[threadIdx.x][n];
        __nv_bfloat16 h = __float2bfloat16_rn(x);
        __nv_bfloat16 l = __float2bfloat16_rn(x - __bfloat162float(h));
        size_t o = (size_t)(n0 + n) * K + k0 + threadIdx.x;
        oh[o] = h;
        ol[o] = l;
    }
}

// ---------------------------------------------------------------------------
// Tensor-core GEMM + bias via mma.sync (bf16x3 split):
//   C[M,N] = Ah@Bh^T + Ah@Bl^T + Al@Bh^T + bias      (fp32 accum/output)
// A planes: [M][K] bf16, B planes: [N][K] bf16 (pre-transposed weights).
// Block 128x128, BK=64, 8 warps, warp tile 64x32 (4 m16 x 4 n8).
// cp.async double-buffered: copy chunk k+1 overlaps MMA of chunk k.
// Smem rows padded to 72 bf16 (144 B) -> conflict-free ldmatrix.
// ---------------------------------------------------------------------------
#define SROW 144              // bytes per smem row (72 bf16)
#define PLANE (128 * SROW)    // 18432 B
#define STAGE (4 * PLANE)     // 73728 B

__global__ __launch_bounds__(256)
void gemm_mma_kernel(const __nv_bfloat16* __restrict__ Ah, const __nv_bfloat16* __restrict__ Al,
                     const __nv_bfloat16* __restrict__ Bh, const __nv_bfloat16* __restrict__ Bl,
                     const float* __restrict__ bias, float* __restrict__ C,
                     int M, int N, int K)
{
    extern __shared__ __align__(16) char sm[];

    const int tid = threadIdx.x;
    const int w   = tid >> 5;
    const int l   = tid & 31;
    const int row0 = blockIdx.y * 128;
    const int col0 = blockIdx.x * 128;
    const int m0w = (w >> 2) * 64;   // warp M origin in tile
    const int n0w = (w & 3) * 32;    // warp N origin in tile

    float acc[4][4][4];
#pragma unroll
    for (int i = 0; i < 4; i++)
#pragma unroll
        for (int j = 0; j < 4; j++)
#pragma unroll
            for (int q = 0; q < 4; q++) acc[i][j][q] = 0.f;

    const uint32_t sb = smem_u32(sm);
    // ldmatrix lane offsets (relative to stage base)
    const uint32_t aRelH = (uint32_t)(m0w + (l & 15)) * SROW + (uint32_t)(((l >> 4) << 3) * 2);
    const uint32_t aRelL = aRelH + PLANE;
    const int bg = l >> 3;
    const uint32_t bRelH = 2u * PLANE
        + (uint32_t)(n0w + (bg >> 1) * 8 + (l & 7)) * SROW + (uint32_t)(((bg & 1) * 8) * 2);
    const uint32_t bRelL = bRelH + PLANE;

    // fill assignment: each thread copies 4x16B per plane
    const int fr = tid >> 1;       // row 0..127
    const int fh = tid & 1;        // half row (64 B)
    const __nv_bfloat16* gAh = Ah + (size_t)(row0 + fr) * K + fh * 32;
    const __nv_bfloat16* gAl = Al + (size_t)(row0 + fr) * K + fh * 32;
    const __nv_bfloat16* gBh = Bh + (size_t)(col0 + fr) * K + fh * 32;
    const __nv_bfloat16* gBl = Bl + (size_t)(col0 + fr) * K + fh * 32;
    const uint32_t dRel = (uint32_t)(fr * SROW + fh * 64);

    const int nchunks = K >> 6;

    auto issue = [&](int kc, int s) {
        const int ke = kc << 6;
        const uint32_t st = sb + (uint32_t)s * STAGE + dRel;
#pragma unroll
        for (int i = 0; i < 4; i++) CP16(st + i * 16,             gAh + ke + i * 8);
#pragma unroll
        for (int i = 0; i < 4; i++) CP16(st + PLANE + i * 16,     gAl + ke + i * 8);
#pragma unroll
        for (int i = 0; i < 4; i++) CP16(st + 2 * PLANE + i * 16, gBh + ke + i * 8);
#pragma unroll
        for (int i = 0; i < 4; i++) CP16(st + 3 * PLANE + i * 16, gBl + ke + i * 8);
        CP_COMMIT();
    };

    issue(0, 0);

    for (int kc = 0; kc < nchunks; kc++) {
        const int s = kc & 1;
        if (kc + 1 < nchunks) {
            issue(kc + 1, s ^ 1);
            CP_WAIT1();
        } else {
            CP_WAIT0();
        }
        __syncthreads();

        const uint32_t stb = sb + (uint32_t)s * STAGE;
#pragma unroll
        for (int ks = 0; ks < 4; ks++) {
            const uint32_t kso = (uint32_t)(ks * 32);   // 16 bf16 = 32 B
            uint32_t ah[4][4], al[4][4];
#pragma unroll
            for (int mt = 0; mt < 4; mt++) {
                LDSM4(ah[mt], stb + aRelH + mt * (16 * SROW) + kso);
                LDSM4(al[mt], stb + aRelL + mt * (16 * SROW) + kso);
            }
            uint32_t bh[4][2], bl[4][2];
#pragma unroll
            for (int jp = 0; jp < 2; jp++) {
                uint32_t r[4];
                LDSM4(r, stb + bRelH + jp * (16 * SROW) + kso);
                bh[2 * jp][0] = r[0]; bh[2 * jp][1] = r[1];
                bh[2 * jp + 1][0] = r[2]; bh[2 * jp + 1][1] = r[3];
                LDSM4(r, stb + bRelL + jp * (16 * SROW) + kso);
                bl[2 * jp][0] = r[0]; bl[2 * jp][1] = r[1];
                bl[2 * jp + 1][0] = r[2]; bl[2 * jp + 1][1] = r[3];
            }
#pragma unroll
            for (int mt = 0; mt < 4; mt++)
#pragma unroll
                for (int nt = 0; nt < 4; nt++)
                    mma_bf16(acc[mt][nt], ah[mt], bh[nt]);
#pragma unroll
            for (int mt = 0; mt < 4; mt++)
#pragma unroll
                for (int nt = 0; nt < 4; nt++)
                    mma_bf16(acc[mt][nt], ah[mt], bl[nt]);
#pragma unroll
            for (int mt = 0; mt < 4; mt++)
#pragma unroll
                for (int nt = 0; nt < 4; nt++)
                    mma_bf16(acc[mt][nt], al[mt], bh[nt]);
        }
        __syncthreads();
    }

    // epilogue: bias + direct stores (float2, frag layout)
    float2 bb[4];
#pragma unroll
    for (int nt = 0; nt < 4; nt++) {
        int cg = col0 + n0w + 8 * nt + 2 * (l & 3);
        bb[nt] = make_float2(bias[cg], bias[cg + 1]);
    }
#pragma unroll
    for (int mt = 0; mt < 4; mt++) {
        int rg = row0 + m0w + 16 * mt + (l >> 2);
#pragma unroll
        for (int nt = 0; nt < 4; nt++) {
            int cg = col0 + n0w + 8 * nt + 2 * (l & 3);
            *(float2*)&C[(size_t)rg * N + cg] =
                make_float2(acc[mt][nt][0] + bb[nt].x, acc[mt][nt][1] + bb[nt].y);
            *(float2*)&C[(size_t)(rg + 8) * N + cg] =
                make_float2(acc[mt][nt][2] + bb[nt].x, acc[mt][nt][3] + bb[nt].y);
        }
    }
}

// ---------------------------------------------------------------------------
// RoPE in-place on q and k parts of qkv. One thread per (b,s,h,pair).
// ---------------------------------------------------------------------------
__global__ void rope_kernel(float* __restrict__ qkv, const int* __restrict__ layer_p)
{
    int idx = blockIdx.x * blockDim.x + threadIdx.x;
    if (idx >= NROWS * NH * 32) return;
    int i  = idx & 31;
    int hh = (idx >> 5) % NH;
    int bs = (idx >> 5) / NH;
    int s  = bs & (NS - 1);

    bool is_global = (layer_p[0] % 3) == 0;
    float theta = is_global ? 160000.f : 10000.f;
    float freq  = powf(theta, -(float)(2 * i) / 64.f);
    float ang   = (float)s * freq;
    float sn, cs;
    sincosf(ang, &sn, &cs);

    size_t base = (size_t)bs * NQKV + hh * NHD + 2 * i;
    float qe = qkv[base], qo = qkv[base + 1];
    qkv[base]      = qe * cs - qo * sn;
    qkv[base + 1]  = qo * cs + qe * sn;
    float ke = qkv[base + ND], ko = qkv[base + ND + 1];
    qkv[base + ND]     = ke * cs - ko * sn;
    qkv[base + ND + 1] = ko * cs + ke * sn;
}

// ---------------------------------------------------------------------------
// Flash-style banded attention; epilogue emits bf16 hi/lo planes directly.
// ---------------------------------------------------------------------------
__global__ __launch_bounds__(256, 1)
void attn_kernel(const float* __restrict__ qkv,
                 __nv_bfloat16* __restrict__ aoh, __nv_bfloat16* __restrict__ aol,
                 const int* __restrict__ layer_p)
{
    extern __shared__ float smf[];
    float* Qt    = smf;
    float* Ks    = Qt + 64 * PAD;
    float* Vs    = Ks + 64 * PAD;
    float* row_m = Vs + 64 * PAD;
    float* row_l = row_m + 64;
    float* row_s = row_l + 64;

    const int tid = threadIdx.x;
    const int blk = blockIdx.x;
    const int qt  = blk & 31;
    const int hh  = (blk >> 5) % NH;
    const int b   = blk / (32 * NH);
    const bool is_global = (layer_p[0] % 3) == 0;
    const int q0 = qt * 64;

    {
        int r = tid >> 2;
        int part = tid & 3;
        const float* src = qkv + (size_t)(b * NS + q0 + r) * NQKV + hh * NHD + part * 16;
#pragma unroll
        for (int v = 0; v < 4; v++) {
            float4 q4 = *(const float4*)(src + v * 4);
            int d0 = part * 16 + v * 4;
            Qt[(d0 + 0) * PAD + r] = q4.x * 0.125f;
            Qt[(d0 + 1) * PAD + r] = q4.y * 0.125f;
            Qt[(d0 + 2) * PAD + r] = q4.z * 0.125f;
            Qt[(d0 + 3) * PAD + r] = q4.w * 0.125f;
        }
    }
    if (tid < 64) { row_m[tid] = NEG_BIG; row_l[tid] = 0.f; }

    const int tr = (tid >> 4) * 4;
    const int tc = (tid & 15) * 4;
    float acc[4][4];
#pragma unroll
    for (int i = 0; i < 4; i++)
#pragma unroll
        for (int j = 0; j < 4; j++) acc[i][j] = 0.f;

    const int kt0 = is_global ? 0 : max(0, qt - 2);
    const int kt1 = is_global ? 31 : min(31, qt + 2);

    for (int kt = kt0; kt <= kt1; kt++) {
        __syncthreads();
        {
            int r = tid >> 2;
            int part = tid & 3;
            const float* ksrc = qkv + (size_t)(b * NS + kt * 64 + r) * NQKV + ND + hh * NHD + part * 16;
#pragma unroll
            for (int v = 0; v < 4; v++) {
                int d0 = part * 16 + v * 4;
                float4 k4 = *(const float4*)(ksrc + v * 4);
                Ks[(d0 + 0) * PAD + r] = k4.x;
                Ks[(d0 + 1) * PAD + r] = k4.y;
                Ks[(d0 + 2) * PAD + r] = k4.z;
                Ks[(d0 + 3) * PAD + r] = k4.w;
                *(float4*)&Vs[r * PAD + d0] = *(const float4*)(ksrc + ND + v * 4);
            }
        }
        __syncthreads();

        float sv[4][4];
#pragma unroll
        for (int i = 0; i < 4; i++)
#pragma unroll
            for (int j = 0; j < 4; j++) sv[i][j] = 0.f;
#pragma unroll 8
        for (int d = 0; d < 64; d++) {
            float qa[4], kb[4];
            *(float4*)qa = *(const float4*)&Qt[d * PAD + tr];
            *(float4*)kb = *(const float4*)&Ks[d * PAD + tc];
#pragma unroll
            for (int i = 0; i < 4; i++)
#pragma unroll
                for (int j = 0; j < 4; j++)
                    sv[i][j] = fmaf(qa[i], kb[j], sv[i][j]);
        }
        if (!is_global) {
#pragma unroll
            for (int i = 0; i < 4; i++)
#pragma unroll
                for (int j = 0; j < 4; j++) {
                    int dlt = (q0 + tr + i) - (kt * 64 + tc + j);
                    if (dlt < 0) dlt = -dlt;
                    if (dlt > 128) sv[i][j] = NEG_BIG;
                }
        }
        __syncthreads();
#pragma unroll
        for (int i = 0; i < 4; i++)
#pragma unroll
            for (int j = 0; j < 4; j++)
                Ks[(tr + i) * PAD + tc + j] = sv[i][j];
        __syncthreads();

        {
            int r  = tid >> 2;
            int qd = tid & 3;
            float* Pr = &Ks[r * PAD + qd * 16];
            float mloc = NEG_BIG;
#pragma unroll
            for (int c = 0; c < 16; c++) mloc = fmaxf(mloc, Pr[c]);
            mloc = fmaxf(mloc, __shfl_xor_sync(0xffffffffu, mloc, 1));
            mloc = fmaxf(mloc, __shfl_xor_sync(0xffffffffu, mloc, 2));
            float m_old = row_m[r];
            float m_new = fmaxf(m_old, mloc);
            float ls = 0.f;
#pragma unroll
            for (int c = 0; c < 16; c++) {
                float e = expf(Pr[c] - m_new);
                Pr[c] = e;
                ls += e;
            }
            ls += __shfl_xor_sync(0xffffffffu, ls, 1);
            ls += __shfl_xor_sync(0xffffffffu, ls, 2);
            if (qd == 0) {
                float fac = expf(m_old - m_new);
                row_s[r] = fac;
                row_m[r] = m_new;
                row_l[r] = row_l[r] * fac + ls;
            }
        }
        __syncthreads();

        {
            float fac[4];
#pragma unroll
            for (int i = 0; i < 4; i++) fac[i] = row_s[tr + i];
#pragma unroll
            for (int i = 0; i < 4; i++)
#pragma unroll
                for (int j = 0; j < 4; j++) acc[i][j] *= fac[i];
#pragma unroll 8
            for (int c = 0; c < 64; c++) {
                float vv[4], pp[4];
                *(float4*)vv = *(const float4*)&Vs[c * PAD + tc];
#pragma unroll
                for (int i = 0; i < 4; i++) pp[i] = Ks[(tr + i) * PAD + c];
#pragma unroll
                for (int i = 0; i < 4; i++)
#pragma unroll
                    for (int j = 0; j < 4; j++)
                        acc[i][j] = fmaf(pp[i], vv[j], acc[i][j]);
            }
        }
    }

    // Normalize and write bf16 hi/lo planes directly
#pragma unroll
    for (int i = 0; i < 4; i++) {
        float inv = 1.f / row_l[tr + i];
        size_t o = (size_t)(b * NS + q0 + tr + i) * ND + hh * NHD + tc;
        __nv_bfloat16 h[4], lo[4];
#pragma unroll
        for (int j = 0; j < 4; j++) {
            float v = acc[i][j] * inv;
            h[j]  = __float2bfloat16_rn(v);
            lo[j] = __float2bfloat16_rn(v - __bfloat162float(h[j]));
        }
        *(uint2*)&aoh[o] = *(uint2*)h;
        *(uint2*)&aol[o] = *(uint2*)lo;
    }
}

// ---------------------------------------------------------------------------
extern "C" void kernel_launch(void* const* d_in, const int* in_sizes, int n_in,
                              void* d_out, int out_size)
{
    const float* x     = (const float*)d_in[0];
    const float* Wqkv  = (const float*)d_in[1];
    const float* bqkv  = (const float*)d_in[2];
    const float* Wout  = (const float*)d_in[3];
    const float* bout  = (const float*)d_in[4];
    const int*   layer = (const int*)d_in[5];
    float* out = (float*)d_out;

    float *qkv;
    __nv_bfloat16 *xh, *xl, *ah, *al, *wqh, *wql, *woh, *wol;
    cudaGetSymbolAddress((void**)&qkv,  g_qkv);
    cudaGetSymbolAddress((void**)&xh, g_xh);
    cudaGetSymbolAddress((void**)&xl, g_xl);
    cudaGetSymbolAddress((void**)&ah, g_ah);
    cudaGetSymbolAddress((void**)&al, g_al);
    cudaGetSymbolAddress((void**)&wqh, g_wqh);
    cudaGetSymbolAddress((void**)&wql, g_wql);
    cudaGetSymbolAddress((void**)&woh, g_woh);
    cudaGetSymbolAddress((void**)&wol, g_wol);

    const int gemm_smem = 2 * STAGE;   // 147456 B
    cudaFuncSetAttribute(gemm_mma_kernel, cudaFuncAttributeMaxDynamicSharedMemorySize, gemm_smem);
    const int attn_smem = (3 * 64 * PAD + 3 * 64) * (int)sizeof(float);  // 52992 B
    cudaFuncSetAttribute(attn_kernel, cudaFuncAttributeMaxDynamicSharedMemorySize, attn_smem);

    // 0) conversions
    conv_rows_kernel<<<(NROWS * ND / 2 + 255) / 256, 256>>>(x, xh, xl, NROWS * ND / 2);
    convT_kernel<<<dim3(NQKV / 32, ND / 32), dim3(32, 8)>>>(Wqkv, wqh, wql, ND, NQKV);
    convT_kernel<<<dim3(ND / 32, ND / 32), dim3(32, 8)>>>(Wout, woh, wol, ND, ND);

    // 1) qkv = x @ Wqkv + bqkv   (mma.sync tensor cores, cp.async pipelined)
    gemm_mma_kernel<<<dim3(NQKV / 128, NROWS / 128), 256, gemm_smem>>>(
        xh, xl, wqh, wql, bqkv, qkv, NROWS, NQKV, ND);
    // 2) RoPE in-place on q,k
    rope_kernel<<<(NROWS * NH * 32) / 256, 256>>>(qkv, layer);
    // 3) banded attention (writes bf16 hi/lo planes)
    attn_kernel<<<NB * NH * 32, 256, attn_smem>>>(qkv, ah, al, layer);
    // 4) out = attn @ Wout + bout
    gemm_mma_kernel<<<dim3(ND / 128, NROWS / 128), 256, gemm_smem>>>(
        ah, al, woh, wol, bout, out, NROWS, ND, ND);
}

// round 9
// speedup vs baseline: 1.1603x; 1.1603x over previous
#include <cuda_runtime.h>
#include <cuda_bf16.h>
#include <math.h>
#include <stdint.h>

#define NB 2
#define NS 2048
#define ND 768
#define NH 12
#define NHD 64
#define NQKV 2304
#define NROWS 4096   // NB*NS

#define NEG_BIG (-1e30f)
#define PAD 68

// ---------------- scratch (device globals; allocation-free) -----------------
__device__ float g_qkv[(size_t)NROWS * NQKV];                 // 37.7 MB
__device__ __nv_bfloat16 g_xh[(size_t)NROWS * ND];            // x hi
__device__ __nv_bfloat16 g_xl[(size_t)NROWS * ND];            // x lo
__device__ __nv_bfloat16 g_ah[(size_t)NROWS * ND];            // attn hi
__device__ __nv_bfloat16 g_al[(size_t)NROWS * ND];            // attn lo
__device__ __nv_bfloat16 g_wqh[(size_t)NQKV * ND];            // Wqkv^T hi [N][K]
__device__ __nv_bfloat16 g_wql[(size_t)NQKV * ND];
__device__ __nv_bfloat16 g_woh[(size_t)ND * ND];              // Wout^T hi [N][K]
__device__ __nv_bfloat16 g_wol[(size_t)ND * ND];

__device__ __forceinline__ uint32_t smem_u32(const void* p) {
    uint32_t a;
    asm("{ .reg .u64 t; cvta.to.shared.u64 t, %1; cvt.u32.u64 %0, t; }" : "=r"(a) : "l"(p));
    return a;
}

__device__ __forceinline__ void mma_bf16(float c[4], const uint32_t a[4], const uint32_t b[2]) {
    asm volatile(
        "mma.sync.aligned.m16n8k16.row.col.f32.bf16.bf16.f32 "
        "{%0,%1,%2,%3}, {%4,%5,%6,%7}, {%8,%9}, {%0,%1,%2,%3};"
        : "+f"(c[0]), "+f"(c[1]), "+f"(c[2]), "+f"(c[3])
        : "r"(a[0]), "r"(a[1]), "r"(a[2]), "r"(a[3]), "r"(b[0]), "r"(b[1]));
}

#define LDSM4(r, addr) \
    asm volatile("ldmatrix.sync.aligned.m8n8.x4.shared.b16 {%0,%1,%2,%3}, [%4];" \
                 : "=r"((r)[0]), "=r"((r)[1]), "=r"((r)[2]), "=r"((r)[3]) : "r"(addr))

#define CP16(dst, src) \
    asm volatile("cp.async.cg.shared.global [%0], [%1], 16;" :: "r"(dst), "l"(src))
#define CP_COMMIT() asm volatile("cp.async.commit_group;")
#define CP_WAIT1()  asm volatile("cp.async.wait_group 1;")
#define CP_WAIT0()  asm volatile("cp.async.wait_group 0;")

// ---------------------------------------------------------------------------
// Convert fp32 row-major [R][C] -> bf16 hi/lo planes (same layout).
// ---------------------------------------------------------------------------
__global__ void conv_rows_kernel(const float* __restrict__ in,
                                 __nv_bfloat16* __restrict__ oh,
                                 __nv_bfloat16* __restrict__ ol, int n2)
{
    int i = blockIdx.x * blockDim.x + threadIdx.x;
    if (i >= n2) return;
    float2 v = ((const float2*)in)[i];
    __nv_bfloat16 h0 = __float2bfloat16_rn(v.x);
    __nv_bfloat16 h1 = __float2bfloat16_rn(v.y);
    __nv_bfloat16 l0 = __float2bfloat16_rn(v.x - __bfloat162float(h0));
    __nv_bfloat16 l1 = __float2bfloat16_rn(v.y - __bfloat162float(h1));
    ((__nv_bfloat162*)oh)[i] = __nv_bfloat162(h0, h1);
    ((__nv_bfloat162*)ol)[i] = __nv_bfloat162(l0, l1);
}

// ---------------------------------------------------------------------------
// Transpose-convert: W fp32 [K][N] -> out bf16 [N][K] hi/lo planes.
// grid (N/32, K/32), block (32, 8).
// ---------------------------------------------------------------------------
__global__ void convT_kernel(const float* __restrict__ W,
                             __nv_bfloat16* __restrict__ oh,
                             __nv_bfloat16* __restrict__ ol, int K, int N)
{
    __shared__ float t[32][33];
    const int n0 = blockIdx.x * 32, k0 = blockIdx.y * 32;
#pragma unroll
    for (int i = 0; i < 4; i++) {
        int k = threadIdx.y + i * 8;
        t[k][threadIdx.x] = W[(size_t)(k0 + k) * N + n0 + threadIdx.x];
    }
    __syncthreads();
#pragma unroll
    for (int i = 0; i < 4; i++) {
        int n = threadIdx.y + i * 8;
        float x = t[threadIdx.x][n];
        __nv_bfloat16 h = __float2bfloat16_rn(x);
        __nv_bfloat16 l = __float2bfloat16_rn(x - __bfloat162float(h));
        size_t o = (size_t)(n0 + n) * K + k0 + threadIdx.x;
        oh[o] = h;
        ol[o] = l;
    }
}

// ---------------------------------------------------------------------------
// Tensor-core GEMM + bias via mma.sync (bf16x3 split):
//   C[M,N] = Ah@Bh^T + Ah@Bl^T + Al@Bh^T + bias      (fp32 accum/output)
// Block 128x128, BK=32, 8 warps, warp tile 64x32.
// 3-stage cp.async pipeline, 32 KB/stage (96 KB total) -> 2 CTAs/SM.
// Pad-free 64 B smem rows with XOR chunk swizzle c ^= (row>>1)&3
// (conflict-free for all ldmatrix phases).
// ---------------------------------------------------------------------------
#define PL 8192              // plane bytes: 128 rows * 64 B
#define STG (4 * PL)         // 32768 B per stage (Ah, Al, Bh, Bl)
#define NSTAGE 3

__global__ __launch_bounds__(256, 2)
void gemm_mma_kernel(const __nv_bfloat16* __restrict__ Ah, const __nv_bfloat16* __restrict__ Al,
                     const __nv_bfloat16* __restrict__ Bh, const __nv_bfloat16* __restrict__ Bl,
                     const float* __restrict__ bias, float* __restrict__ C,
                     int M, int N, int K)
{
    extern __shared__ __align__(16) char sm[];

    const int tid = threadIdx.x;
    const int w   = tid >> 5;
    const int l   = tid & 31;
    const int row0 = blockIdx.y * 128;
    const int col0 = blockIdx.x * 128;
    const int m0w = (w >> 2) * 64;   // warp M origin in tile
    const int n0w = (w & 3) * 32;    // warp N origin in tile

    float acc[4][4][4];
#pragma unroll
    for (int i = 0; i < 4; i++)
#pragma unroll
        for (int j = 0; j < 4; j++)
#pragma unroll
            for (int q = 0; q < 4; q++) acc[i][j][q] = 0.f;

    const uint32_t sb = smem_u32(sm);

    // ldmatrix lane-relative offsets (within a stage).
    // A (plane 0/1): rows m0w+16*mt+(l&15); chunk (l>>4) + 2*ks, swizzled.
    const int rA   = m0w + (l & 15);
    const uint32_t selA = (uint32_t)((rA >> 1) & 3);
    const uint32_t c0A  = (uint32_t)(l >> 4);
    const uint32_t aRel0 = (uint32_t)rA * 64 + ((c0A ^ selA) << 4);
    const uint32_t aRel1 = (uint32_t)rA * 64 + (((c0A + 2) ^ selA) << 4);
    // B (plane 2/3): rows n0w+(bg>>1)*8+(l&7); chunk (bg&1) + 2*ks.
    const int bg = l >> 3;
    const int rB = n0w + (bg >> 1) * 8 + (l & 7);
    const uint32_t selB = (uint32_t)((rB >> 1) & 3);
    const uint32_t c0B  = (uint32_t)(bg & 1);
    const uint32_t bRel0 = 2u * PL + (uint32_t)rB * 64 + ((c0B ^ selB) << 4);
    const uint32_t bRel1 = 2u * PL + (uint32_t)rB * 64 + (((c0B + 2) ^ selB) << 4);

    // fill: thread -> row tid>>1, chunks fc, fc+1 (16 B each) per plane
    const int fr = tid >> 1;
    const int fc = (tid & 1) * 2;
    const uint32_t fsel = (uint32_t)((fr >> 1) & 3);
    const uint32_t d0 = (uint32_t)fr * 64 + (((uint32_t)fc ^ fsel) << 4);
    const uint32_t d1 = (uint32_t)fr * 64 + ((((uint32_t)fc + 1) ^ fsel) << 4);
    const __nv_bfloat16* gAh = Ah + (size_t)(row0 + fr) * K + fc * 8;
    const __nv_bfloat16* gAl = Al + (size_t)(row0 + fr) * K + fc * 8;
    const __nv_bfloat16* gBh = Bh + (size_t)(col0 + fr) * K + fc * 8;
    const __nv_bfloat16* gBl = Bl + (size_t)(col0 + fr) * K + fc * 8;

    const int nch = K >> 5;   // BK=32 chunks

    auto issue = [&](int kc, int s) {
        const int ke = kc << 5;
        const uint32_t st = sb + (uint32_t)s * STG;
        CP16(st + d0,          gAh + ke);
        CP16(st + d1,          gAh + ke + 8);
        CP16(st + PL + d0,     gAl + ke);
        CP16(st + PL + d1,     gAl + ke + 8);
        CP16(st + 2 * PL + d0, gBh + ke);
        CP16(st + 2 * PL + d1, gBh + ke + 8);
        CP16(st + 3 * PL + d0, gBl + ke);
        CP16(st + 3 * PL + d1, gBl + ke + 8);
        CP_COMMIT();
    };

    issue(0, 0);
    issue(1, 1);

    int s = 0;
    for (int kc = 0; kc < nch; kc++) {
        if (kc + 2 < nch) { CP_WAIT1(); } else { CP_WAIT0(); }
        __syncthreads();
        if (kc + 2 < nch) {
            int s2 = s + 2; if (s2 >= NSTAGE) s2 -= NSTAGE;
            issue(kc + 2, s2);
        }

        const uint32_t stb = sb + (uint32_t)s * STG;
#pragma unroll
        for (int ks = 0; ks < 2; ks++) {
            const uint32_t aR = ks ? aRel1 : aRel0;
            const uint32_t bR = ks ? bRel1 : bRel0;
            uint32_t ah[4][4], al[4][4];
#pragma unroll
            for (int mt = 0; mt < 4; mt++) {
                LDSM4(ah[mt], stb + aR + mt * 1024);
                LDSM4(al[mt], stb + PL + aR + mt * 1024);
            }
            uint32_t bh[4][2], bl[4][2];
#pragma unroll
            for (int jp = 0; jp < 2; jp++) {
                uint32_t r[4];
                LDSM4(r, stb + bR + jp * 1024);
                bh[2 * jp][0] = r[0]; bh[2 * jp][1] = r[1];
                bh[2 * jp + 1][0] = r[2]; bh[2 * jp + 1][1] = r[3];
                LDSM4(r, stb + PL + bR + jp * 1024);
                bl[2 * jp][0] = r[0]; bl[2 * jp][1] = r[1];
                bl[2 * jp + 1][0] = r[2]; bl[2 * jp + 1][1] = r[3];
            }
#pragma unroll
            for (int mt = 0; mt < 4; mt++)
#pragma unroll
                for (int nt = 0; nt < 4; nt++)
                    mma_bf16(acc[mt][nt], ah[mt], bh[nt]);
#pragma unroll
            for (int mt = 0; mt < 4; mt++)
#pragma unroll
                for (int nt = 0; nt < 4; nt++)
                    mma_bf16(acc[mt][nt], ah[mt], bl[nt]);
#pragma unroll
            for (int mt = 0; mt < 4; mt++)
#pragma unroll
                for (int nt = 0; nt < 4; nt++)
                    mma_bf16(acc[mt][nt], al[mt], bh[nt]);
        }
        if (++s >= NSTAGE) s = 0;
    }

    // epilogue: bias + direct stores (float2, frag layout)
    float2 bb[4];
#pragma unroll
    for (int nt = 0; nt < 4; nt++) {
        int cg = col0 + n0w + 8 * nt + 2 * (l & 3);
        bb[nt] = make_float2(bias[cg], bias[cg + 1]);
    }
#pragma unroll
    for (int mt = 0; mt < 4; mt++) {
        int rg = row0 + m0w + 16 * mt + (l >> 2);
#pragma unroll
        for (int nt = 0; nt < 4; nt++) {
            int cg = col0 + n0w + 8 * nt + 2 * (l & 3);
            *(float2*)&C[(size_t)rg * N + cg] =
                make_float2(acc[mt][nt][0] + bb[nt].x, acc[mt][nt][1] + bb[nt].y);
            *(float2*)&C[(size_t)(rg + 8) * N + cg] =
                make_float2(acc[mt][nt][2] + bb[nt].x, acc[mt][nt][3] + bb[nt].y);
        }
    }
}

// ---------------------------------------------------------------------------
// RoPE in-place on q and k parts of qkv. One thread per (b,s,h,pair).
// ---------------------------------------------------------------------------
__global__ void rope_kernel(float* __restrict__ qkv, const int* __restrict__ layer_p)
{
    int idx = blockIdx.x * blockDim.x + threadIdx.x;
    if (idx >= NROWS * NH * 32) return;
    int i  = idx & 31;
    int hh = (idx >> 5) % NH;
    int bs = (idx >> 5) / NH;
    int s  = bs & (NS - 1);

    bool is_global = (layer_p[0] % 3) == 0;
    float theta = is_global ? 160000.f : 10000.f;
    float freq  = powf(theta, -(float)(2 * i) / 64.f);
    float ang   = (float)s * freq;
    float sn, cs;
    sincosf(ang, &sn, &cs);

    size_t base = (size_t)bs * NQKV + hh * NHD + 2 * i;
    float qe = qkv[base], qo = qkv[base + 1];
    qkv[base]      = qe * cs - qo * sn;
    qkv[base + 1]  = qo * cs + qe * sn;
    float ke = qkv[base + ND], ko = qkv[base + ND + 1];
    qkv[base + ND]     = ke * cs - ko * sn;
    qkv[base + ND + 1] = ko * cs + ke * sn;
}

// ---------------------------------------------------------------------------
// Flash-style banded attention; epilogue emits bf16 hi/lo planes directly.
// ---------------------------------------------------------------------------
__global__ __launch_bounds__(256, 1)
void attn_kernel(const float* __restrict__ qkv,
                 __nv_bfloat16* __restrict__ aoh, __nv_bfloat16* __restrict__ aol,
                 const int* __restrict__ layer_p)
{
    extern __shared__ float smf[];
    float* Qt    = smf;
    float* Ks    = Qt + 64 * PAD;
    float* Vs    = Ks + 64 * PAD;
    float* row_m = Vs + 64 * PAD;
    float* row_l = row_m + 64;
    float* row_s = row_l + 64;

    const int tid = threadIdx.x;
    const int blk = blockIdx.x;
    const int qt  = blk & 31;
    const int hh  = (blk >> 5) % NH;
    const int b   = blk / (32 * NH);
    const bool is_global = (layer_p[0] % 3) == 0;
    const int q0 = qt * 64;

    {
        int r = tid >> 2;
        int part = tid & 3;
        const float* src = qkv + (size_t)(b * NS + q0 + r) * NQKV + hh * NHD + part * 16;
#pragma unroll
        for (int v = 0; v < 4; v++) {
            float4 q4 = *(const float4*)(src + v * 4);
            int d0 = part * 16 + v * 4;
            Qt[(d0 + 0) * PAD + r] = q4.x * 0.125f;
            Qt[(d0 + 1) * PAD + r] = q4.y * 0.125f;
            Qt[(d0 + 2) * PAD + r] = q4.z * 0.125f;
            Qt[(d0 + 3) * PAD + r] = q4.w * 0.125f;
        }
    }
    if (tid < 64) { row_m[tid] = NEG_BIG; row_l[tid] = 0.f; }

    const int tr = (tid >> 4) * 4;
    const int tc = (tid & 15) * 4;
    float acc[4][4];
#pragma unroll
    for (int i = 0; i < 4; i++)
#pragma unroll
        for (int j = 0; j < 4; j++) acc[i][j] = 0.f;

    const int kt0 = is_global ? 0 : max(0, qt - 2);
    const int kt1 = is_global ? 31 : min(31, qt + 2);

    for (int kt = kt0; kt <= kt1; kt++) {
        __syncthreads();
        {
            int r = tid >> 2;
            int part = tid & 3;
            const float* ksrc = qkv + (size_t)(b * NS + kt * 64 + r) * NQKV + ND + hh * NHD + part * 16;
#pragma unroll
            for (int v = 0; v < 4; v++) {
                int d0 = part * 16 + v * 4;
                float4 k4 = *(const float4*)(ksrc + v * 4);
                Ks[(d0 + 0) * PAD + r] = k4.x;
                Ks[(d0 + 1) * PAD + r] = k4.y;
                Ks[(d0 + 2) * PAD + r] = k4.z;
                Ks[(d0 + 3) * PAD + r] = k4.w;
                *(float4*)&Vs[r * PAD + d0] = *(const float4*)(ksrc + ND + v * 4);
            }
        }
        __syncthreads();

        float sv[4][4];
#pragma unroll
        for (int i = 0; i < 4; i++)
#pragma unroll
            for (int j = 0; j < 4; j++) sv[i][j] = 0.f;
#pragma unroll 8
        for (int d = 0; d < 64; d++) {
            float qa[4], kb[4];
            *(float4*)qa = *(const float4*)&Qt[d * PAD + tr];
            *(float4*)kb = *(const float4*)&Ks[d * PAD + tc];
#pragma unroll
            for (int i = 0; i < 4; i++)
#pragma unroll
                for (int j = 0; j < 4; j++)
                    sv[i][j] = fmaf(qa[i], kb[j], sv[i][j]);
        }
        if (!is_global) {
#pragma unroll
            for (int i = 0; i < 4; i++)
#pragma unroll
                for (int j = 0; j < 4; j++) {
                    int dlt = (q0 + tr + i) - (kt * 64 + tc + j);
                    if (dlt < 0) dlt = -dlt;
                    if (dlt > 128) sv[i][j] = NEG_BIG;
                }
        }
        __syncthreads();
#pragma unroll
        for (int i = 0; i < 4; i++)
#pragma unroll
            for (int j = 0; j < 4; j++)
                Ks[(tr + i) * PAD + tc + j] = sv[i][j];
        __syncthreads();

        {
            int r  = tid >> 2;
            int qd = tid & 3;
            float* Pr = &Ks[r * PAD + qd * 16];
            float mloc = NEG_BIG;
#pragma unroll
            for (int c = 0; c < 16; c++) mloc = fmaxf(mloc, Pr[c]);
            mloc = fmaxf(mloc, __shfl_xor_sync(0xffffffffu, mloc, 1));
            mloc = fmaxf(mloc, __shfl_xor_sync(0xffffffffu, mloc, 2));
            float m_old = row_m[r];
            float m_new = fmaxf(m_old, mloc);
            float ls = 0.f;
#pragma unroll
            for (int c = 0; c < 16; c++) {
                float e = expf(Pr[c] - m_new);
                Pr[c] = e;
                ls += e;
            }
            ls += __shfl_xor_sync(0xffffffffu, ls, 1);
            ls += __shfl_xor_sync(0xffffffffu, ls, 2);
            if (qd == 0) {
                float fac = expf(m_old - m_new);
                row_s[r] = fac;
                row_m[r] = m_new;
                row_l[r] = row_l[r] * fac + ls;
            }
        }
        __syncthreads();

        {
            float fac[4];
#pragma unroll
            for (int i = 0; i < 4; i++) fac[i] = row_s[tr + i];
#pragma unroll
            for (int i = 0; i < 4; i++)
#pragma unroll
                for (int j = 0; j < 4; j++) acc[i][j] *= fac[i];
#pragma unroll 8
            for (int c = 0; c < 64; c++) {
                float vv[4], pp[4];
                *(float4*)vv = *(const float4*)&Vs[c * PAD + tc];
#pragma unroll
                for (int i = 0; i < 4; i++) pp[i] = Ks[(tr + i) * PAD + c];
#pragma unroll
                for (int i = 0; i < 4; i++)
#pragma unroll
                    for (int j = 0; j < 4; j++)
                        acc[i][j] = fmaf(pp[i], vv[j], acc[i][j]);
            }
        }
    }

    // Normalize and write bf16 hi/lo planes directly
#pragma unroll
    for (int i = 0; i < 4; i++) {
        float inv = 1.f / row_l[tr + i];
        size_t o = (size_t)(b * NS + q0 + tr + i) * ND + hh * NHD + tc;
        __nv_bfloat16 h[4], lo[4];
#pragma unroll
        for (int j = 0; j < 4; j++) {
            float v = acc[i][j] * inv;
            h[j]  = __float2bfloat16_rn(v);
            lo[j] = __float2bfloat16_rn(v - __bfloat162float(h[j]));
        }
        *(uint2*)&aoh[o] = *(uint2*)h;
        *(uint2*)&aol[o] = *(uint2*)lo;
    }
}

// ---------------------------------------------------------------------------
extern "C" void kernel_launch(void* const* d_in, const int* in_sizes, int n_in,
                              void* d_out, int out_size)
{
    const float* x     = (const float*)d_in[0];
    const float* Wqkv  = (const float*)d_in[1];
    const float* bqkv  = (const float*)d_in[2];
    const float* Wout  = (const float*)d_in[3];
    const float* bout  = (const float*)d_in[4];
    const int*   layer = (const int*)d_in[5];
    float* out = (float*)d_out;

    float *qkv;
    __nv_bfloat16 *xh, *xl, *ah, *al, *wqh, *wql, *woh, *wol;
    cudaGetSymbolAddress((void**)&qkv,  g_qkv);
    cudaGetSymbolAddress((void**)&xh, g_xh);
    cudaGetSymbolAddress((void**)&xl, g_xl);
    cudaGetSymbolAddress((void**)&ah, g_ah);
    cudaGetSymbolAddress((void**)&al, g_al);
    cudaGetSymbolAddress((void**)&wqh, g_wqh);
    cudaGetSymbolAddress((void**)&wql, g_wql);
    cudaGetSymbolAddress((void**)&woh, g_woh);
    cudaGetSymbolAddress((void**)&wol, g_wol);

    const int gemm_smem = NSTAGE * STG;   // 98304 B
    cudaFuncSetAttribute(gemm_mma_kernel, cudaFuncAttributeMaxDynamicSharedMemorySize, gemm_smem);
    const int attn_smem = (3 * 64 * PAD + 3 * 64) * (int)sizeof(float);  // 52992 B
    cudaFuncSetAttribute(attn_kernel, cudaFuncAttributeMaxDynamicSharedMemorySize, attn_smem);

    // 0) conversions
    conv_rows_kernel<<<(NROWS * ND / 2 + 255) / 256, 256>>>(x, xh, xl, NROWS * ND / 2);
    convT_kernel<<<dim3(NQKV / 32, ND / 32), dim3(32, 8)>>>(Wqkv, wqh, wql, ND, NQKV);
    convT_kernel<<<dim3(ND / 32, ND / 32), dim3(32, 8)>>>(Wout, woh, wol, ND, ND);

    // 1) qkv = x @ Wqkv + bqkv   (mma.sync, 3-stage cp.async, 2 CTAs/SM)
    gemm_mma_kernel<<<dim3(NQKV / 128, NROWS / 128), 256, gemm_smem>>>(
        xh, xl, wqh, wql, bqkv, qkv, NROWS, NQKV, ND);
    // 2) RoPE in-place on q,k
    rope_kernel<<<(NROWS * NH * 32) / 256, 256>>>(qkv, layer);
    // 3) banded attention (writes bf16 hi/lo planes)
    attn_kernel<<<NB * NH * 32, 256, attn_smem>>>(qkv, ah, al, layer);
    // 4) out = attn @ Wout + bout
    gemm_mma_kernel<<<dim3(ND / 128, NROWS / 128), 256, gemm_smem>>>(
        ah, al, woh, wol, bout, out, NROWS, ND, ND);
}

// round 10
// speedup vs baseline: 1.3332x; 1.1490x over previous
#include <cuda_runtime.h>
#include <cuda_bf16.h>
#include <math.h>
#include <stdint.h>

#define NB 2
#define NS 2048
#define ND 768
#define NH 12
#define NHD 64
#define NQKV 2304
#define NROWS 4096   // NB*NS

#define NEG_BIG (-1e30f)

// ---------------- scratch (device globals; allocation-free) -----------------
__device__ float g_qkv[(size_t)NROWS * NQKV];                 // 37.7 MB
__device__ __nv_bfloat16 g_xh[(size_t)NROWS * ND];            // x hi
__device__ __nv_bfloat16 g_xl[(size_t)NROWS * ND];            // x lo
__device__ __nv_bfloat16 g_ah[(size_t)NROWS * ND];            // attn hi
__device__ __nv_bfloat16 g_al[(size_t)NROWS * ND];            // attn lo
__device__ __nv_bfloat16 g_wqh[(size_t)NQKV * ND];            // Wqkv^T hi [N][K]
__device__ __nv_bfloat16 g_wql[(size_t)NQKV * ND];
__device__ __nv_bfloat16 g_woh[(size_t)ND * ND];              // Wout^T hi [N][K]
__device__ __nv_bfloat16 g_wol[(size_t)ND * ND];

__device__ __forceinline__ uint32_t smem_u32(const void* p) {
    uint32_t a;
    asm("{ .reg .u64 t; cvta.to.shared.u64 t, %1; cvt.u32.u64 %0, t; }" : "=r"(a) : "l"(p));
    return a;
}

__device__ __forceinline__ void mma_bf16(float c[4], const uint32_t a[4], const uint32_t b[2]) {
    asm volatile(
        "mma.sync.aligned.m16n8k16.row.col.f32.bf16.bf16.f32 "
        "{%0,%1,%2,%3}, {%4,%5,%6,%7}, {%8,%9}, {%0,%1,%2,%3};"
        : "+f"(c[0]), "+f"(c[1]), "+f"(c[2]), "+f"(c[3])
        : "r"(a[0]), "r"(a[1]), "r"(a[2]), "r"(a[3]), "r"(b[0]), "r"(b[1]));
}

#define LDSM4(r, addr) \
    asm volatile("ldmatrix.sync.aligned.m8n8.x4.shared.b16 {%0,%1,%2,%3}, [%4];" \
                 : "=r"((r)[0]), "=r"((r)[1]), "=r"((r)[2]), "=r"((r)[3]) : "r"(addr))

#define CP16(dst, src) \
    asm volatile("cp.async.cg.shared.global [%0], [%1], 16;" :: "r"(dst), "l"(src))
#define CP_COMMIT() asm volatile("cp.async.commit_group;")
#define CP_WAIT1()  asm volatile("cp.async.wait_group 1;")
#define CP_WAIT0()  asm volatile("cp.async.wait_group 0;")

// ---------------------------------------------------------------------------
// Convert fp32 row-major [R][C] -> bf16 hi/lo planes (same layout).
// ---------------------------------------------------------------------------
__global__ void conv_rows_kernel(const float* __restrict__ in,
                                 __nv_bfloat16* __restrict__ oh,
                                 __nv_bfloat16* __restrict__ ol, int n2)
{
    int i = blockIdx.x * blockDim.x + threadIdx.x;
    if (i >= n2) return;
    float2 v = ((const float2*)in)[i];
    __nv_bfloat16 h0 = __float2bfloat16_rn(v.x);
    __nv_bfloat16 h1 = __float2bfloat16_rn(v.y);
    __nv_bfloat16 l0 = __float2bfloat16_rn(v.x - __bfloat162float(h0));
    __nv_bfloat16 l1 = __float2bfloat16_rn(v.y - __bfloat162float(h1));
    ((__nv_bfloat162*)oh)[i] = __nv_bfloat162(h0, h1);
    ((__nv_bfloat162*)ol)[i] = __nv_bfloat162(l0, l1);
}

// ---------------------------------------------------------------------------
// Transpose-convert: W fp32 [K][N] -> out bf16 [N][K] hi/lo planes.
// ---------------------------------------------------------------------------
__global__ void convT_kernel(const float* __restrict__ W,
                             __nv_bfloat16* __restrict__ oh,
                             __nv_bfloat16* __restrict__ ol, int K, int N)
{
    __shared__ float t[32][33];
    const int n0 = blockIdx.x * 32, k0 = blockIdx.y * 32;
#pragma unroll
    for (int i = 0; i < 4; i++) {
        int k = threadIdx.y + i * 8;
        t[k][threadIdx.x] = W[(size_t)(k0 + k) * N + n0 + threadIdx.x];
    }
    __syncthreads();
#pragma unroll
    for (int i = 0; i < 4; i++) {
        int n = threadIdx.y + i * 8;
        float x = t[threadIdx.x][n];
        __nv_bfloat16 h = __float2bfloat16_rn(x);
        __nv_bfloat16 l = __float2bfloat16_rn(x - __bfloat162float(h));
        size_t o = (size_t)(n0 + n) * K + k0 + threadIdx.x;
        oh[o] = h;
        ol[o] = l;
    }
}

// ---------------------------------------------------------------------------
// GEMM (unchanged from round 9): 128x128, BK=32, 3-stage cp.async, 2 CTAs/SM.
// ---------------------------------------------------------------------------
#define PL 8192
#define STG (4 * PL)
#define NSTAGE 3

__global__ __launch_bounds__(256, 2)
void gemm_mma_kernel(const __nv_bfloat16* __restrict__ Ah, const __nv_bfloat16* __restrict__ Al,
                     const __nv_bfloat16* __restrict__ Bh, const __nv_bfloat16* __restrict__ Bl,
                     const float* __restrict__ bias, float* __restrict__ C,
                     int M, int N, int K)
{
    extern __shared__ __align__(16) char sm[];

    const int tid = threadIdx.x;
    const int w   = tid >> 5;
    const int l   = tid & 31;
    const int row0 = blockIdx.y * 128;
    const int col0 = blockIdx.x * 128;
    const int m0w = (w >> 2) * 64;
    const int n0w = (w & 3) * 32;

    float acc[4][4][4];
#pragma unroll
    for (int i = 0; i < 4; i++)
#pragma unroll
        for (int j = 0; j < 4; j++)
#pragma unroll
            for (int q = 0; q < 4; q++) acc[i][j][q] = 0.f;

    const uint32_t sb = smem_u32(sm);

    const int rA   = m0w + (l & 15);
    const uint32_t selA = (uint32_t)((rA >> 1) & 3);
    const uint32_t c0A  = (uint32_t)(l >> 4);
    const uint32_t aRel0 = (uint32_t)rA * 64 + ((c0A ^ selA) << 4);
    const uint32_t aRel1 = (uint32_t)rA * 64 + (((c0A + 2) ^ selA) << 4);
    const int bg = l >> 3;
    const int rB = n0w + (bg >> 1) * 8 + (l & 7);
    const uint32_t selB = (uint32_t)((rB >> 1) & 3);
    const uint32_t c0B  = (uint32_t)(bg & 1);
    const uint32_t bRel0 = 2u * PL + (uint32_t)rB * 64 + ((c0B ^ selB) << 4);
    const uint32_t bRel1 = 2u * PL + (uint32_t)rB * 64 + (((c0B + 2) ^ selB) << 4);

    const int fr = tid >> 1;
    const int fc = (tid & 1) * 2;
    const uint32_t fsel = (uint32_t)((fr >> 1) & 3);
    const uint32_t d0 = (uint32_t)fr * 64 + (((uint32_t)fc ^ fsel) << 4);
    const uint32_t d1 = (uint32_t)fr * 64 + ((((uint32_t)fc + 1) ^ fsel) << 4);
    const __nv_bfloat16* gAh = Ah + (size_t)(row0 + fr) * K + fc * 8;
    const __nv_bfloat16* gAl = Al + (size_t)(row0 + fr) * K + fc * 8;
    const __nv_bfloat16* gBh = Bh + (size_t)(col0 + fr) * K + fc * 8;
    const __nv_bfloat16* gBl = Bl + (size_t)(col0 + fr) * K + fc * 8;

    const int nch = K >> 5;

    auto issue = [&](int kc, int s) {
        const int ke = kc << 5;
        const uint32_t st = sb + (uint32_t)s * STG;
        CP16(st + d0,          gAh + ke);
        CP16(st + d1,          gAh + ke + 8);
        CP16(st + PL + d0,     gAl + ke);
        CP16(st + PL + d1,     gAl + ke + 8);
        CP16(st + 2 * PL + d0, gBh + ke);
        CP16(st + 2 * PL + d1, gBh + ke + 8);
        CP16(st + 3 * PL + d0, gBl + ke);
        CP16(st + 3 * PL + d1, gBl + ke + 8);
        CP_COMMIT();
    };

    issue(0, 0);
    issue(1, 1);

    int s = 0;
    for (int kc = 0; kc < nch; kc++) {
        if (kc + 2 < nch) { CP_WAIT1(); } else { CP_WAIT0(); }
        __syncthreads();
        if (kc + 2 < nch) {
            int s2 = s + 2; if (s2 >= NSTAGE) s2 -= NSTAGE;
            issue(kc + 2, s2);
        }

        const uint32_t stb = sb + (uint32_t)s * STG;
#pragma unroll
        for (int ks = 0; ks < 2; ks++) {
            const uint32_t aR = ks ? aRel1 : aRel0;
            const uint32_t bR = ks ? bRel1 : bRel0;
            uint32_t ah[4][4], al[4][4];
#pragma unroll
            for (int mt = 0; mt < 4; mt++) {
                LDSM4(ah[mt], stb + aR + mt * 1024);
                LDSM4(al[mt], stb + PL + aR + mt * 1024);
            }
            uint32_t bh[4][2], bl[4][2];
#pragma unroll
            for (int jp = 0; jp < 2; jp++) {
                uint32_t r[4];
                LDSM4(r, stb + bR + jp * 1024);
                bh[2 * jp][0] = r[0]; bh[2 * jp][1] = r[1];
                bh[2 * jp + 1][0] = r[2]; bh[2 * jp + 1][1] = r[3];
                LDSM4(r, stb + PL + bR + jp * 1024);
                bl[2 * jp][0] = r[0]; bl[2 * jp][1] = r[1];
                bl[2 * jp + 1][0] = r[2]; bl[2 * jp + 1][1] = r[3];
            }
#pragma unroll
            for (int mt = 0; mt < 4; mt++)
#pragma unroll
                for (int nt = 0; nt < 4; nt++)
                    mma_bf16(acc[mt][nt], ah[mt], bh[nt]);
#pragma unroll
            for (int mt = 0; mt < 4; mt++)
#pragma unroll
                for (int nt = 0; nt < 4; nt++)
                    mma_bf16(acc[mt][nt], ah[mt], bl[nt]);
#pragma unroll
            for (int mt = 0; mt < 4; mt++)
#pragma unroll
                for (int nt = 0; nt < 4; nt++)
                    mma_bf16(acc[mt][nt], al[mt], bh[nt]);
        }
        if (++s >= NSTAGE) s = 0;
    }

    float2 bb[4];
#pragma unroll
    for (int nt = 0; nt < 4; nt++) {
        int cg = col0 + n0w + 8 * nt + 2 * (l & 3);
        bb[nt] = make_float2(bias[cg], bias[cg + 1]);
    }
#pragma unroll
    for (int mt = 0; mt < 4; mt++) {
        int rg = row0 + m0w + 16 * mt + (l >> 2);
#pragma unroll
        for (int nt = 0; nt < 4; nt++) {
            int cg = col0 + n0w + 8 * nt + 2 * (l & 3);
            *(float2*)&C[(size_t)rg * N + cg] =
                make_float2(acc[mt][nt][0] + bb[nt].x, acc[mt][nt][1] + bb[nt].y);
            *(float2*)&C[(size_t)(rg + 8) * N + cg] =
                make_float2(acc[mt][nt][2] + bb[nt].x, acc[mt][nt][3] + bb[nt].y);
        }
    }
}

// ---------------------------------------------------------------------------
// RoPE in-place on q and k parts of qkv.
// ---------------------------------------------------------------------------
__global__ void rope_kernel(float* __restrict__ qkv, const int* __restrict__ layer_p)
{
    int idx = blockIdx.x * blockDim.x + threadIdx.x;
    if (idx >= NROWS * NH * 32) return;
    int i  = idx & 31;
    int hh = (idx >> 5) % NH;
    int bs = (idx >> 5) / NH;
    int s  = bs & (NS - 1);

    bool is_global = (layer_p[0] % 3) == 0;
    float theta = is_global ? 160000.f : 10000.f;
    float freq  = powf(theta, -(float)(2 * i) / 64.f);
    float ang   = (float)s * freq;
    float sn, cs;
    sincosf(ang, &sn, &cs);

    size_t base = (size_t)bs * NQKV + hh * NHD + 2 * i;
    float qe = qkv[base], qo = qkv[base + 1];
    qkv[base]      = qe * cs - qo * sn;
    qkv[base + 1]  = qo * cs + qe * sn;
    float ke = qkv[base + ND], ko = qkv[base + ND + 1];
    qkv[base + ND]     = ke * cs - ko * sn;
    qkv[base + ND + 1] = ko * cs + ke * sn;
}

// ---------------------------------------------------------------------------
// Tensor-core flash attention, one block per (b, h, 64-row q tile).
// S = QK^T and O += P@V both via mma.sync bf16x3 split; softmax in fp32.
// bf16 planes use 144 B rows (round-7-validated conflict-free ldmatrix layout).
// V stored transposed [dim][key] so PV uses the standard B-operand pattern.
// P planes reuse the K planes (dead after S).
// ---------------------------------------------------------------------------
#define TSROW 144
#define TPL (64 * TSROW)   // 9216 B per plane

__device__ __forceinline__ void split4_store(char* ph, char* pl, uint32_t off, float4 v)
{
    __nv_bfloat16 h0 = __float2bfloat16_rn(v.x);
    __nv_bfloat16 h1 = __float2bfloat16_rn(v.y);
    __nv_bfloat16 h2 = __float2bfloat16_rn(v.z);
    __nv_bfloat16 h3 = __float2bfloat16_rn(v.w);
    __nv_bfloat162 hl0(h0, h1), hl1(h2, h3);
    __nv_bfloat162 ll0(__float2bfloat16_rn(v.x - __bfloat162float(h0)),
                       __float2bfloat16_rn(v.y - __bfloat162float(h1)));
    __nv_bfloat162 ll1(__float2bfloat16_rn(v.z - __bfloat162float(h2)),
                       __float2bfloat16_rn(v.w - __bfloat162float(h3)));
    *(__nv_bfloat162*)(ph + off)     = hl0;
    *(__nv_bfloat162*)(ph + off + 4) = hl1;
    *(__nv_bfloat162*)(pl + off)     = ll0;
    *(__nv_bfloat162*)(pl + off + 4) = ll1;
}

__global__ __launch_bounds__(256)
void attn_mma_kernel(const float* __restrict__ qkv,
                     __nv_bfloat16* __restrict__ aoh, __nv_bfloat16* __restrict__ aol,
                     const int* __restrict__ layer_p)
{
    extern __shared__ __align__(16) char sm[];
    char* Qh  = sm;                 // [q][d]
    char* Ql  = sm + TPL;
    char* Kh  = sm + 2 * TPL;       // [key][d]; reused as Ph [q][key]
    char* Kl  = sm + 3 * TPL;       //            reused as Pl
    char* Vth = sm + 4 * TPL;       // [d][key]
    char* Vtl = sm + 5 * TPL;
    float* Sbuf  = (float*)(sm + 6 * TPL);   // [64][68]
    float* row_m = Sbuf + 64 * 68;
    float* row_l = row_m + 64;
    float* row_s = row_l + 64;

    const int tid = threadIdx.x;
    const int w   = tid >> 5;
    const int l   = tid & 31;
    const int blk = blockIdx.x;
    const int qt  = blk & 31;
    const int hh  = (blk >> 5) % NH;
    const int b   = blk / (32 * NH);
    const bool is_global = (layer_p[0] % 3) == 0;
    const int q0 = qt * 64;

    const int mrow = (w & 3) * 16;      // warp S/O row origin
    const int ncol = (w >> 2) * 32;     // warp S/O col origin
    const uint32_t sb = smem_u32(sm);
    const uint32_t aRel = (uint32_t)(mrow + (l & 15)) * TSROW + (uint32_t)((l >> 4) * 16);
    const int bg = l >> 3;
    const uint32_t bRel = (uint32_t)(ncol + (bg >> 1) * 8 + (l & 7)) * TSROW
                        + (uint32_t)((bg & 1) * 16);

    // load Q (scaled 1/8), split to bf16 planes
    {
        int r = tid >> 2, part = tid & 3;
        const float* src = qkv + (size_t)(b * NS + q0 + r) * NQKV + hh * NHD + part * 16;
#pragma unroll
        for (int v = 0; v < 4; v++) {
            float4 q4 = *(const float4*)(src + v * 4);
            q4.x *= 0.125f; q4.y *= 0.125f; q4.z *= 0.125f; q4.w *= 0.125f;
            split4_store(Qh, Ql, (uint32_t)(r * TSROW + (part * 16 + v * 4) * 2), q4);
        }
    }
    if (tid < 64) { row_m[tid] = NEG_BIG; row_l[tid] = 0.f; }

    float oacc[4][4];
#pragma unroll
    for (int i = 0; i < 4; i++)
#pragma unroll
        for (int j = 0; j < 4; j++) oacc[i][j] = 0.f;

    const int kt0 = is_global ? 0 : max(0, qt - 2);
    const int kt1 = is_global ? 31 : min(31, qt + 2);

    for (int kt = kt0; kt <= kt1; kt++) {
        __syncthreads();   // prior consumers of K/P/V planes done; Q ready (iter 0)
        {   // load K row-major + V transposed, split to bf16 planes
            int r = tid >> 2, part = tid & 3;
            const float* ksrc = qkv + (size_t)(b * NS + kt * 64 + r) * NQKV + ND + hh * NHD + part * 16;
#pragma unroll
            for (int v = 0; v < 4; v++) {
                float4 k4 = *(const float4*)(ksrc + v * 4);
                split4_store(Kh, Kl, (uint32_t)(r * TSROW + (part * 16 + v * 4) * 2), k4);
                float4 v4 = *(const float4*)(ksrc + ND + v * 4);
                int dd = part * 16 + v * 4;
                const float* vp = &v4.x;
#pragma unroll
                for (int j = 0; j < 4; j++) {
                    float x = vp[j];
                    __nv_bfloat16 h = __float2bfloat16_rn(x);
                    __nv_bfloat16 lo = __float2bfloat16_rn(x - __bfloat162float(h));
                    *(__nv_bfloat16*)(Vth + (dd + j) * TSROW + r * 2) = h;
                    *(__nv_bfloat16*)(Vtl + (dd + j) * TSROW + r * 2) = lo;
                }
            }
        }
        __syncthreads();

        // ---- S = Q K^T (bf16x3, fp32 accum) ----
        float sa[4][4];
#pragma unroll
        for (int i = 0; i < 4; i++)
#pragma unroll
            for (int j = 0; j < 4; j++) sa[i][j] = 0.f;
#pragma unroll
        for (int ks = 0; ks < 4; ks++) {
            const uint32_t kso = (uint32_t)(ks * 32);
            uint32_t qh4[4], ql4[4];
            LDSM4(qh4, sb + aRel + kso);
            LDSM4(ql4, sb + TPL + aRel + kso);
            uint32_t bh[4][2], bl[4][2];
#pragma unroll
            for (int jp = 0; jp < 2; jp++) {
                uint32_t r4[4];
                LDSM4(r4, sb + 2 * TPL + bRel + jp * (16 * TSROW) + kso);
                bh[2 * jp][0] = r4[0]; bh[2 * jp][1] = r4[1];
                bh[2 * jp + 1][0] = r4[2]; bh[2 * jp + 1][1] = r4[3];
                LDSM4(r4, sb + 3 * TPL + bRel + jp * (16 * TSROW) + kso);
                bl[2 * jp][0] = r4[0]; bl[2 * jp][1] = r4[1];
                bl[2 * jp + 1][0] = r4[2]; bl[2 * jp + 1][1] = r4[3];
            }
#pragma unroll
            for (int nt = 0; nt < 4; nt++) mma_bf16(sa[nt], qh4, bh[nt]);
#pragma unroll
            for (int nt = 0; nt < 4; nt++) mma_bf16(sa[nt], qh4, bl[nt]);
#pragma unroll
            for (int nt = 0; nt < 4; nt++) mma_bf16(sa[nt], ql4, bh[nt]);
        }
        {   // store S fragments to fp32 buffer
            int fr0 = mrow + (l >> 2);
#pragma unroll
            for (int nt = 0; nt < 4; nt++) {
                int col = ncol + 8 * nt + 2 * (l & 3);
                *(float2*)&Sbuf[fr0 * 68 + col]       = make_float2(sa[nt][0], sa[nt][1]);
                *(float2*)&Sbuf[(fr0 + 8) * 68 + col] = make_float2(sa[nt][2], sa[nt][3]);
            }
        }
        __syncthreads();

        // ---- banded mask + online softmax; emit Ph/Pl bf16 planes ----
        {
            int r  = tid >> 2;
            int qd = tid & 3;
            float* Pr = &Sbuf[r * 68 + qd * 16];
            if (!is_global) {
#pragma unroll
                for (int c = 0; c < 16; c++) {
                    int dlt = (q0 + r) - (kt * 64 + qd * 16 + c);
                    if (dlt < 0) dlt = -dlt;
                    if (dlt > 128) Pr[c] = NEG_BIG;
                }
            }
            float mloc = NEG_BIG;
#pragma unroll
            for (int c = 0; c < 16; c++) mloc = fmaxf(mloc, Pr[c]);
            mloc = fmaxf(mloc, __shfl_xor_sync(0xffffffffu, mloc, 1));
            mloc = fmaxf(mloc, __shfl_xor_sync(0xffffffffu, mloc, 2));
            float m_old = row_m[r];
            float m_new = fmaxf(m_old, mloc);
            float ls = 0.f;
#pragma unroll
            for (int c = 0; c < 16; c += 2) {
                float e0 = expf(Pr[c]     - m_new);
                float e1 = expf(Pr[c + 1] - m_new);
                ls += e0 + e1;
                __nv_bfloat16 h0 = __float2bfloat16_rn(e0);
                __nv_bfloat16 h1 = __float2bfloat16_rn(e1);
                uint32_t off = (uint32_t)(r * TSROW + (qd * 16 + c) * 2);
                *(__nv_bfloat162*)(Kh + off) = __nv_bfloat162(h0, h1);   // Ph
                *(__nv_bfloat162*)(Kl + off) = __nv_bfloat162(            // Pl
                    __float2bfloat16_rn(e0 - __bfloat162float(h0)),
                    __float2bfloat16_rn(e1 - __bfloat162float(h1)));
            }
            ls += __shfl_xor_sync(0xffffffffu, ls, 1);
            ls += __shfl_xor_sync(0xffffffffu, ls, 2);
            if (qd == 0) {
                float fac = expf(m_old - m_new);
                row_s[r] = fac;
                row_m[r] = m_new;
                row_l[r] = row_l[r] * fac + ls;
            }
        }
        __syncthreads();

        // ---- rescale O and O += P @ V (bf16x3) ----
        {
            float f0 = row_s[mrow + (l >> 2)];
            float f1 = row_s[mrow + 8 + (l >> 2)];
#pragma unroll
            for (int nt = 0; nt < 4; nt++) {
                oacc[nt][0] *= f0; oacc[nt][1] *= f0;
                oacc[nt][2] *= f1; oacc[nt][3] *= f1;
            }
#pragma unroll
            for (int ks = 0; ks < 4; ks++) {
                const uint32_t kso = (uint32_t)(ks * 32);
                uint32_t ph4[4], pl4[4];
                LDSM4(ph4, sb + 2 * TPL + aRel + kso);
                LDSM4(pl4, sb + 3 * TPL + aRel + kso);
                uint32_t vh[4][2], vl[4][2];
#pragma unroll
                for (int jp = 0; jp < 2; jp++) {
                    uint32_t r4[4];
                    LDSM4(r4, sb + 4 * TPL + bRel + jp * (16 * TSROW) + kso);
                    vh[2 * jp][0] = r4[0]; vh[2 * jp][1] = r4[1];
                    vh[2 * jp + 1][0] = r4[2]; vh[2 * jp + 1][1] = r4[3];
                    LDSM4(r4, sb + 5 * TPL + bRel + jp * (16 * TSROW) + kso);
                    vl[2 * jp][0] = r4[0]; vl[2 * jp][1] = r4[1];
                    vl[2 * jp + 1][0] = r4[2]; vl[2 * jp + 1][1] = r4[3];
                }
#pragma unroll
                for (int nt = 0; nt < 4; nt++) mma_bf16(oacc[nt], ph4, vh[nt]);
#pragma unroll
                for (int nt = 0; nt < 4; nt++) mma_bf16(oacc[nt], ph4, vl[nt]);
#pragma unroll
                for (int nt = 0; nt < 4; nt++) mma_bf16(oacc[nt], pl4, vh[nt]);
            }
        }
    }

    // normalize + write bf16 hi/lo planes from fragments
    {
        float i0 = 1.f / row_l[mrow + (l >> 2)];
        float i1 = 1.f / row_l[mrow + 8 + (l >> 2)];
        size_t r0 = (size_t)(b * NS + q0 + mrow + (l >> 2)) * ND;
        size_t r1 = r0 + 8 * (size_t)ND;
#pragma unroll
        for (int nt = 0; nt < 4; nt++) {
            int col = hh * NHD + ncol + 8 * nt + 2 * (l & 3);
            float v0 = oacc[nt][0] * i0, v1 = oacc[nt][1] * i0;
            float v2 = oacc[nt][2] * i1, v3 = oacc[nt][3] * i1;
            __nv_bfloat16 h0 = __float2bfloat16_rn(v0), h1 = __float2bfloat16_rn(v1);
            __nv_bfloat16 h2 = __float2bfloat16_rn(v2), h3 = __float2bfloat16_rn(v3);
            *(__nv_bfloat162*)&aoh[r0 + col] = __nv_bfloat162(h0, h1);
            *(__nv_bfloat162*)&aol[r0 + col] = __nv_bfloat162(
                __float2bfloat16_rn(v0 - __bfloat162float(h0)),
                __float2bfloat16_rn(v1 - __bfloat162float(h1)));
            *(__nv_bfloat162*)&aoh[r1 + col] = __nv_bfloat162(h2, h3);
            *(__nv_bfloat162*)&aol[r1 + col] = __nv_bfloat162(
                __float2bfloat16_rn(v2 - __bfloat162float(h2)),
                __float2bfloat16_rn(v3 - __bfloat162float(h3)));
        }
    }
}

// ---------------------------------------------------------------------------
extern "C" void kernel_launch(void* const* d_in, const int* in_sizes, int n_in,
                              void* d_out, int out_size)
{
    const float* x     = (const float*)d_in[0];
    const float* Wqkv  = (const float*)d_in[1];
    const float* bqkv  = (const float*)d_in[2];
    const float* Wout  = (const float*)d_in[3];
    const float* bout  = (const float*)d_in[4];
    const int*   layer = (const int*)d_in[5];
    float* out = (float*)d_out;

    float *qkv;
    __nv_bfloat16 *xh, *xl, *ah, *al, *wqh, *wql, *woh, *wol;
    cudaGetSymbolAddress((void**)&qkv,  g_qkv);
    cudaGetSymbolAddress((void**)&xh, g_xh);
    cudaGetSymbolAddress((void**)&xl, g_xl);
    cudaGetSymbolAddress((void**)&ah, g_ah);
    cudaGetSymbolAddress((void**)&al, g_al);
    cudaGetSymbolAddress((void**)&wqh, g_wqh);
    cudaGetSymbolAddress((void**)&wql, g_wql);
    cudaGetSymbolAddress((void**)&woh, g_woh);
    cudaGetSymbolAddress((void**)&wol, g_wol);

    const int gemm_smem = NSTAGE * STG;   // 98304 B
    cudaFuncSetAttribute(gemm_mma_kernel, cudaFuncAttributeMaxDynamicSharedMemorySize, gemm_smem);
    const int attn_smem = 6 * TPL + 64 * 68 * 4 + 3 * 64 * 4;   // 73472 B
    cudaFuncSetAttribute(attn_mma_kernel, cudaFuncAttributeMaxDynamicSharedMemorySize, attn_smem);

    // 0) conversions
    conv_rows_kernel<<<(NROWS * ND / 2 + 255) / 256, 256>>>(x, xh, xl, NROWS * ND / 2);
    convT_kernel<<<dim3(NQKV / 32, ND / 32), dim3(32, 8)>>>(Wqkv, wqh, wql, ND, NQKV);
    convT_kernel<<<dim3(ND / 32, ND / 32), dim3(32, 8)>>>(Wout, woh, wol, ND, ND);

    // 1) qkv = x @ Wqkv + bqkv
    gemm_mma_kernel<<<dim3(NQKV / 128, NROWS / 128), 256, gemm_smem>>>(
        xh, xl, wqh, wql, bqkv, qkv, NROWS, NQKV, ND);
    // 2) RoPE in-place on q,k
    rope_kernel<<<(NROWS * NH * 32) / 256, 256>>>(qkv, layer);
    // 3) tensor-core banded attention (writes bf16 hi/lo planes)
    attn_mma_kernel<<<NB * NH * 32, 256, attn_smem>>>(qkv, ah, al, layer);
    // 4) out = attn @ Wout + bout
    gemm_mma_kernel<<<dim3(ND / 128, NROWS / 128), 256, gemm_smem>>>(
        ah, al, woh, wol, bout, out, NROWS, ND, ND);
}

// round 11
// speedup vs baseline: 1.4645x; 1.0985x over previous
#include <cuda_runtime.h>
#include <cuda_bf16.h>
#include <math.h>
#include <stdint.h>

#define NB 2
#define NS 2048
#define ND 768
#define NH 12
#define NHD 64
#define NQKV 2304
#define NROWS 4096   // NB*NS

#define NEG_BIG (-1e30f)

// ---------------- scratch (device globals; allocation-free) -----------------
__device__ float g_qkv[(size_t)NROWS * NQKV];                 // 37.7 MB
__device__ __nv_bfloat16 g_xh[(size_t)NROWS * ND];
__device__ __nv_bfloat16 g_xl[(size_t)NROWS * ND];
__device__ __nv_bfloat16 g_ah[(size_t)NROWS * ND];
__device__ __nv_bfloat16 g_al[(size_t)NROWS * ND];
__device__ __nv_bfloat16 g_wqh[(size_t)NQKV * ND];
__device__ __nv_bfloat16 g_wql[(size_t)NQKV * ND];
__device__ __nv_bfloat16 g_woh[(size_t)ND * ND];
__device__ __nv_bfloat16 g_wol[(size_t)ND * ND];
// attention operand planes (bf16 hi/lo)
__device__ __nv_bfloat16 g_qh[(size_t)NROWS * ND];            // rotated, scaled Q
__device__ __nv_bfloat16 g_ql[(size_t)NROWS * ND];
__device__ __nv_bfloat16 g_kh[(size_t)NROWS * ND];            // rotated K
__device__ __nv_bfloat16 g_kl[(size_t)NROWS * ND];
__device__ __nv_bfloat16 g_vth[(size_t)NROWS * ND];           // V^T [b][h][d][s]
__device__ __nv_bfloat16 g_vtl[(size_t)NROWS * ND];

__device__ __forceinline__ uint32_t smem_u32(const void* p) {
    uint32_t a;
    asm("{ .reg .u64 t; cvta.to.shared.u64 t, %1; cvt.u32.u64 %0, t; }" : "=r"(a) : "l"(p));
    return a;
}

__device__ __forceinline__ void mma_bf16(float c[4], const uint32_t a[4], const uint32_t b[2]) {
    asm volatile(
        "mma.sync.aligned.m16n8k16.row.col.f32.bf16.bf16.f32 "
        "{%0,%1,%2,%3}, {%4,%5,%6,%7}, {%8,%9}, {%0,%1,%2,%3};"
        : "+f"(c[0]), "+f"(c[1]), "+f"(c[2]), "+f"(c[3])
        : "r"(a[0]), "r"(a[1]), "r"(a[2]), "r"(a[3]), "r"(b[0]), "r"(b[1]));
}

#define LDSM4(r, addr) \
    asm volatile("ldmatrix.sync.aligned.m8n8.x4.shared.b16 {%0,%1,%2,%3}, [%4];" \
                 : "=r"((r)[0]), "=r"((r)[1]), "=r"((r)[2]), "=r"((r)[3]) : "r"(addr))

#define CP16(dst, src) \
    asm volatile("cp.async.cg.shared.global [%0], [%1], 16;" :: "r"(dst), "l"(src))
#define CP_COMMIT() asm volatile("cp.async.commit_group;")
#define CP_WAIT1()  asm volatile("cp.async.wait_group 1;")
#define CP_WAIT0()  asm volatile("cp.async.wait_group 0;")

// ---------------------------------------------------------------------------
// Convert fp32 row-major -> bf16 hi/lo planes.
// ---------------------------------------------------------------------------
__global__ void conv_rows_kernel(const float* __restrict__ in,
                                 __nv_bfloat16* __restrict__ oh,
                                 __nv_bfloat16* __restrict__ ol, int n2)
{
    int i = blockIdx.x * blockDim.x + threadIdx.x;
    if (i >= n2) return;
    float2 v = ((const float2*)in)[i];
    __nv_bfloat16 h0 = __float2bfloat16_rn(v.x);
    __nv_bfloat16 h1 = __float2bfloat16_rn(v.y);
    __nv_bfloat16 l0 = __float2bfloat16_rn(v.x - __bfloat162float(h0));
    __nv_bfloat16 l1 = __float2bfloat16_rn(v.y - __bfloat162float(h1));
    ((__nv_bfloat162*)oh)[i] = __nv_bfloat162(h0, h1);
    ((__nv_bfloat162*)ol)[i] = __nv_bfloat162(l0, l1);
}

// ---------------------------------------------------------------------------
// Transpose-convert: W fp32 [K][N] -> bf16 [N][K] hi/lo planes.
// ---------------------------------------------------------------------------
__global__ void convT_kernel(const float* __restrict__ W,
                             __nv_bfloat16* __restrict__ oh,
                             __nv_bfloat16* __restrict__ ol, int K, int N)
{
    __shared__ float t[32][33];
    const int n0 = blockIdx.x * 32, k0 = blockIdx.y * 32;
#pragma unroll
    for (int i = 0; i < 4; i++) {
        int k = threadIdx.y + i * 8;
        t[k][threadIdx.x] = W[(size_t)(k0 + k) * N + n0 + threadIdx.x];
    }
    __syncthreads();
#pragma unroll
    for (int i = 0; i < 4; i++) {
        int n = threadIdx.y + i * 8;
        float x = t[threadIdx.x][n];
        __nv_bfloat16 h = __float2bfloat16_rn(x);
        __nv_bfloat16 l = __float2bfloat16_rn(x - __bfloat162float(h));
        size_t o = (size_t)(n0 + n) * K + k0 + threadIdx.x;
        oh[o] = h;
        ol[o] = l;
    }
}

// ---------------------------------------------------------------------------
// GEMM (unchanged): 128x128, BK=32, 3-stage cp.async, 2 CTAs/SM.
// ---------------------------------------------------------------------------
#define PL 8192
#define STG (4 * PL)
#define NSTAGE 3

__global__ __launch_bounds__(256, 2)
void gemm_mma_kernel(const __nv_bfloat16* __restrict__ Ah, const __nv_bfloat16* __restrict__ Al,
                     const __nv_bfloat16* __restrict__ Bh, const __nv_bfloat16* __restrict__ Bl,
                     const float* __restrict__ bias, float* __restrict__ C,
                     int M, int N, int K)
{
    extern __shared__ __align__(16) char sm[];

    const int tid = threadIdx.x;
    const int w   = tid >> 5;
    const int l   = tid & 31;
    const int row0 = blockIdx.y * 128;
    const int col0 = blockIdx.x * 128;
    const int m0w = (w >> 2) * 64;
    const int n0w = (w & 3) * 32;

    float acc[4][4][4];
#pragma unroll
    for (int i = 0; i < 4; i++)
#pragma unroll
        for (int j = 0; j < 4; j++)
#pragma unroll
            for (int q = 0; q < 4; q++) acc[i][j][q] = 0.f;

    const uint32_t sb = smem_u32(sm);

    const int rA   = m0w + (l & 15);
    const uint32_t selA = (uint32_t)((rA >> 1) & 3);
    const uint32_t c0A  = (uint32_t)(l >> 4);
    const uint32_t aRel0 = (uint32_t)rA * 64 + ((c0A ^ selA) << 4);
    const uint32_t aRel1 = (uint32_t)rA * 64 + (((c0A + 2) ^ selA) << 4);
    const int bg = l >> 3;
    const int rB = n0w + (bg >> 1) * 8 + (l & 7);
    const uint32_t selB = (uint32_t)((rB >> 1) & 3);
    const uint32_t c0B  = (uint32_t)(bg & 1);
    const uint32_t bRel0 = 2u * PL + (uint32_t)rB * 64 + ((c0B ^ selB) << 4);
    const uint32_t bRel1 = 2u * PL + (uint32_t)rB * 64 + (((c0B + 2) ^ selB) << 4);

    const int fr = tid >> 1;
    const int fc = (tid & 1) * 2;
    const uint32_t fsel = (uint32_t)((fr >> 1) & 3);
    const uint32_t d0 = (uint32_t)fr * 64 + (((uint32_t)fc ^ fsel) << 4);
    const uint32_t d1 = (uint32_t)fr * 64 + ((((uint32_t)fc + 1) ^ fsel) << 4);
    const __nv_bfloat16* gAh = Ah + (size_t)(row0 + fr) * K + fc * 8;
    const __nv_bfloat16* gAl = Al + (size_t)(row0 + fr) * K + fc * 8;
    const __nv_bfloat16* gBh = Bh + (size_t)(col0 + fr) * K + fc * 8;
    const __nv_bfloat16* gBl = Bl + (size_t)(col0 + fr) * K + fc * 8;

    const int nch = K >> 5;

    auto issue = [&](int kc, int s) {
        const int ke = kc << 5;
        const uint32_t st = sb + (uint32_t)s * STG;
        CP16(st + d0,          gAh + ke);
        CP16(st + d1,          gAh + ke + 8);
        CP16(st + PL + d0,     gAl + ke);
        CP16(st + PL + d1,     gAl + ke + 8);
        CP16(st + 2 * PL + d0, gBh + ke);
        CP16(st + 2 * PL + d1, gBh + ke + 8);
        CP16(st + 3 * PL + d0, gBl + ke);
        CP16(st + 3 * PL + d1, gBl + ke + 8);
        CP_COMMIT();
    };

    issue(0, 0);
    issue(1, 1);

    int s = 0;
    for (int kc = 0; kc < nch; kc++) {
        if (kc + 2 < nch) { CP_WAIT1(); } else { CP_WAIT0(); }
        __syncthreads();
        if (kc + 2 < nch) {
            int s2 = s + 2; if (s2 >= NSTAGE) s2 -= NSTAGE;
            issue(kc + 2, s2);
        }

        const uint32_t stb = sb + (uint32_t)s * STG;
#pragma unroll
        for (int ks = 0; ks < 2; ks++) {
            const uint32_t aR = ks ? aRel1 : aRel0;
            const uint32_t bR = ks ? bRel1 : bRel0;
            uint32_t ah[4][4], al[4][4];
#pragma unroll
            for (int mt = 0; mt < 4; mt++) {
                LDSM4(ah[mt], stb + aR + mt * 1024);
                LDSM4(al[mt], stb + PL + aR + mt * 1024);
            }
            uint32_t bh[4][2], bl[4][2];
#pragma unroll
            for (int jp = 0; jp < 2; jp++) {
                uint32_t r[4];
                LDSM4(r, stb + bR + jp * 1024);
                bh[2 * jp][0] = r[0]; bh[2 * jp][1] = r[1];
                bh[2 * jp + 1][0] = r[2]; bh[2 * jp + 1][1] = r[3];
                LDSM4(r, stb + PL + bR + jp * 1024);
                bl[2 * jp][0] = r[0]; bl[2 * jp][1] = r[1];
                bl[2 * jp + 1][0] = r[2]; bl[2 * jp + 1][1] = r[3];
            }
#pragma unroll
            for (int mt = 0; mt < 4; mt++)
#pragma unroll
                for (int nt = 0; nt < 4; nt++)
                    mma_bf16(acc[mt][nt], ah[mt], bh[nt]);
#pragma unroll
            for (int mt = 0; mt < 4; mt++)
#pragma unroll
                for (int nt = 0; nt < 4; nt++)
                    mma_bf16(acc[mt][nt], ah[mt], bl[nt]);
#pragma unroll
            for (int mt = 0; mt < 4; mt++)
#pragma unroll
                for (int nt = 0; nt < 4; nt++)
                    mma_bf16(acc[mt][nt], al[mt], bh[nt]);
        }
        if (++s >= NSTAGE) s = 0;
    }

    float2 bb[4];
#pragma unroll
    for (int nt = 0; nt < 4; nt++) {
        int cg = col0 + n0w + 8 * nt + 2 * (l & 3);
        bb[nt] = make_float2(bias[cg], bias[cg + 1]);
    }
#pragma unroll
    for (int mt = 0; mt < 4; mt++) {
        int rg = row0 + m0w + 16 * mt + (l >> 2);
#pragma unroll
        for (int nt = 0; nt < 4; nt++) {
            int cg = col0 + n0w + 8 * nt + 2 * (l & 3);
            *(float2*)&C[(size_t)rg * N + cg] =
                make_float2(acc[mt][nt][0] + bb[nt].x, acc[mt][nt][1] + bb[nt].y);
            *(float2*)&C[(size_t)(rg + 8) * N + cg] =
                make_float2(acc[mt][nt][2] + bb[nt].x, acc[mt][nt][3] + bb[nt].y);
        }
    }
}

// ---------------------------------------------------------------------------
// RoPE: read fp32 q,k from qkv; write rotated, split bf16 planes directly.
// Q pre-scaled by 1/sqrt(64). No fp32 writeback.
// ---------------------------------------------------------------------------
__global__ void rope_kernel(const float* __restrict__ qkv,
                            __nv_bfloat16* __restrict__ qh, __nv_bfloat16* __restrict__ ql,
                            __nv_bfloat16* __restrict__ kh, __nv_bfloat16* __restrict__ kl,
                            const int* __restrict__ layer_p)
{
    int idx = blockIdx.x * blockDim.x + threadIdx.x;
    if (idx >= NROWS * NH * 32) return;
    int i  = idx & 31;
    int hh = (idx >> 5) % NH;
    int bs = (idx >> 5) / NH;
    int s  = bs & (NS - 1);

    bool is_global = (layer_p[0] % 3) == 0;
    float theta = is_global ? 160000.f : 10000.f;
    float freq  = powf(theta, -(float)(2 * i) / 64.f);
    float ang   = (float)s * freq;
    float sn, cs;
    sincosf(ang, &sn, &cs);

    size_t base = (size_t)bs * NQKV + hh * NHD + 2 * i;
    float qe = qkv[base], qo = qkv[base + 1];
    float q0 = (qe * cs - qo * sn) * 0.125f;
    float q1 = (qo * cs + qe * sn) * 0.125f;
    float ke = qkv[base + ND], ko = qkv[base + ND + 1];
    float k0 = ke * cs - ko * sn;
    float k1 = ko * cs + ke * sn;

    size_t o = (size_t)bs * ND + hh * NHD + 2 * i;
    __nv_bfloat16 h0 = __float2bfloat16_rn(q0), h1 = __float2bfloat16_rn(q1);
    *(__nv_bfloat162*)&qh[o] = __nv_bfloat162(h0, h1);
    *(__nv_bfloat162*)&ql[o] = __nv_bfloat162(
        __float2bfloat16_rn(q0 - __bfloat162float(h0)),
        __float2bfloat16_rn(q1 - __bfloat162float(h1)));
    h0 = __float2bfloat16_rn(k0); h1 = __float2bfloat16_rn(k1);
    *(__nv_bfloat162*)&kh[o] = __nv_bfloat162(h0, h1);
    *(__nv_bfloat162*)&kl[o] = __nv_bfloat162(
        __float2bfloat16_rn(k0 - __bfloat162float(h0)),
        __float2bfloat16_rn(k1 - __bfloat162float(h1)));
}

// ---------------------------------------------------------------------------
// conv_v: V fp32 [b*NS+s][h*64+d] -> transposed split planes [b][h][d][s].
// grid (NS/32, NB*NH*2), block (32,8); 32x32 smem transpose tiles.
// ---------------------------------------------------------------------------
__global__ void conv_v_kernel(const float* __restrict__ qkv,
                              __nv_bfloat16* __restrict__ vth,
                              __nv_bfloat16* __restrict__ vtl)
{
    __shared__ float t[32][33];
    const int s0 = blockIdx.x * 32;
    const int gy = blockIdx.y;
    const int d0 = (gy & 1) * 32;
    const int bh = gy >> 1;
    const int hh = bh % NH;
    const int b  = bh / NH;
#pragma unroll
    for (int i = 0; i < 4; i++) {
        int s = threadIdx.y + i * 8;
        t[s][threadIdx.x] = qkv[(size_t)(b * NS + s0 + s) * NQKV + 2 * ND + hh * NHD + d0 + threadIdx.x];
    }
    __syncthreads();
#pragma unroll
    for (int i = 0; i < 4; i++) {
        int d = threadIdx.y + i * 8;
        float x = t[threadIdx.x][d];
        __nv_bfloat16 h = __float2bfloat16_rn(x);
        __nv_bfloat16 l = __float2bfloat16_rn(x - __bfloat162float(h));
        size_t o = ((size_t)(b * NH + hh) * NHD + d0 + d) * NS + s0 + threadIdx.x;
        vth[o] = h;
        vtl[o] = l;
    }
}

// ---------------------------------------------------------------------------
// Tensor-core flash attention on pre-split bf16 planes; cp.async tile loads.
// ---------------------------------------------------------------------------
#define TSROW 144
#define TPL (64 * TSROW)   // 9216 B per plane

__global__ __launch_bounds__(256)
void attn_mma_kernel(const __nv_bfloat16* __restrict__ qh_g, const __nv_bfloat16* __restrict__ ql_g,
                     const __nv_bfloat16* __restrict__ kh_g, const __nv_bfloat16* __restrict__ kl_g,
                     const __nv_bfloat16* __restrict__ vth_g, const __nv_bfloat16* __restrict__ vtl_g,
                     __nv_bfloat16* __restrict__ aoh, __nv_bfloat16* __restrict__ aol,
                     const int* __restrict__ layer_p)
{
    extern __shared__ __align__(16) char sm[];
    // planes: 0 Qh, 1 Ql, 2 Kh/Ph, 3 Kl/Pl, 4 Vth, 5 Vtl
    char* Kh = sm + 2 * TPL;
    char* Kl = sm + 3 * TPL;
    float* Sbuf  = (float*)(sm + 6 * TPL);   // [64][68]
    float* row_m = Sbuf + 64 * 68;
    float* row_l = row_m + 64;
    float* row_s = row_l + 64;

    const int tid = threadIdx.x;
    const int w   = tid >> 5;
    const int l   = tid & 31;
    const int blk = blockIdx.x;
    const int qt  = blk & 31;
    const int hh  = (blk >> 5) % NH;
    const int b   = blk / (32 * NH);
    const bool is_global = (layer_p[0] % 3) == 0;
    const int q0 = qt * 64;

    const int mrow = (w & 3) * 16;
    const int ncol = (w >> 2) * 32;
    const uint32_t sb = smem_u32(sm);
    const uint32_t aRel = (uint32_t)(mrow + (l & 15)) * TSROW + (uint32_t)((l >> 4) * 16);
    const int bg = l >> 3;
    const uint32_t bRel = (uint32_t)(ncol + (bg >> 1) * 8 + (l & 7)) * TSROW
                        + (uint32_t)((bg & 1) * 16);

    // cp.async fill pattern: row r = tid>>2, segs (tid&3)*2, +1  (8x16B per row)
    const int fr  = tid >> 2;
    const int fs  = (tid & 3) * 2;
    const uint32_t fRel = (uint32_t)fr * TSROW + (uint32_t)fs * 16;

    // Q planes (load once)
    {
        const __nv_bfloat16* gq  = qh_g + (size_t)(b * NS + q0 + fr) * ND + hh * NHD + fs * 8;
        const __nv_bfloat16* gql = ql_g + (size_t)(b * NS + q0 + fr) * ND + hh * NHD + fs * 8;
        CP16(sb + fRel,            gq);
        CP16(sb + fRel + 16,       gq + 8);
        CP16(sb + TPL + fRel,      gql);
        CP16(sb + TPL + fRel + 16, gql + 8);
        CP_COMMIT();
    }
    if (tid < 64) { row_m[tid] = NEG_BIG; row_l[tid] = 0.f; }

    float oacc[4][4];
#pragma unroll
    for (int i = 0; i < 4; i++)
#pragma unroll
        for (int j = 0; j < 4; j++) oacc[i][j] = 0.f;

    const int kt0 = is_global ? 0 : max(0, qt - 2);
    const int kt1 = is_global ? 31 : min(31, qt + 2);

    for (int kt = kt0; kt <= kt1; kt++) {
        __syncthreads();   // prior P/V consumers done before overwrite
        {
            const __nv_bfloat16* gkh = kh_g + (size_t)(b * NS + kt * 64 + fr) * ND + hh * NHD + fs * 8;
            const __nv_bfloat16* gkl = kl_g + (size_t)(b * NS + kt * 64 + fr) * ND + hh * NHD + fs * 8;
            const __nv_bfloat16* gvh = vth_g + ((size_t)(b * NH + hh) * NHD + fr) * NS + kt * 64 + fs * 8;
            const __nv_bfloat16* gvl = vtl_g + ((size_t)(b * NH + hh) * NHD + fr) * NS + kt * 64 + fs * 8;
            CP16(sb + 2 * TPL + fRel,      gkh);
            CP16(sb + 2 * TPL + fRel + 16, gkh + 8);
            CP16(sb + 3 * TPL + fRel,      gkl);
            CP16(sb + 3 * TPL + fRel + 16, gkl + 8);
            CP16(sb + 4 * TPL + fRel,      gvh);
            CP16(sb + 4 * TPL + fRel + 16, gvh + 8);
            CP16(sb + 5 * TPL + fRel,      gvl);
            CP16(sb + 5 * TPL + fRel + 16, gvl + 8);
            CP_COMMIT();
            CP_WAIT0();
        }
        __syncthreads();

        // ---- S = Q K^T (bf16x3) ----
        float sa[4][4];
#pragma unroll
        for (int i = 0; i < 4; i++)
#pragma unroll
            for (int j = 0; j < 4; j++) sa[i][j] = 0.f;
#pragma unroll
        for (int ks = 0; ks < 4; ks++) {
            const uint32_t kso = (uint32_t)(ks * 32);
            uint32_t qh4[4], ql4[4];
            LDSM4(qh4, sb + aRel + kso);
            LDSM4(ql4, sb + TPL + aRel + kso);
            uint32_t bh[4][2], bl[4][2];
#pragma unroll
            for (int jp = 0; jp < 2; jp++) {
                uint32_t r4[4];
                LDSM4(r4, sb + 2 * TPL + bRel + jp * (16 * TSROW) + kso);
                bh[2 * jp][0] = r4[0]; bh[2 * jp][1] = r4[1];
                bh[2 * jp + 1][0] = r4[2]; bh[2 * jp + 1][1] = r4[3];
                LDSM4(r4, sb + 3 * TPL + bRel + jp * (16 * TSROW) + kso);
                bl[2 * jp][0] = r4[0]; bl[2 * jp][1] = r4[1];
                bl[2 * jp + 1][0] = r4[2]; bl[2 * jp + 1][1] = r4[3];
            }
#pragma unroll
            for (int nt = 0; nt < 4; nt++) mma_bf16(sa[nt], qh4, bh[nt]);
#pragma unroll
            for (int nt = 0; nt < 4; nt++) mma_bf16(sa[nt], qh4, bl[nt]);
#pragma unroll
            for (int nt = 0; nt < 4; nt++) mma_bf16(sa[nt], ql4, bh[nt]);
        }
        {
            int fr0 = mrow + (l >> 2);
#pragma unroll
            for (int nt = 0; nt < 4; nt++) {
                int col = ncol + 8 * nt + 2 * (l & 3);
                *(float2*)&Sbuf[fr0 * 68 + col]       = make_float2(sa[nt][0], sa[nt][1]);
                *(float2*)&Sbuf[(fr0 + 8) * 68 + col] = make_float2(sa[nt][2], sa[nt][3]);
            }
        }
        __syncthreads();

        // ---- banded mask + online softmax; emit Ph/Pl (reuse K planes) ----
        {
            int r  = tid >> 2;
            int qd = tid & 3;
            float* Pr = &Sbuf[r * 68 + qd * 16];
            if (!is_global) {
#pragma unroll
                for (int c = 0; c < 16; c++) {
                    int dlt = (q0 + r) - (kt * 64 + qd * 16 + c);
                    if (dlt < 0) dlt = -dlt;
                    if (dlt > 128) Pr[c] = NEG_BIG;
                }
            }
            float mloc = NEG_BIG;
#pragma unroll
            for (int c = 0; c < 16; c++) mloc = fmaxf(mloc, Pr[c]);
            mloc = fmaxf(mloc, __shfl_xor_sync(0xffffffffu, mloc, 1));
            mloc = fmaxf(mloc, __shfl_xor_sync(0xffffffffu, mloc, 2));
            float m_old = row_m[r];
            float m_new = fmaxf(m_old, mloc);
            float ls = 0.f;
#pragma unroll
            for (int c = 0; c < 16; c += 2) {
                float e0 = __expf(Pr[c]     - m_new);
                float e1 = __expf(Pr[c + 1] - m_new);
                ls += e0 + e1;
                __nv_bfloat16 h0 = __float2bfloat16_rn(e0);
                __nv_bfloat16 h1 = __float2bfloat16_rn(e1);
                uint32_t off = (uint32_t)(r * TSROW + (qd * 16 + c) * 2);
                *(__nv_bfloat162*)(Kh + off) = __nv_bfloat162(h0, h1);
                *(__nv_bfloat162*)(Kl + off) = __nv_bfloat162(
                    __float2bfloat16_rn(e0 - __bfloat162float(h0)),
                    __float2bfloat16_rn(e1 - __bfloat162float(h1)));
            }
            ls += __shfl_xor_sync(0xffffffffu, ls, 1);
            ls += __shfl_xor_sync(0xffffffffu, ls, 2);
            if (qd == 0) {
                float fac = __expf(m_old - m_new);
                row_s[r] = fac;
                row_m[r] = m_new;
                row_l[r] = row_l[r] * fac + ls;
            }
        }
        __syncthreads();

        // ---- rescale O; O += P @ V (bf16x3) ----
        {
            float f0 = row_s[mrow + (l >> 2)];
            float f1 = row_s[mrow + 8 + (l >> 2)];
#pragma unroll
            for (int nt = 0; nt < 4; nt++) {
                oacc[nt][0] *= f0; oacc[nt][1] *= f0;
                oacc[nt][2] *= f1; oacc[nt][3] *= f1;
            }
#pragma unroll
            for (int ks = 0; ks < 4; ks++) {
                const uint32_t kso = (uint32_t)(ks * 32);
                uint32_t ph4[4], pl4[4];
                LDSM4(ph4, sb + 2 * TPL + aRel + kso);
                LDSM4(pl4, sb + 3 * TPL + aRel + kso);
                uint32_t vh[4][2], vl[4][2];
#pragma unroll
                for (int jp = 0; jp < 2; jp++) {
                    uint32_t r4[4];
                    LDSM4(r4, sb + 4 * TPL + bRel + jp * (16 * TSROW) + kso);
                    vh[2 * jp][0] = r4[0]; vh[2 * jp][1] = r4[1];
                    vh[2 * jp + 1][0] = r4[2]; vh[2 * jp + 1][1] = r4[3];
                    LDSM4(r4, sb + 5 * TPL + bRel + jp * (16 * TSROW) + kso);
                    vl[2 * jp][0] = r4[0]; vl[2 * jp][1] = r4[1];
                    vl[2 * jp + 1][0] = r4[2]; vl[2 * jp + 1][1] = r4[3];
                }
#pragma unroll
                for (int nt = 0; nt < 4; nt++) mma_bf16(oacc[nt], ph4, vh[nt]);
#pragma unroll
                for (int nt = 0; nt < 4; nt++) mma_bf16(oacc[nt], ph4, vl[nt]);
#pragma unroll
                for (int nt = 0; nt < 4; nt++) mma_bf16(oacc[nt], pl4, vh[nt]);
            }
        }
    }

    // normalize + write attn bf16 hi/lo planes
    {
        float i0 = 1.f / row_l[mrow + (l >> 2)];
        float i1 = 1.f / row_l[mrow + 8 + (l >> 2)];
        size_t r0 = (size_t)(b * NS + q0 + mrow + (l >> 2)) * ND;
        size_t r1 = r0 + 8 * (size_t)ND;
#pragma unroll
        for (int nt = 0; nt < 4; nt++) {
            int col = hh * NHD + ncol + 8 * nt + 2 * (l & 3);
            float v0 = oacc[nt][0] * i0, v1 = oacc[nt][1] * i0;
            float v2 = oacc[nt][2] * i1, v3 = oacc[nt][3] * i1;
            __nv_bfloat16 h0 = __float2bfloat16_rn(v0), h1 = __float2bfloat16_rn(v1);
            __nv_bfloat16 h2 = __float2bfloat16_rn(v2), h3 = __float2bfloat16_rn(v3);
            *(__nv_bfloat162*)&aoh[r0 + col] = __nv_bfloat162(h0, h1);
            *(__nv_bfloat162*)&aol[r0 + col] = __nv_bfloat162(
                __float2bfloat16_rn(v0 - __bfloat162float(h0)),
                __float2bfloat16_rn(v1 - __bfloat162float(h1)));
            *(__nv_bfloat162*)&aoh[r1 + col] = __nv_bfloat162(h2, h3);
            *(__nv_bfloat162*)&aol[r1 + col] = __nv_bfloat162(
                __float2bfloat16_rn(v2 - __bfloat162float(h2)),
                __float2bfloat16_rn(v3 - __bfloat162float(h3)));
        }
    }
}

// ---------------------------------------------------------------------------
extern "C" void kernel_launch(void* const* d_in, const int* in_sizes, int n_in,
                              void* d_out, int out_size)
{
    const float* x     = (const float*)d_in[0];
    const float* Wqkv  = (const float*)d_in[1];
    const float* bqkv  = (const float*)d_in[2];
    const float* Wout  = (const float*)d_in[3];
    const float* bout  = (const float*)d_in[4];
    const int*   layer = (const int*)d_in[5];
    float* out = (float*)d_out;

    float *qkv;
    __nv_bfloat16 *xh, *xl, *ah, *al, *wqh, *wql, *woh, *wol;
    __nv_bfloat16 *qh, *ql, *kh, *kl, *vth, *vtl;
    cudaGetSymbolAddress((void**)&qkv,  g_qkv);
    cudaGetSymbolAddress((void**)&xh, g_xh);
    cudaGetSymbolAddress((void**)&xl, g_xl);
    cudaGetSymbolAddress((void**)&ah, g_ah);
    cudaGetSymbolAddress((void**)&al, g_al);
    cudaGetSymbolAddress((void**)&wqh, g_wqh);
    cudaGetSymbolAddress((void**)&wql, g_wql);
    cudaGetSymbolAddress((void**)&woh, g_woh);
    cudaGetSymbolAddress((void**)&wol, g_wol);
    cudaGetSymbolAddress((void**)&qh, g_qh);
    cudaGetSymbolAddress((void**)&ql, g_ql);
    cudaGetSymbolAddress((void**)&kh, g_kh);
    cudaGetSymbolAddress((void**)&kl, g_kl);
    cudaGetSymbolAddress((void**)&vth, g_vth);
    cudaGetSymbolAddress((void**)&vtl, g_vtl);

    const int gemm_smem = NSTAGE * STG;   // 98304 B
    cudaFuncSetAttribute(gemm_mma_kernel, cudaFuncAttributeMaxDynamicSharedMemorySize, gemm_smem);
    const int attn_smem = 6 * TPL + 64 * 68 * 4 + 3 * 64 * 4;   // 73472 B
    cudaFuncSetAttribute(attn_mma_kernel, cudaFuncAttributeMaxDynamicSharedMemorySize, attn_smem);

    // 0) conversions
    conv_rows_kernel<<<(NROWS * ND / 2 + 255) / 256, 256>>>(x, xh, xl, NROWS * ND / 2);
    convT_kernel<<<dim3(NQKV / 32, ND / 32), dim3(32, 8)>>>(Wqkv, wqh, wql, ND, NQKV);
    convT_kernel<<<dim3(ND / 32, ND / 32), dim3(32, 8)>>>(Wout, woh, wol, ND, ND);

    // 1) qkv = x @ Wqkv + bqkv
    gemm_mma_kernel<<<dim3(NQKV / 128, NROWS / 128), 256, gemm_smem>>>(
        xh, xl, wqh, wql, bqkv, qkv, NROWS, NQKV, ND);
    // 2) RoPE -> split bf16 Q/K planes; V -> transposed split planes
    rope_kernel<<<(NROWS * NH * 32) / 256, 256>>>(qkv, qh, ql, kh, kl, layer);
    conv_v_kernel<<<dim3(NS / 32, NB * NH * 2), dim3(32, 8)>>>(qkv, vth, vtl);
    // 3) tensor-core banded attention on pre-split planes
    attn_mma_kernel<<<NB * NH * 32, 256, attn_smem>>>(qh, ql, kh, kl, vth, vtl, ah, al, layer);
    // 4) out = attn @ Wout + bout
    gemm_mma_kernel<<<dim3(ND / 128, NROWS / 128), 256, gemm_smem>>>(
        ah, al, woh, wol, bout, out, NROWS, ND, ND);
}

// round 12
// speedup vs baseline: 1.8140x; 1.2386x over previous
#include <cuda_runtime.h>
#include <cuda_bf16.h>
#include <cuda_fp16.h>
#include <math.h>
#include <stdint.h>

#define NB 2
#define NS 2048
#define ND 768
#define NH 12
#define NHD 64
#define NQKV 2304
#define NROWS 4096   // NB*NS

#define NEG_BIG (-1e30f)

// ---------------- scratch (device globals; allocation-free) -----------------
__device__ float g_qkv[(size_t)NROWS * NQKV];                 // 37.7 MB
__device__ __half g_x16[(size_t)NROWS * ND];                  // x fp16 (A of GEMM1)
__device__ __half g_a16[(size_t)NROWS * ND];                  // attn out fp16 (A of GEMM2)
__device__ __half g_wqh16[(size_t)NQKV * ND];                 // Wqkv^T fp16 hi [N][K]
__device__ __half g_wql16[(size_t)NQKV * ND];                 // Wqkv^T fp16 lo
__device__ __half g_woh16[(size_t)ND * ND];                   // Wout^T fp16 hi
__device__ __half g_wol16[(size_t)ND * ND];                   // Wout^T fp16 lo
// attention operand planes (bf16 hi/lo; bf16x3 kept inside attention)
__device__ __nv_bfloat16 g_qh[(size_t)NROWS * ND];
__device__ __nv_bfloat16 g_ql[(size_t)NROWS * ND];
__device__ __nv_bfloat16 g_kh[(size_t)NROWS * ND];
__device__ __nv_bfloat16 g_kl[(size_t)NROWS * ND];
__device__ __nv_bfloat16 g_vth[(size_t)NROWS * ND];           // V^T [b][h][d][s]
__device__ __nv_bfloat16 g_vtl[(size_t)NROWS * ND];

__device__ __forceinline__ uint32_t smem_u32(const void* p) {
    uint32_t a;
    asm("{ .reg .u64 t; cvta.to.shared.u64 t, %1; cvt.u32.u64 %0, t; }" : "=r"(a) : "l"(p));
    return a;
}

__device__ __forceinline__ void mma_bf16(float c[4], const uint32_t a[4], const uint32_t b[2]) {
    asm volatile(
        "mma.sync.aligned.m16n8k16.row.col.f32.bf16.bf16.f32 "
        "{%0,%1,%2,%3}, {%4,%5,%6,%7}, {%8,%9}, {%0,%1,%2,%3};"
        : "+f"(c[0]), "+f"(c[1]), "+f"(c[2]), "+f"(c[3])
        : "r"(a[0]), "r"(a[1]), "r"(a[2]), "r"(a[3]), "r"(b[0]), "r"(b[1]));
}

__device__ __forceinline__ void mma_f16(float c[4], const uint32_t a[4], const uint32_t b[2]) {
    asm volatile(
        "mma.sync.aligned.m16n8k16.row.col.f32.f16.f16.f32 "
        "{%0,%1,%2,%3}, {%4,%5,%6,%7}, {%8,%9}, {%0,%1,%2,%3};"
        : "+f"(c[0]), "+f"(c[1]), "+f"(c[2]), "+f"(c[3])
        : "r"(a[0]), "r"(a[1]), "r"(a[2]), "r"(a[3]), "r"(b[0]), "r"(b[1]));
}

#define LDSM4(r, addr) \
    asm volatile("ldmatrix.sync.aligned.m8n8.x4.shared.b16 {%0,%1,%2,%3}, [%4];" \
                 : "=r"((r)[0]), "=r"((r)[1]), "=r"((r)[2]), "=r"((r)[3]) : "r"(addr))

#define CP16(dst, src) \
    asm volatile("cp.async.cg.shared.global [%0], [%1], 16;" :: "r"(dst), "l"(src))
#define CP_COMMIT() asm volatile("cp.async.commit_group;")
#define CP_WAIT2()  asm volatile("cp.async.wait_group 2;")
#define CP_WAIT1()  asm volatile("cp.async.wait_group 1;")
#define CP_WAIT0()  asm volatile("cp.async.wait_group 0;")

// ---------------------------------------------------------------------------
// x fp32 -> fp16 (single plane).
// ---------------------------------------------------------------------------
__global__ void conv_fp16_kernel(const float* __restrict__ in,
                                 __half* __restrict__ o, int n2)
{
    int i = blockIdx.x * blockDim.x + threadIdx.x;
    if (i >= n2) return;
    float2 v = ((const float2*)in)[i];
    ((__half2*)o)[i] = __floats2half2_rn(v.x, v.y);
}

// ---------------------------------------------------------------------------
// Transpose-convert: W fp32 [K][N] -> fp16 [N][K] hi/lo planes.
// ---------------------------------------------------------------------------
__global__ void convT16_kernel(const float* __restrict__ W,
                               __half* __restrict__ oh,
                               __half* __restrict__ ol, int K, int N)
{
    __shared__ float t[32][33];
    const int n0 = blockIdx.x * 32, k0 = blockIdx.y * 32;
#pragma unroll
    for (int i = 0; i < 4; i++) {
        int k = threadIdx.y + i * 8;
        t[k][threadIdx.x] = W[(size_t)(k0 + k) * N + n0 + threadIdx.x];
    }
    __syncthreads();
#pragma unroll
    for (int i = 0; i < 4; i++) {
        int n = threadIdx.y + i * 8;
        float x = t[threadIdx.x][n];
        __half h = __float2half_rn(x);
        __half l = __float2half_rn(x - __half2float(h));
        size_t o = (size_t)(n0 + n) * K + k0 + threadIdx.x;
        oh[o] = h;
        ol[o] = l;
    }
}

// ---------------------------------------------------------------------------
// fp16 2-pass GEMM + bias: C = A @ (Bh + Bl)^T + bias  (fp32 accum/output)
// A: [M][K] fp16 single plane; B: [N][K] fp16 hi/lo (pre-transposed weights).
// Block 128x128, BK=32, 8 warps, warp tile 64x32.
// 4-stage cp.async pipeline, 24 KB/stage (96 KB) -> 2 CTAs/SM.
// ---------------------------------------------------------------------------
#define PL 8192
#define STG (3 * PL)       // 24576 B per stage (A, Bh, Bl)
#define NSTAGE 4

__global__ __launch_bounds__(256, 2)
void gemm_mma_kernel(const __half* __restrict__ A,
                     const __half* __restrict__ Bh, const __half* __restrict__ Bl,
                     const float* __restrict__ bias, float* __restrict__ C,
                     int M, int N, int K)
{
    extern __shared__ __align__(16) char sm[];

    const int tid = threadIdx.x;
    const int w   = tid >> 5;
    const int l   = tid & 31;
    const int row0 = blockIdx.y * 128;
    const int col0 = blockIdx.x * 128;
    const int m0w = (w >> 2) * 64;
    const int n0w = (w & 3) * 32;

    float acc[4][4][4];
#pragma unroll
    for (int i = 0; i < 4; i++)
#pragma unroll
        for (int j = 0; j < 4; j++)
#pragma unroll
            for (int q = 0; q < 4; q++) acc[i][j][q] = 0.f;

    const uint32_t sb = smem_u32(sm);

    const int rA   = m0w + (l & 15);
    const uint32_t selA = (uint32_t)((rA >> 1) & 3);
    const uint32_t c0A  = (uint32_t)(l >> 4);
    const uint32_t aRel0 = (uint32_t)rA * 64 + ((c0A ^ selA) << 4);
    const uint32_t aRel1 = (uint32_t)rA * 64 + (((c0A + 2) ^ selA) << 4);
    const int bg = l >> 3;
    const int rB = n0w + (bg >> 1) * 8 + (l & 7);
    const uint32_t selB = (uint32_t)((rB >> 1) & 3);
    const uint32_t c0B  = (uint32_t)(bg & 1);
    const uint32_t bRel0 = PL + (uint32_t)rB * 64 + ((c0B ^ selB) << 4);
    const uint32_t bRel1 = PL + (uint32_t)rB * 64 + (((c0B + 2) ^ selB) << 4);

    const int fr = tid >> 1;
    const int fc = (tid & 1) * 2;
    const uint32_t fsel = (uint32_t)((fr >> 1) & 3);
    const uint32_t d0 = (uint32_t)fr * 64 + (((uint32_t)fc ^ fsel) << 4);
    const uint32_t d1 = (uint32_t)fr * 64 + ((((uint32_t)fc + 1) ^ fsel) << 4);
    const __half* gA  = A  + (size_t)(row0 + fr) * K + fc * 8;
    const __half* gBh = Bh + (size_t)(col0 + fr) * K + fc * 8;
    const __half* gBl = Bl + (size_t)(col0 + fr) * K + fc * 8;

    const int nch = K >> 5;

    auto issue = [&](int kc, int s) {
        const int ke = kc << 5;
        const uint32_t st = sb + (uint32_t)s * STG;
        CP16(st + d0,          gA + ke);
        CP16(st + d1,          gA + ke + 8);
        CP16(st + PL + d0,     gBh + ke);
        CP16(st + PL + d1,     gBh + ke + 8);
        CP16(st + 2 * PL + d0, gBl + ke);
        CP16(st + 2 * PL + d1, gBl + ke + 8);
        CP_COMMIT();
    };

    issue(0, 0);
    issue(1, 1);
    issue(2, 2);

    int s = 0;
    for (int kc = 0; kc < nch; kc++) {
        if (kc + 3 <= nch)      { CP_WAIT2(); }
        else if (kc + 2 <= nch) { CP_WAIT1(); }
        else                    { CP_WAIT0(); }
        __syncthreads();
        if (kc + 3 < nch) {
            int s3 = s + 3; if (s3 >= NSTAGE) s3 -= NSTAGE;
            issue(kc + 3, s3);
        }

        const uint32_t stb = sb + (uint32_t)s * STG;
#pragma unroll
        for (int ks = 0; ks < 2; ks++) {
            const uint32_t aR = ks ? aRel1 : aRel0;
            const uint32_t bR = ks ? bRel1 : bRel0;
            uint32_t a4[4][4];
#pragma unroll
            for (int mt = 0; mt < 4; mt++)
                LDSM4(a4[mt], stb + aR + mt * 1024);
            uint32_t bh[4][2], bl[4][2];
#pragma unroll
            for (int jp = 0; jp < 2; jp++) {
                uint32_t r[4];
                LDSM4(r, stb + bR + jp * 1024);
                bh[2 * jp][0] = r[0]; bh[2 * jp][1] = r[1];
                bh[2 * jp + 1][0] = r[2]; bh[2 * jp + 1][1] = r[3];
                LDSM4(r, stb + PL + bR + jp * 1024);
                bl[2 * jp][0] = r[0]; bl[2 * jp][1] = r[1];
                bl[2 * jp + 1][0] = r[2]; bl[2 * jp + 1][1] = r[3];
            }
#pragma unroll
            for (int mt = 0; mt < 4; mt++)
#pragma unroll
                for (int nt = 0; nt < 4; nt++)
                    mma_f16(acc[mt][nt], a4[mt], bh[nt]);
#pragma unroll
            for (int mt = 0; mt < 4; mt++)
#pragma unroll
                for (int nt = 0; nt < 4; nt++)
                    mma_f16(acc[mt][nt], a4[mt], bl[nt]);
        }
        if (++s >= NSTAGE) s = 0;
    }

    float2 bb[4];
#pragma unroll
    for (int nt = 0; nt < 4; nt++) {
        int cg = col0 + n0w + 8 * nt + 2 * (l & 3);
        bb[nt] = make_float2(bias[cg], bias[cg + 1]);
    }
#pragma unroll
    for (int mt = 0; mt < 4; mt++) {
        int rg = row0 + m0w + 16 * mt + (l >> 2);
#pragma unroll
        for (int nt = 0; nt < 4; nt++) {
            int cg = col0 + n0w + 8 * nt + 2 * (l & 3);
            *(float2*)&C[(size_t)rg * N + cg] =
                make_float2(acc[mt][nt][0] + bb[nt].x, acc[mt][nt][1] + bb[nt].y);
            *(float2*)&C[(size_t)(rg + 8) * N + cg] =
                make_float2(acc[mt][nt][2] + bb[nt].x, acc[mt][nt][3] + bb[nt].y);
        }
    }
}

// ---------------------------------------------------------------------------
// RoPE: read fp32 q,k from qkv; write rotated, split bf16 planes directly.
// ---------------------------------------------------------------------------
__global__ void rope_kernel(const float* __restrict__ qkv,
                            __nv_bfloat16* __restrict__ qh, __nv_bfloat16* __restrict__ ql,
                            __nv_bfloat16* __restrict__ kh, __nv_bfloat16* __restrict__ kl,
                            const int* __restrict__ layer_p)
{
    int idx = blockIdx.x * blockDim.x + threadIdx.x;
    if (idx >= NROWS * NH * 32) return;
    int i  = idx & 31;
    int hh = (idx >> 5) % NH;
    int bs = (idx >> 5) / NH;
    int s  = bs & (NS - 1);

    bool is_global = (layer_p[0] % 3) == 0;
    float theta = is_global ? 160000.f : 10000.f;
    float freq  = powf(theta, -(float)(2 * i) / 64.f);
    float ang   = (float)s * freq;
    float sn, cs;
    sincosf(ang, &sn, &cs);

    size_t base = (size_t)bs * NQKV + hh * NHD + 2 * i;
    float qe = qkv[base], qo = qkv[base + 1];
    float q0 = (qe * cs - qo * sn) * 0.125f;
    float q1 = (qo * cs + qe * sn) * 0.125f;
    float ke = qkv[base + ND], ko = qkv[base + ND + 1];
    float k0 = ke * cs - ko * sn;
    float k1 = ko * cs + ke * sn;

    size_t o = (size_t)bs * ND + hh * NHD + 2 * i;
    __nv_bfloat16 h0 = __float2bfloat16_rn(q0), h1 = __float2bfloat16_rn(q1);
    *(__nv_bfloat162*)&qh[o] = __nv_bfloat162(h0, h1);
    *(__nv_bfloat162*)&ql[o] = __nv_bfloat162(
        __float2bfloat16_rn(q0 - __bfloat162float(h0)),
        __float2bfloat16_rn(q1 - __bfloat162float(h1)));
    h0 = __float2bfloat16_rn(k0); h1 = __float2bfloat16_rn(k1);
    *(__nv_bfloat162*)&kh[o] = __nv_bfloat162(h0, h1);
    *(__nv_bfloat162*)&kl[o] = __nv_bfloat162(
        __float2bfloat16_rn(k0 - __bfloat162float(h0)),
        __float2bfloat16_rn(k1 - __bfloat162float(h1)));
}

// ---------------------------------------------------------------------------
// conv_v: V fp32 [b*NS+s][h*64+d] -> transposed split bf16 planes [b][h][d][s].
// ---------------------------------------------------------------------------
__global__ void conv_v_kernel(const float* __restrict__ qkv,
                              __nv_bfloat16* __restrict__ vth,
                              __nv_bfloat16* __restrict__ vtl)
{
    __shared__ float t[32][33];
    const int s0 = blockIdx.x * 32;
    const int gy = blockIdx.y;
    const int d0 = (gy & 1) * 32;
    const int bh = gy >> 1;
    const int hh = bh % NH;
    const int b  = bh / NH;
#pragma unroll
    for (int i = 0; i < 4; i++) {
        int s = threadIdx.y + i * 8;
        t[s][threadIdx.x] = qkv[(size_t)(b * NS + s0 + s) * NQKV + 2 * ND + hh * NHD + d0 + threadIdx.x];
    }
    __syncthreads();
#pragma unroll
    for (int i = 0; i < 4; i++) {
        int d = threadIdx.y + i * 8;
        float x = t[threadIdx.x][d];
        __nv_bfloat16 h = __float2bfloat16_rn(x);
        __nv_bfloat16 l = __float2bfloat16_rn(x - __bfloat162float(h));
        size_t o = ((size_t)(b * NH + hh) * NHD + d0 + d) * NS + s0 + threadIdx.x;
        vth[o] = h;
        vtl[o] = l;
    }
}

// ---------------------------------------------------------------------------
// Tensor-core flash attention on pre-split bf16 planes (bf16x3 inside).
// Epilogue writes single fp16 plane (A operand of the fp16 out-projection).
// ---------------------------------------------------------------------------
#define TSROW 144
#define TPL (64 * TSROW)   // 9216 B per plane

__global__ __launch_bounds__(256)
void attn_mma_kernel(const __nv_bfloat16* __restrict__ qh_g, const __nv_bfloat16* __restrict__ ql_g,
                     const __nv_bfloat16* __restrict__ kh_g, const __nv_bfloat16* __restrict__ kl_g,
                     const __nv_bfloat16* __restrict__ vth_g, const __nv_bfloat16* __restrict__ vtl_g,
                     __half* __restrict__ ao,
                     const int* __restrict__ layer_p)
{
    extern __shared__ __align__(16) char sm[];
    // planes: 0 Qh, 1 Ql, 2 Kh/Ph, 3 Kl/Pl, 4 Vth, 5 Vtl
    char* Kh = sm + 2 * TPL;
    char* Kl = sm + 3 * TPL;
    float* Sbuf  = (float*)(sm + 6 * TPL);   // [64][68]
    float* row_m = Sbuf + 64 * 68;
    float* row_l = row_m + 64;
    float* row_s = row_l + 64;

    const int tid = threadIdx.x;
    const int w   = tid >> 5;
    const int l   = tid & 31;
    const int blk = blockIdx.x;
    const int qt  = blk & 31;
    const int hh  = (blk >> 5) % NH;
    const int b   = blk / (32 * NH);
    const bool is_global = (layer_p[0] % 3) == 0;
    const int q0 = qt * 64;

    const int mrow = (w & 3) * 16;
    const int ncol = (w >> 2) * 32;
    const uint32_t sb = smem_u32(sm);
    const uint32_t aRel = (uint32_t)(mrow + (l & 15)) * TSROW + (uint32_t)((l >> 4) * 16);
    const int bg = l >> 3;
    const uint32_t bRel = (uint32_t)(ncol + (bg >> 1) * 8 + (l & 7)) * TSROW
                        + (uint32_t)((bg & 1) * 16);

    const int fr  = tid >> 2;
    const int fs  = (tid & 3) * 2;
    const uint32_t fRel = (uint32_t)fr * TSROW + (uint32_t)fs * 16;

    // Q planes (load once)
    {
        const __nv_bfloat16* gq  = qh_g + (size_t)(b * NS + q0 + fr) * ND + hh * NHD + fs * 8;
        const __nv_bfloat16* gql = ql_g + (size_t)(b * NS + q0 + fr) * ND + hh * NHD + fs * 8;
        CP16(sb + fRel,            gq);
        CP16(sb + fRel + 16,       gq + 8);
        CP16(sb + TPL + fRel,      gql);
        CP16(sb + TPL + fRel + 16, gql + 8);
        CP_COMMIT();
    }
    if (tid < 64) { row_m[tid] = NEG_BIG; row_l[tid] = 0.f; }

    float oacc[4][4];
#pragma unroll
    for (int i = 0; i < 4; i++)
#pragma unroll
        for (int j = 0; j < 4; j++) oacc[i][j] = 0.f;

    const int kt0 = is_global ? 0 : max(0, qt - 2);
    const int kt1 = is_global ? 31 : min(31, qt + 2);

    for (int kt = kt0; kt <= kt1; kt++) {
        __syncthreads();
        {
            const __nv_bfloat16* gkh = kh_g + (size_t)(b * NS + kt * 64 + fr) * ND + hh * NHD + fs * 8;
            const __nv_bfloat16* gkl = kl_g + (size_t)(b * NS + kt * 64 + fr) * ND + hh * NHD + fs * 8;
            const __nv_bfloat16* gvh = vth_g + ((size_t)(b * NH + hh) * NHD + fr) * NS + kt * 64 + fs * 8;
            const __nv_bfloat16* gvl = vtl_g + ((size_t)(b * NH + hh) * NHD + fr) * NS + kt * 64 + fs * 8;
            CP16(sb + 2 * TPL + fRel,      gkh);
            CP16(sb + 2 * TPL + fRel + 16, gkh + 8);
            CP16(sb + 3 * TPL + fRel,      gkl);
            CP16(sb + 3 * TPL + fRel + 16, gkl + 8);
            CP16(sb + 4 * TPL + fRel,      gvh);
            CP16(sb + 4 * TPL + fRel + 16, gvh + 8);
            CP16(sb + 5 * TPL + fRel,      gvl);
            CP16(sb + 5 * TPL + fRel + 16, gvl + 8);
            CP_COMMIT();
            CP_WAIT0();
        }
        __syncthreads();

        // ---- S = Q K^T (bf16x3) ----
        float sa[4][4];
#pragma unroll
        for (int i = 0; i < 4; i++)
#pragma unroll
            for (int j = 0; j < 4; j++) sa[i][j] = 0.f;
#pragma unroll
        for (int ks = 0; ks < 4; ks++) {
            const uint32_t kso = (uint32_t)(ks * 32);
            uint32_t qh4[4], ql4[4];
            LDSM4(qh4, sb + aRel + kso);
            LDSM4(ql4, sb + TPL + aRel + kso);
            uint32_t bh[4][2], bl[4][2];
#pragma unroll
            for (int jp = 0; jp < 2; jp++) {
                uint32_t r4[4];
                LDSM4(r4, sb + 2 * TPL + bRel + jp * (16 * TSROW) + kso);
                bh[2 * jp][0] = r4[0]; bh[2 * jp][1] = r4[1];
                bh[2 * jp + 1][0] = r4[2]; bh[2 * jp + 1][1] = r4[3];
                LDSM4(r4, sb + 3 * TPL + bRel + jp * (16 * TSROW) + kso);
                bl[2 * jp][0] = r4[0]; bl[2 * jp][1] = r4[1];
                bl[2 * jp + 1][0] = r4[2]; bl[2 * jp + 1][1] = r4[3];
            }
#pragma unroll
            for (int nt = 0; nt < 4; nt++) mma_bf16(sa[nt], qh4, bh[nt]);
#pragma unroll
            for (int nt = 0; nt < 4; nt++) mma_bf16(sa[nt], qh4, bl[nt]);
#pragma unroll
            for (int nt = 0; nt < 4; nt++) mma_bf16(sa[nt], ql4, bh[nt]);
        }
        {
            int fr0 = mrow + (l >> 2);
#pragma unroll
            for (int nt = 0; nt < 4; nt++) {
                int col = ncol + 8 * nt + 2 * (l & 3);
                *(float2*)&Sbuf[fr0 * 68 + col]       = make_float2(sa[nt][0], sa[nt][1]);
                *(float2*)&Sbuf[(fr0 + 8) * 68 + col] = make_float2(sa[nt][2], sa[nt][3]);
            }
        }
        __syncthreads();

        // ---- banded mask + online softmax; emit Ph/Pl (reuse K planes) ----
        {
            int r  = tid >> 2;
            int qd = tid & 3;
            float* Pr = &Sbuf[r * 68 + qd * 16];
            if (!is_global) {
#pragma unroll
                for (int c = 0; c < 16; c++) {
                    int dlt = (q0 + r) - (kt * 64 + qd * 16 + c);
                    if (dlt < 0) dlt = -dlt;
                    if (dlt > 128) Pr[c] = NEG_BIG;
                }
            }
            float mloc = NEG_BIG;
#pragma unroll
            for (int c = 0; c < 16; c++) mloc = fmaxf(mloc, Pr[c]);
            mloc = fmaxf(mloc, __shfl_xor_sync(0xffffffffu, mloc, 1));
            mloc = fmaxf(mloc, __shfl_xor_sync(0xffffffffu, mloc, 2));
            float m_old = row_m[r];
            float m_new = fmaxf(m_old, mloc);
            float ls = 0.f;
#pragma unroll
            for (int c = 0; c < 16; c += 2) {
                float e0 = __expf(Pr[c]     - m_new);
                float e1 = __expf(Pr[c + 1] - m_new);
                ls += e0 + e1;
                __nv_bfloat16 h0 = __float2bfloat16_rn(e0);
                __nv_bfloat16 h1 = __float2bfloat16_rn(e1);
                uint32_t off = (uint32_t)(r * TSROW + (qd * 16 + c) * 2);
                *(__nv_bfloat162*)(Kh + off) = __nv_bfloat162(h0, h1);
                *(__nv_bfloat162*)(Kl + off) = __nv_bfloat162(
                    __float2bfloat16_rn(e0 - __bfloat162float(h0)),
                    __float2bfloat16_rn(e1 - __bfloat162float(h1)));
            }
            ls += __shfl_xor_sync(0xffffffffu, ls, 1);
            ls += __shfl_xor_sync(0xffffffffu, ls, 2);
            if (qd == 0) {
                float fac = __expf(m_old - m_new);
                row_s[r] = fac;
                row_m[r] = m_new;
                row_l[r] = row_l[r] * fac + ls;
            }
        }
        __syncthreads();

        // ---- rescale O; O += P @ V (bf16x3) ----
        {
            float f0 = row_s[mrow + (l >> 2)];
            float f1 = row_s[mrow + 8 + (l >> 2)];
#pragma unroll
            for (int nt = 0; nt < 4; nt++) {
                oacc[nt][0] *= f0; oacc[nt][1] *= f0;
                oacc[nt][2] *= f1; oacc[nt][3] *= f1;
            }
#pragma unroll
            for (int ks = 0; ks < 4; ks++) {
                const uint32_t kso = (uint32_t)(ks * 32);
                uint32_t ph4[4], pl4[4];
                LDSM4(ph4, sb + 2 * TPL + aRel + kso);
                LDSM4(pl4, sb + 3 * TPL + aRel + kso);
                uint32_t vh[4][2], vl[4][2];
#pragma unroll
                for (int jp = 0; jp < 2; jp++) {
                    uint32_t r4[4];
                    LDSM4(r4, sb + 4 * TPL + bRel + jp * (16 * TSROW) + kso);
                    vh[2 * jp][0] = r4[0]; vh[2 * jp][1] = r4[1];
                    vh[2 * jp + 1][0] = r4[2]; vh[2 * jp + 1][1] = r4[3];
                    LDSM4(r4, sb + 5 * TPL + bRel + jp * (16 * TSROW) + kso);
                    vl[2 * jp][0] = r4[0]; vl[2 * jp][1] = r4[1];
                    vl[2 * jp + 1][0] = r4[2]; vl[2 * jp + 1][1] = r4[3];
                }
#pragma unroll
                for (int nt = 0; nt < 4; nt++) mma_bf16(oacc[nt], ph4, vh[nt]);
#pragma unroll
                for (int nt = 0; nt < 4; nt++) mma_bf16(oacc[nt], ph4, vl[nt]);
#pragma unroll
                for (int nt = 0; nt < 4; nt++) mma_bf16(oacc[nt], pl4, vh[nt]);
            }
        }
    }

    // normalize + write single fp16 plane
    {
        float i0 = 1.f / row_l[mrow + (l >> 2)];
        float i1 = 1.f / row_l[mrow + 8 + (l >> 2)];
        size_t r0 = (size_t)(b * NS + q0 + mrow + (l >> 2)) * ND;
        size_t r1 = r0 + 8 * (size_t)ND;
#pragma unroll
        for (int nt = 0; nt < 4; nt++) {
            int col = hh * NHD + ncol + 8 * nt + 2 * (l & 3);
            *(__half2*)&ao[r0 + col] = __floats2half2_rn(oacc[nt][0] * i0, oacc[nt][1] * i0);
            *(__half2*)&ao[r1 + col] = __floats2half2_rn(oacc[nt][2] * i1, oacc[nt][3] * i1);
        }
    }
}

// ---------------------------------------------------------------------------
extern "C" void kernel_launch(void* const* d_in, const int* in_sizes, int n_in,
                              void* d_out, int out_size)
{
    const float* x     = (const float*)d_in[0];
    const float* Wqkv  = (const float*)d_in[1];
    const float* bqkv  = (const float*)d_in[2];
    const float* Wout  = (const float*)d_in[3];
    const float* bout  = (const float*)d_in[4];
    const int*   layer = (const int*)d_in[5];
    float* out = (float*)d_out;

    float *qkv;
    __half *x16, *a16, *wqh, *wql, *woh, *wol;
    __nv_bfloat16 *qh, *ql, *kh, *kl, *vth, *vtl;
    cudaGetSymbolAddress((void**)&qkv,  g_qkv);
    cudaGetSymbolAddress((void**)&x16, g_x16);
    cudaGetSymbolAddress((void**)&a16, g_a16);
    cudaGetSymbolAddress((void**)&wqh, g_wqh16);
    cudaGetSymbolAddress((void**)&wql, g_wql16);
    cudaGetSymbolAddress((void**)&woh, g_woh16);
    cudaGetSymbolAddress((void**)&wol, g_wol16);
    cudaGetSymbolAddress((void**)&qh, g_qh);
    cudaGetSymbolAddress((void**)&ql, g_ql);
    cudaGetSymbolAddress((void**)&kh, g_kh);
    cudaGetSymbolAddress((void**)&kl, g_kl);
    cudaGetSymbolAddress((void**)&vth, g_vth);
    cudaGetSymbolAddress((void**)&vtl, g_vtl);

    const int gemm_smem = NSTAGE * STG;   // 98304 B
    cudaFuncSetAttribute(gemm_mma_kernel, cudaFuncAttributeMaxDynamicSharedMemorySize, gemm_smem);
    const int attn_smem = 6 * TPL + 64 * 68 * 4 + 3 * 64 * 4;   // 73472 B
    cudaFuncSetAttribute(attn_mma_kernel, cudaFuncAttributeMaxDynamicSharedMemorySize, attn_smem);

    // 0) conversions
    conv_fp16_kernel<<<(NROWS * ND / 2 + 255) / 256, 256>>>(x, x16, NROWS * ND / 2);
    convT16_kernel<<<dim3(NQKV / 32, ND / 32), dim3(32, 8)>>>(Wqkv, wqh, wql, ND, NQKV);
    convT16_kernel<<<dim3(ND / 32, ND / 32), dim3(32, 8)>>>(Wout, woh, wol, ND, ND);

    // 1) qkv = x @ Wqkv + bqkv   (fp16 2-pass mma.sync, 4-stage cp.async)
    gemm_mma_kernel<<<dim3(NQKV / 128, NROWS / 128), 256, gemm_smem>>>(
        x16, wqh, wql, bqkv, qkv, NROWS, NQKV, ND);
    // 2) RoPE -> split bf16 Q/K planes; V -> transposed split planes
    rope_kernel<<<(NROWS * NH * 32) / 256, 256>>>(qkv, qh, ql, kh, kl, layer);
    conv_v_kernel<<<dim3(NS / 32, NB * NH * 2), dim3(32, 8)>>>(qkv, vth, vtl);
    // 3) tensor-core banded attention (writes fp16 plane)
    attn_mma_kernel<<<NB * NH * 32, 256, attn_smem>>>(qh, ql, kh, kl, vth, vtl, a16, layer);
    // 4) out = attn @ Wout + bout   (fp16 2-pass)
    gemm_mma_kernel<<<dim3(ND / 128, NROWS / 128), 256, gemm_smem>>>(
        a16, woh, wol, bout, out, NROWS, ND, ND);
}

// round 13
// speedup vs baseline: 2.3056x; 1.2710x over previous
#include <cuda_runtime.h>
#include <cuda_bf16.h>
#include <cuda_fp16.h>
#include <math.h>
#include <stdint.h>

#define NB 2
#define NS 2048
#define ND 768
#define NH 12
#define NHD 64
#define NQKV 2304
#define NROWS 4096   // NB*NS

#define NEG_BIG (-1e30f)

// ---------------- scratch (device globals; allocation-free) -----------------
__device__ float g_qkv[(size_t)NROWS * NQKV];                 // 37.7 MB
__device__ __half g_x16[(size_t)NROWS * ND];                  // x fp16 (A of GEMM1)
__device__ __half g_a16[(size_t)NROWS * ND];                  // attn out fp16 (A of GEMM2)
__device__ __half g_wq16[(size_t)NQKV * ND];                  // Wqkv^T fp16 [N][K]
__device__ __half g_wo16[(size_t)ND * ND];                    // Wout^T fp16 [N][K]
// attention operand planes (bf16 hi/lo; bf16x3 kept inside attention)
__device__ __nv_bfloat16 g_qh[(size_t)NROWS * ND];
__device__ __nv_bfloat16 g_ql[(size_t)NROWS * ND];
__device__ __nv_bfloat16 g_kh[(size_t)NROWS * ND];
__device__ __nv_bfloat16 g_kl[(size_t)NROWS * ND];
__device__ __nv_bfloat16 g_vth[(size_t)NROWS * ND];           // V^T [b][h][d][s]
__device__ __nv_bfloat16 g_vtl[(size_t)NROWS * ND];

__device__ __forceinline__ uint32_t smem_u32(const void* p) {
    uint32_t a;
    asm("{ .reg .u64 t; cvta.to.shared.u64 t, %1; cvt.u32.u64 %0, t; }" : "=r"(a) : "l"(p));
    return a;
}

__device__ __forceinline__ void mma_bf16(float c[4], const uint32_t a[4], const uint32_t b[2]) {
    asm volatile(
        "mma.sync.aligned.m16n8k16.row.col.f32.bf16.bf16.f32 "
        "{%0,%1,%2,%3}, {%4,%5,%6,%7}, {%8,%9}, {%0,%1,%2,%3};"
        : "+f"(c[0]), "+f"(c[1]), "+f"(c[2]), "+f"(c[3])
        : "r"(a[0]), "r"(a[1]), "r"(a[2]), "r"(a[3]), "r"(b[0]), "r"(b[1]));
}

__device__ __forceinline__ void mma_f16(float c[4], const uint32_t a[4], const uint32_t b[2]) {
    asm volatile(
        "mma.sync.aligned.m16n8k16.row.col.f32.f16.f16.f32 "
        "{%0,%1,%2,%3}, {%4,%5,%6,%7}, {%8,%9}, {%0,%1,%2,%3};"
        : "+f"(c[0]), "+f"(c[1]), "+f"(c[2]), "+f"(c[3])
        : "r"(a[0]), "r"(a[1]), "r"(a[2]), "r"(a[3]), "r"(b[0]), "r"(b[1]));
}

#define LDSM4(r, addr) \
    asm volatile("ldmatrix.sync.aligned.m8n8.x4.shared.b16 {%0,%1,%2,%3}, [%4];" \
                 : "=r"((r)[0]), "=r"((r)[1]), "=r"((r)[2]), "=r"((r)[3]) : "r"(addr))

#define CP16(dst, src) \
    asm volatile("cp.async.cg.shared.global [%0], [%1], 16;" :: "r"(dst), "l"(src))
#define CP_COMMIT() asm volatile("cp.async.commit_group;")
#define CP_WAIT4()  asm volatile("cp.async.wait_group 4;")
#define CP_WAIT3()  asm volatile("cp.async.wait_group 3;")
#define CP_WAIT2()  asm volatile("cp.async.wait_group 2;")
#define CP_WAIT1()  asm volatile("cp.async.wait_group 1;")
#define CP_WAIT0()  asm volatile("cp.async.wait_group 0;")

// ---------------------------------------------------------------------------
// fp32 -> fp16 (single plane).
// ---------------------------------------------------------------------------
__global__ void conv_fp16_kernel(const float* __restrict__ in,
                                 __half* __restrict__ o, int n2)
{
    int i = blockIdx.x * blockDim.x + threadIdx.x;
    if (i >= n2) return;
    float2 v = ((const float2*)in)[i];
    ((__half2*)o)[i] = __floats2half2_rn(v.x, v.y);
}

// ---------------------------------------------------------------------------
// Transpose-convert: W fp32 [K][N] -> fp16 [N][K] single plane.
// ---------------------------------------------------------------------------
__global__ void convW_kernel(const float* __restrict__ W,
                             __half* __restrict__ o, int K, int N)
{
    __shared__ float t[32][33];
    const int n0 = blockIdx.x * 32, k0 = blockIdx.y * 32;
#pragma unroll
    for (int i = 0; i < 4; i++) {
        int k = threadIdx.y + i * 8;
        t[k][threadIdx.x] = W[(size_t)(k0 + k) * N + n0 + threadIdx.x];
    }
    __syncthreads();
#pragma unroll
    for (int i = 0; i < 4; i++) {
        int n = threadIdx.y + i * 8;
        o[(size_t)(n0 + n) * K + k0 + threadIdx.x] = __float2half_rn(t[threadIdx.x][n]);
    }
}

// ---------------------------------------------------------------------------
// Single-pass fp16 GEMM + bias: C = A @ B^T + bias  (fp32 accum/output)
// A: [M][K] fp16; B: [N][K] fp16 (pre-transposed weights).
// Block 128x128, BK=32, 8 warps, warp tile 64x32.
// 6-stage cp.async pipeline, 16 KB/stage (96 KB) -> 2 CTAs/SM.
// ---------------------------------------------------------------------------
#define PL 8192
#define STG (2 * PL)       // 16384 B per stage (A, B)
#define NSTAGE 6

__global__ __launch_bounds__(256, 2)
void gemm_mma_kernel(const __half* __restrict__ A, const __half* __restrict__ B,
                     const float* __restrict__ bias, float* __restrict__ C,
                     int M, int N, int K)
{
    extern __shared__ __align__(16) char sm[];

    const int tid = threadIdx.x;
    const int w   = tid >> 5;
    const int l   = tid & 31;
    const int row0 = blockIdx.y * 128;
    const int col0 = blockIdx.x * 128;
    const int m0w = (w >> 2) * 64;
    const int n0w = (w & 3) * 32;

    float acc[4][4][4];
#pragma unroll
    for (int i = 0; i < 4; i++)
#pragma unroll
        for (int j = 0; j < 4; j++)
#pragma unroll
            for (int q = 0; q < 4; q++) acc[i][j][q] = 0.f;

    const uint32_t sb = smem_u32(sm);

    const int rA   = m0w + (l & 15);
    const uint32_t selA = (uint32_t)((rA >> 1) & 3);
    const uint32_t c0A  = (uint32_t)(l >> 4);
    const uint32_t aRel0 = (uint32_t)rA * 64 + ((c0A ^ selA) << 4);
    const uint32_t aRel1 = (uint32_t)rA * 64 + (((c0A + 2) ^ selA) << 4);
    const int bg = l >> 3;
    const int rB = n0w + (bg >> 1) * 8 + (l & 7);
    const uint32_t selB = (uint32_t)((rB >> 1) & 3);
    const uint32_t c0B  = (uint32_t)(bg & 1);
    const uint32_t bRel0 = PL + (uint32_t)rB * 64 + ((c0B ^ selB) << 4);
    const uint32_t bRel1 = PL + (uint32_t)rB * 64 + (((c0B + 2) ^ selB) << 4);

    const int fr = tid >> 1;
    const int fc = (tid & 1) * 2;
    const uint32_t fsel = (uint32_t)((fr >> 1) & 3);
    const uint32_t d0 = (uint32_t)fr * 64 + (((uint32_t)fc ^ fsel) << 4);
    const uint32_t d1 = (uint32_t)fr * 64 + ((((uint32_t)fc + 1) ^ fsel) << 4);
    const __half* gA = A + (size_t)(row0 + fr) * K + fc * 8;
    const __half* gB = B + (size_t)(col0 + fr) * K + fc * 8;

    const int nch = K >> 5;

    auto issue = [&](int kc, int s) {
        const int ke = kc << 5;
        const uint32_t st = sb + (uint32_t)s * STG;
        CP16(st + d0,      gA + ke);
        CP16(st + d1,      gA + ke + 8);
        CP16(st + PL + d0, gB + ke);
        CP16(st + PL + d1, gB + ke + 8);
        CP_COMMIT();
    };

    // prefetch up to 5 stages
#pragma unroll
    for (int p = 0; p < 5; p++)
        if (p < nch) issue(p, p);

    int s = 0;
    for (int kc = 0; kc < nch; kc++) {
        // ensure stage kc complete: allow pending = groups issued after kc
        int after = nch - 1 - kc;
        if (after > 4) after = 4;
        switch (after) {
            case 4: CP_WAIT4(); break;
            case 3: CP_WAIT3(); break;
            case 2: CP_WAIT2(); break;
            case 1: CP_WAIT1(); break;
            default: CP_WAIT0(); break;
        }
        __syncthreads();
        if (kc + 5 < nch) {
            int s5 = s + 5; if (s5 >= NSTAGE) s5 -= NSTAGE;
            issue(kc + 5, s5);
        }

        const uint32_t stb = sb + (uint32_t)s * STG;
#pragma unroll
        for (int ks = 0; ks < 2; ks++) {
            const uint32_t aR = ks ? aRel1 : aRel0;
            const uint32_t bR = ks ? bRel1 : bRel0;
            uint32_t a4[4][4];
#pragma unroll
            for (int mt = 0; mt < 4; mt++)
                LDSM4(a4[mt], stb + aR + mt * 1024);
            uint32_t b4[4][2];
#pragma unroll
            for (int jp = 0; jp < 2; jp++) {
                uint32_t r[4];
                LDSM4(r, stb + bR + jp * 1024);
                b4[2 * jp][0] = r[0]; b4[2 * jp][1] = r[1];
                b4[2 * jp + 1][0] = r[2]; b4[2 * jp + 1][1] = r[3];
            }
#pragma unroll
            for (int mt = 0; mt < 4; mt++)
#pragma unroll
                for (int nt = 0; nt < 4; nt++)
                    mma_f16(acc[mt][nt], a4[mt], b4[nt]);
        }
        if (++s >= NSTAGE) s = 0;
    }

    float2 bb[4];
#pragma unroll
    for (int nt = 0; nt < 4; nt++) {
        int cg = col0 + n0w + 8 * nt + 2 * (l & 3);
        bb[nt] = make_float2(bias[cg], bias[cg + 1]);
    }
#pragma unroll
    for (int mt = 0; mt < 4; mt++) {
        int rg = row0 + m0w + 16 * mt + (l >> 2);
#pragma unroll
        for (int nt = 0; nt < 4; nt++) {
            int cg = col0 + n0w + 8 * nt + 2 * (l & 3);
            *(float2*)&C[(size_t)rg * N + cg] =
                make_float2(acc[mt][nt][0] + bb[nt].x, acc[mt][nt][1] + bb[nt].y);
            *(float2*)&C[(size_t)(rg + 8) * N + cg] =
                make_float2(acc[mt][nt][2] + bb[nt].x, acc[mt][nt][3] + bb[nt].y);
        }
    }
}

// ---------------------------------------------------------------------------
// RoPE: read fp32 q,k from qkv; write rotated, split bf16 planes directly.
// ---------------------------------------------------------------------------
__global__ void rope_kernel(const float* __restrict__ qkv,
                            __nv_bfloat16* __restrict__ qh, __nv_bfloat16* __restrict__ ql,
                            __nv_bfloat16* __restrict__ kh, __nv_bfloat16* __restrict__ kl,
                            const int* __restrict__ layer_p)
{
    int idx = blockIdx.x * blockDim.x + threadIdx.x;
    if (idx >= NROWS * NH * 32) return;
    int i  = idx & 31;
    int hh = (idx >> 5) % NH;
    int bs = (idx >> 5) / NH;
    int s  = bs & (NS - 1);

    bool is_global = (layer_p[0] % 3) == 0;
    float theta = is_global ? 160000.f : 10000.f;
    float freq  = powf(theta, -(float)(2 * i) / 64.f);
    float ang   = (float)s * freq;
    float sn, cs;
    sincosf(ang, &sn, &cs);

    size_t base = (size_t)bs * NQKV + hh * NHD + 2 * i;
    float qe = qkv[base], qo = qkv[base + 1];
    float q0 = (qe * cs - qo * sn) * 0.125f;
    float q1 = (qo * cs + qe * sn) * 0.125f;
    float ke = qkv[base + ND], ko = qkv[base + ND + 1];
    float k0 = ke * cs - ko * sn;
    float k1 = ko * cs + ke * sn;

    size_t o = (size_t)bs * ND + hh * NHD + 2 * i;
    __nv_bfloat16 h0 = __float2bfloat16_rn(q0), h1 = __float2bfloat16_rn(q1);
    *(__nv_bfloat162*)&qh[o] = __nv_bfloat162(h0, h1);
    *(__nv_bfloat162*)&ql[o] = __nv_bfloat162(
        __float2bfloat16_rn(q0 - __bfloat162float(h0)),
        __float2bfloat16_rn(q1 - __bfloat162float(h1)));
    h0 = __float2bfloat16_rn(k0); h1 = __float2bfloat16_rn(k1);
    *(__nv_bfloat162*)&kh[o] = __nv_bfloat162(h0, h1);
    *(__nv_bfloat162*)&kl[o] = __nv_bfloat162(
        __float2bfloat16_rn(k0 - __bfloat162float(h0)),
        __float2bfloat16_rn(k1 - __bfloat162float(h1)));
}

// ---------------------------------------------------------------------------
// conv_v: V fp32 [b*NS+s][h*64+d] -> transposed split bf16 planes [b][h][d][s].
// ---------------------------------------------------------------------------
__global__ void conv_v_kernel(const float* __restrict__ qkv,
                              __nv_bfloat16* __restrict__ vth,
                              __nv_bfloat16* __restrict__ vtl)
{
    __shared__ float t[32][33];
    const int s0 = blockIdx.x * 32;
    const int gy = blockIdx.y;
    const int d0 = (gy & 1) * 32;
    const int bh = gy >> 1;
    const int hh = bh % NH;
    const int b  = bh / NH;
#pragma unroll
    for (int i = 0; i < 4; i++) {
        int s = threadIdx.y + i * 8;
        t[s][threadIdx.x] = qkv[(size_t)(b * NS + s0 + s) * NQKV + 2 * ND + hh * NHD + d0 + threadIdx.x];
    }
    __syncthreads();
#pragma unroll
    for (int i = 0; i < 4; i++) {
        int d = threadIdx.y + i * 8;
        float x = t[threadIdx.x][d];
        __nv_bfloat16 h = __float2bfloat16_rn(x);
        __nv_bfloat16 l = __float2bfloat16_rn(x - __bfloat162float(h));
        size_t o = ((size_t)(b * NH + hh) * NHD + d0 + d) * NS + s0 + threadIdx.x;
        vth[o] = h;
        vtl[o] = l;
    }
}

// ---------------------------------------------------------------------------
// Tensor-core flash attention on pre-split bf16 planes (bf16x3 inside).
// Epilogue writes single fp16 plane (A operand of the fp16 out-projection).
// ---------------------------------------------------------------------------
#define TSROW 144
#define TPL (64 * TSROW)   // 9216 B per plane

__global__ __launch_bounds__(256)
void attn_mma_kernel(const __nv_bfloat16* __restrict__ qh_g, const __nv_bfloat16* __restrict__ ql_g,
                     const __nv_bfloat16* __restrict__ kh_g, const __nv_bfloat16* __restrict__ kl_g,
                     const __nv_bfloat16* __restrict__ vth_g, const __nv_bfloat16* __restrict__ vtl_g,
                     __half* __restrict__ ao,
                     const int* __restrict__ layer_p)
{
    extern __shared__ __align__(16) char sm[];
    // planes: 0 Qh, 1 Ql, 2 Kh/Ph, 3 Kl/Pl, 4 Vth, 5 Vtl
    char* Kh = sm + 2 * TPL;
    char* Kl = sm + 3 * TPL;
    float* Sbuf  = (float*)(sm + 6 * TPL);   // [64][68]
    float* row_m = Sbuf + 64 * 68;
    float* row_l = row_m + 64;
    float* row_s = row_l + 64;

    const int tid = threadIdx.x;
    const int w   = tid >> 5;
    const int l   = tid & 31;
    const int blk = blockIdx.x;
    const int qt  = blk & 31;
    const int hh  = (blk >> 5) % NH;
    const int b   = blk / (32 * NH);
    const bool is_global = (layer_p[0] % 3) == 0;
    const int q0 = qt * 64;

    const int mrow = (w & 3) * 16;
    const int ncol = (w >> 2) * 32;
    const uint32_t sb = smem_u32(sm);
    const uint32_t aRel = (uint32_t)(mrow + (l & 15)) * TSROW + (uint32_t)((l >> 4) * 16);
    const int bg = l >> 3;
    const uint32_t bRel = (uint32_t)(ncol + (bg >> 1) * 8 + (l & 7)) * TSROW
                        + (uint32_t)((bg & 1) * 16);

    const int fr  = tid >> 2;
    const int fs  = (tid & 3) * 2;
    const uint32_t fRel = (uint32_t)fr * TSROW + (uint32_t)fs * 16;

    // Q planes (load once)
    {
        const __nv_bfloat16* gq  = qh_g + (size_t)(b * NS + q0 + fr) * ND + hh * NHD + fs * 8;
        const __nv_bfloat16* gql = ql_g + (size_t)(b * NS + q0 + fr) * ND + hh * NHD + fs * 8;
        CP16(sb + fRel,            gq);
        CP16(sb + fRel + 16,       gq + 8);
        CP16(sb + TPL + fRel,      gql);
        CP16(sb + TPL + fRel + 16, gql + 8);
        CP_COMMIT();
    }
    if (tid < 64) { row_m[tid] = NEG_BIG; row_l[tid] = 0.f; }

    float oacc[4][4];
#pragma unroll
    for (int i = 0; i < 4; i++)
#pragma unroll
        for (int j = 0; j < 4; j++) oacc[i][j] = 0.f;

    const int kt0 = is_global ? 0 : max(0, qt - 2);
    const int kt1 = is_global ? 31 : min(31, qt + 2);

    for (int kt = kt0; kt <= kt1; kt++) {
        __syncthreads();
        {
            const __nv_bfloat16* gkh = kh_g + (size_t)(b * NS + kt * 64 + fr) * ND + hh * NHD + fs * 8;
            const __nv_bfloat16* gkl = kl_g + (size_t)(b * NS + kt * 64 + fr) * ND + hh * NHD + fs * 8;
            const __nv_bfloat16* gvh = vth_g + ((size_t)(b * NH + hh) * NHD + fr) * NS + kt * 64 + fs * 8;
            const __nv_bfloat16* gvl = vtl_g + ((size_t)(b * NH + hh) * NHD + fr) * NS + kt * 64 + fs * 8;
            CP16(sb + 2 * TPL + fRel,      gkh);
            CP16(sb + 2 * TPL + fRel + 16, gkh + 8);
            CP16(sb + 3 * TPL + fRel,      gkl);
            CP16(sb + 3 * TPL + fRel + 16, gkl + 8);
            CP16(sb + 4 * TPL + fRel,      gvh);
            CP16(sb + 4 * TPL + fRel + 16, gvh + 8);
            CP16(sb + 5 * TPL + fRel,      gvl);
            CP16(sb + 5 * TPL + fRel + 16, gvl + 8);
            CP_COMMIT();
            CP_WAIT0();
        }
        __syncthreads();

        // ---- S = Q K^T (bf16x3) ----
        float sa[4][4];
#pragma unroll
        for (int i = 0; i < 4; i++)
#pragma unroll
            for (int j = 0; j < 4; j++) sa[i][j] = 0.f;
#pragma unroll
        for (int ks = 0; ks < 4; ks++) {
            const uint32_t kso = (uint32_t)(ks * 32);
            uint32_t qh4[4], ql4[4];
            LDSM4(qh4, sb + aRel + kso);
            LDSM4(ql4, sb + TPL + aRel + kso);
            uint32_t bh[4][2], bl[4][2];
#pragma unroll
            for (int jp = 0; jp < 2; jp++) {
                uint32_t r4[4];
                LDSM4(r4, sb + 2 * TPL + bRel + jp * (16 * TSROW) + kso);
                bh[2 * jp][0] = r4[0]; bh[2 * jp][1] = r4[1];
                bh[2 * jp + 1][0] = r4[2]; bh[2 * jp + 1][1] = r4[3];
                LDSM4(r4, sb + 3 * TPL + bRel + jp * (16 * TSROW) + kso);
                bl[2 * jp][0] = r4[0]; bl[2 * jp][1] = r4[1];
                bl[2 * jp + 1][0] = r4[2]; bl[2 * jp + 1][1] = r4[3];
            }
#pragma unroll
            for (int nt = 0; nt < 4; nt++) mma_bf16(sa[nt], qh4, bh[nt]);
#pragma unroll
            for (int nt = 0; nt < 4; nt++) mma_bf16(sa[nt], qh4, bl[nt]);
#pragma unroll
            for (int nt = 0; nt < 4; nt++) mma_bf16(sa[nt], ql4, bh[nt]);
        }
        {
            int fr0 = mrow + (l >> 2);
#pragma unroll
            for (int nt = 0; nt < 4; nt++) {
                int col = ncol + 8 * nt + 2 * (l & 3);
                *(float2*)&Sbuf[fr0 * 68 + col]       = make_float2(sa[nt][0], sa[nt][1]);
                *(float2*)&Sbuf[(fr0 + 8) * 68 + col] = make_float2(sa[nt][2], sa[nt][3]);
            }
        }
        __syncthreads();

        // ---- banded mask + online softmax; emit Ph/Pl (reuse K planes) ----
        {
            int r  = tid >> 2;
            int qd = tid & 3;
            float* Pr = &Sbuf[r * 68 + qd * 16];
            if (!is_global) {
#pragma unroll
                for (int c = 0; c < 16; c++) {
                    int dlt = (q0 + r) - (kt * 64 + qd * 16 + c);
                    if (dlt < 0) dlt = -dlt;
                    if (dlt > 128) Pr[c] = NEG_BIG;
                }
            }
            float mloc = NEG_BIG;
#pragma unroll
            for (int c = 0; c < 16; c++) mloc = fmaxf(mloc, Pr[c]);
            mloc = fmaxf(mloc, __shfl_xor_sync(0xffffffffu, mloc, 1));
            mloc = fmaxf(mloc, __shfl_xor_sync(0xffffffffu, mloc, 2));
            float m_old = row_m[r];
            float m_new = fmaxf(m_old, mloc);
            float ls = 0.f;
#pragma unroll
            for (int c = 0; c < 16; c += 2) {
                float e0 = __expf(Pr[c]     - m_new);
                float e1 = __expf(Pr[c + 1] - m_new);
                ls += e0 + e1;
                __nv_bfloat16 h0 = __float2bfloat16_rn(e0);
                __nv_bfloat16 h1 = __float2bfloat16_rn(e1);
                uint32_t off = (uint32_t)(r * TSROW + (qd * 16 + c) * 2);
                *(__nv_bfloat162*)(Kh + off) = __nv_bfloat162(h0, h1);
                *(__nv_bfloat162*)(Kl + off) = __nv_bfloat162(
                    __float2bfloat16_rn(e0 - __bfloat162float(h0)),
                    __float2bfloat16_rn(e1 - __bfloat162float(h1)));
            }
            ls += __shfl_xor_sync(0xffffffffu, ls, 1);
            ls += __shfl_xor_sync(0xffffffffu, ls, 2);
            if (qd == 0) {
                float fac = __expf(m_old - m_new);
                row_s[r] = fac;
                row_m[r] = m_new;
                row_l[r] = row_l[r] * fac + ls;
            }
        }
        __syncthreads();

        // ---- rescale O; O += P @ V (bf16x3) ----
        {
            float f0 = row_s[mrow + (l >> 2)];
            float f1 = row_s[mrow + 8 + (l >> 2)];
#pragma unroll
            for (int nt = 0; nt < 4; nt++) {
                oacc[nt][0] *= f0; oacc[nt][1] *= f0;
                oacc[nt][2] *= f1; oacc[nt][3] *= f1;
            }
#pragma unroll
            for (int ks = 0; ks < 4; ks++) {
                const uint32_t kso = (uint32_t)(ks * 32);
                uint32_t ph4[4], pl4[4];
                LDSM4(ph4, sb + 2 * TPL + aRel + kso);
                LDSM4(pl4, sb + 3 * TPL + aRel + kso);
                uint32_t vh[4][2], vl[4][2];
#pragma unroll
                for (int jp = 0; jp < 2; jp++) {
                    uint32_t r4[4];
                    LDSM4(r4, sb + 4 * TPL + bRel + jp * (16 * TSROW) + kso);
                    vh[2 * jp][0] = r4[0]; vh[2 * jp][1] = r4[1];
                    vh[2 * jp + 1][0] = r4[2]; vh[2 * jp + 1][1] = r4[3];
                    LDSM4(r4, sb + 5 * TPL + bRel + jp * (16 * TSROW) + kso);
                    vl[2 * jp][0] = r4[0]; vl[2 * jp][1] = r4[1];
                    vl[2 * jp + 1][0] = r4[2]; vl[2 * jp + 1][1] = r4[3];
                }
#pragma unroll
                for (int nt = 0; nt < 4; nt++) mma_bf16(oacc[nt], ph4, vh[nt]);
#pragma unroll
                for (int nt = 0; nt < 4; nt++) mma_bf16(oacc[nt], ph4, vl[nt]);
#pragma unroll
                for (int nt = 0; nt < 4; nt++) mma_bf16(oacc[nt], pl4, vh[nt]);
            }
        }
    }

    // normalize + write single fp16 plane
    {
        float i0 = 1.f / row_l[mrow + (l >> 2)];
        float i1 = 1.f / row_l[mrow + 8 + (l >> 2)];
        size_t r0 = (size_t)(b * NS + q0 + mrow + (l >> 2)) * ND;
        size_t r1 = r0 + 8 * (size_t)ND;
#pragma unroll
        for (int nt = 0; nt < 4; nt++) {
            int col = hh * NHD + ncol + 8 * nt + 2 * (l & 3);
            *(__half2*)&ao[r0 + col] = __floats2half2_rn(oacc[nt][0] * i0, oacc[nt][1] * i0);
            *(__half2*)&ao[r1 + col] = __floats2half2_rn(oacc[nt][2] * i1, oacc[nt][3] * i1);
        }
    }
}

// ---------------------------------------------------------------------------
extern "C" void kernel_launch(void* const* d_in, const int* in_sizes, int n_in,
                              void* d_out, int out_size)
{
    const float* x     = (const float*)d_in[0];
    const float* Wqkv  = (const float*)d_in[1];
    const float* bqkv  = (const float*)d_in[2];
    const float* Wout  = (const float*)d_in[3];
    const float* bout  = (const float*)d_in[4];
    const int*   layer = (const int*)d_in[5];
    float* out = (float*)d_out;

    float *qkv;
    __half *x16, *a16, *wq, *wo;
    __nv_bfloat16 *qh, *ql, *kh, *kl, *vth, *vtl;
    cudaGetSymbolAddress((void**)&qkv,  g_qkv);
    cudaGetSymbolAddress((void**)&x16, g_x16);
    cudaGetSymbolAddress((void**)&a16, g_a16);
    cudaGetSymbolAddress((void**)&wq, g_wq16);
    cudaGetSymbolAddress((void**)&wo, g_wo16);
    cudaGetSymbolAddress((void**)&qh, g_qh);
    cudaGetSymbolAddress((void**)&ql, g_ql);
    cudaGetSymbolAddress((void**)&kh, g_kh);
    cudaGetSymbolAddress((void**)&kl, g_kl);
    cudaGetSymbolAddress((void**)&vth, g_vth);
    cudaGetSymbolAddress((void**)&vtl, g_vtl);

    const int gemm_smem = NSTAGE * STG;   // 98304 B
    cudaFuncSetAttribute(gemm_mma_kernel, cudaFuncAttributeMaxDynamicSharedMemorySize, gemm_smem);
    const int attn_smem = 6 * TPL + 64 * 68 * 4 + 3 * 64 * 4;   // 73472 B
    cudaFuncSetAttribute(attn_mma_kernel, cudaFuncAttributeMaxDynamicSharedMemorySize, attn_smem);

    // 0) conversions
    conv_fp16_kernel<<<(NROWS * ND / 2 + 255) / 256, 256>>>(x, x16, NROWS * ND / 2);
    convW_kernel<<<dim3(NQKV / 32, ND / 32), dim3(32, 8)>>>(Wqkv, wq, ND, NQKV);
    convW_kernel<<<dim3(ND / 32, ND / 32), dim3(32, 8)>>>(Wout, wo, ND, ND);

    // 1) qkv = x @ Wqkv + bqkv   (single-pass fp16 mma.sync, 6-stage cp.async)
    gemm_mma_kernel<<<dim3(NQKV / 128, NROWS / 128), 256, gemm_smem>>>(
        x16, wq, bqkv, qkv, NROWS, NQKV, ND);
    // 2) RoPE -> split bf16 Q/K planes; V -> transposed split planes
    rope_kernel<<<(NROWS * NH * 32) / 256, 256>>>(qkv, qh, ql, kh, kl, layer);
    conv_v_kernel<<<dim3(NS / 32, NB * NH * 2), dim3(32, 8)>>>(qkv, vth, vtl);
    // 3) tensor-core banded attention (bf16x3; writes fp16 plane)
    attn_mma_kernel<<<NB * NH * 32, 256, attn_smem>>>(qh, ql, kh, kl, vth, vtl, a16, layer);
    // 4) out = attn @ Wout + bout   (single-pass fp16)
    gemm_mma_kernel<<<dim3(ND / 128, NROWS / 128), 256, gemm_smem>>>(
        a16, wo, bout, out, NROWS, ND, ND);
}

// round 14
// speedup vs baseline: 2.4069x; 1.0439x over previous
#include <cuda_runtime.h>
#include <cuda_fp16.h>
#include <math.h>
#include <stdint.h>

#define NB 2
#define NS 2048
#define ND 768
#define NH 12
#define NHD 64
#define NQKV 2304
#define NROWS 4096   // NB*NS

#define NEG_BIG (-1e30f)

// ---------------- scratch (device globals; allocation-free) -----------------
__device__ float g_qkv[(size_t)NROWS * NQKV];                 // V region used only
__device__ __half g_x16[(size_t)NROWS * ND];                  // x fp16 (A of GEMM1)
__device__ __half g_a16[(size_t)NROWS * ND];                  // attn out fp16 (A of GEMM2)
__device__ __half g_wq16[(size_t)NQKV * ND];                  // Wqkv^T fp16 [N][K]
__device__ __half g_wo16[(size_t)ND * ND];                    // Wout^T fp16 [N][K]
__device__ float2 g_rot[NS * 32];                             // cos/sin table
// attention operand planes (fp16)
__device__ __half g_qp[(size_t)NROWS * ND];                   // rotated, scaled Q (single)
__device__ __half g_kh16[(size_t)NROWS * ND];                 // rotated K hi
__device__ __half g_kl16[(size_t)NROWS * ND];                 // rotated K lo
__device__ __half g_vth16[(size_t)NROWS * ND];                // V^T hi [b][h][d][s]
__device__ __half g_vtl16[(size_t)NROWS * ND];                // V^T lo

__device__ __forceinline__ uint32_t smem_u32(const void* p) {
    uint32_t a;
    asm("{ .reg .u64 t; cvta.to.shared.u64 t, %1; cvt.u32.u64 %0, t; }" : "=r"(a) : "l"(p));
    return a;
}

__device__ __forceinline__ void mma_f16(float c[4], const uint32_t a[4], const uint32_t b[2]) {
    asm volatile(
        "mma.sync.aligned.m16n8k16.row.col.f32.f16.f16.f32 "
        "{%0,%1,%2,%3}, {%4,%5,%6,%7}, {%8,%9}, {%0,%1,%2,%3};"
        : "+f"(c[0]), "+f"(c[1]), "+f"(c[2]), "+f"(c[3])
        : "r"(a[0]), "r"(a[1]), "r"(a[2]), "r"(a[3]), "r"(b[0]), "r"(b[1]));
}

#define LDSM4(r, addr) \
    asm volatile("ldmatrix.sync.aligned.m8n8.x4.shared.b16 {%0,%1,%2,%3}, [%4];" \
                 : "=r"((r)[0]), "=r"((r)[1]), "=r"((r)[2]), "=r"((r)[3]) : "r"(addr))

#define CP16(dst, src) \
    asm volatile("cp.async.cg.shared.global [%0], [%1], 16;" :: "r"(dst), "l"(src))
#define CP_COMMIT() asm volatile("cp.async.commit_group;")
#define CP_WAIT4()  asm volatile("cp.async.wait_group 4;")
#define CP_WAIT3()  asm volatile("cp.async.wait_group 3;")
#define CP_WAIT2()  asm volatile("cp.async.wait_group 2;")
#define CP_WAIT1()  asm volatile("cp.async.wait_group 1;")
#define CP_WAIT0()  asm volatile("cp.async.wait_group 0;")

// ---------------------------------------------------------------------------
// fp32 -> fp16 (single plane).
// ---------------------------------------------------------------------------
__global__ void conv_fp16_kernel(const float* __restrict__ in,
                                 __half* __restrict__ o, int n2)
{
    int i = blockIdx.x * blockDim.x + threadIdx.x;
    if (i >= n2) return;
    float2 v = ((const float2*)in)[i];
    ((__half2*)o)[i] = __floats2half2_rn(v.x, v.y);
}

// ---------------------------------------------------------------------------
// Transpose-convert: W fp32 [K][N] -> fp16 [N][K] single plane.
// ---------------------------------------------------------------------------
__global__ void convW_kernel(const float* __restrict__ W,
                             __half* __restrict__ o, int K, int N)
{
    __shared__ float t[32][33];
    const int n0 = blockIdx.x * 32, k0 = blockIdx.y * 32;
#pragma unroll
    for (int i = 0; i < 4; i++) {
        int k = threadIdx.y + i * 8;
        t[k][threadIdx.x] = W[(size_t)(k0 + k) * N + n0 + threadIdx.x];
    }
    __syncthreads();
#pragma unroll
    for (int i = 0; i < 4; i++) {
        int n = threadIdx.y + i * 8;
        o[(size_t)(n0 + n) * K + k0 + threadIdx.x] = __float2half_rn(t[threadIdx.x][n]);
    }
}

// ---------------------------------------------------------------------------
// RoPE cos/sin table: rot[s*32+i] = (cos(s*f_i), sin(s*f_i)).
// ---------------------------------------------------------------------------
__global__ void rot_kernel(const int* __restrict__ layer_p, float2* __restrict__ rot)
{
    int idx = blockIdx.x * blockDim.x + threadIdx.x;
    if (idx >= NS * 32) return;
    int i = idx & 31;
    int s = idx >> 5;
    bool is_global = (layer_p[0] % 3) == 0;
    float theta = is_global ? 160000.f : 10000.f;
    float freq  = powf(theta, -(float)(2 * i) / 64.f);
    float sn, cs;
    sincosf((float)s * freq, &sn, &cs);
    rot[idx] = make_float2(cs, sn);
}

// ---------------------------------------------------------------------------
// Shared GEMM mainloop config: 128x128, BK=32, 6-stage cp.async, 2 CTAs/SM.
// ---------------------------------------------------------------------------
#define PL 8192
#define STG (2 * PL)
#define NSTAGE 6

#define GEMM_MAINLOOP_BODY                                                     \
    float acc[4][4][4];                                                        \
    _Pragma("unroll")                                                          \
    for (int i = 0; i < 4; i++)                                                \
        _Pragma("unroll")                                                      \
        for (int j = 0; j < 4; j++)                                            \
            _Pragma("unroll")                                                  \
            for (int q = 0; q < 4; q++) acc[i][j][q] = 0.f;                    \
    const uint32_t sb = smem_u32(sm);                                          \
    const int rA   = m0w + (l & 15);                                           \
    const uint32_t selA = (uint32_t)((rA >> 1) & 3);                           \
    const uint32_t c0A  = (uint32_t)(l >> 4);                                  \
    const uint32_t aRel0 = (uint32_t)rA * 64 + ((c0A ^ selA) << 4);            \
    const uint32_t aRel1 = (uint32_t)rA * 64 + (((c0A + 2) ^ selA) << 4);      \
    const int bg = l >> 3;                                                     \
    const int rB = n0w + (bg >> 1) * 8 + (l & 7);                              \
    const uint32_t selB = (uint32_t)((rB >> 1) & 3);                           \
    const uint32_t c0B  = (uint32_t)(bg & 1);                                  \
    const uint32_t bRel0 = PL + (uint32_t)rB * 64 + ((c0B ^ selB) << 4);       \
    const uint32_t bRel1 = PL + (uint32_t)rB * 64 + (((c0B + 2) ^ selB) << 4); \
    const int fr = tid >> 1;                                                   \
    const int fc = (tid & 1) * 2;                                              \
    const uint32_t fsel = (uint32_t)((fr >> 1) & 3);                           \
    const uint32_t d0 = (uint32_t)fr * 64 + (((uint32_t)fc ^ fsel) << 4);      \
    const uint32_t d1 = (uint32_t)fr * 64 + ((((uint32_t)fc + 1) ^ fsel) << 4);\
    const __half* gA = A + (size_t)(row0 + fr) * K + fc * 8;                   \
    const __half* gB = B + (size_t)(col0 + fr) * K + fc * 8;                   \
    const int nch = K >> 5;                                                    \
    auto issue = [&](int kc, int s) {                                          \
        const int ke = kc << 5;                                                \
        const uint32_t st = sb + (uint32_t)s * STG;                            \
        CP16(st + d0,      gA + ke);                                           \
        CP16(st + d1,      gA + ke + 8);                                       \
        CP16(st + PL + d0, gB + ke);                                           \
        CP16(st + PL + d1, gB + ke + 8);                                       \
        CP_COMMIT();                                                           \
    };                                                                         \
    _Pragma("unroll")                                                          \
    for (int p = 0; p < 5; p++)                                                \
        if (p < nch) issue(p, p);                                              \
    int s = 0;                                                                 \
    for (int kc = 0; kc < nch; kc++) {                                         \
        int after = nch - 1 - kc;                                              \
        if (after > 4) after = 4;                                              \
        switch (after) {                                                       \
            case 4: CP_WAIT4(); break;                                         \
            case 3: CP_WAIT3(); break;                                         \
            case 2: CP_WAIT2(); break;                                         \
            case 1: CP_WAIT1(); break;                                         \
            default: CP_WAIT0(); break;                                        \
        }                                                                      \
        __syncthreads();                                                       \
        if (kc + 5 < nch) {                                                    \
            int s5 = s + 5; if (s5 >= NSTAGE) s5 -= NSTAGE;                    \
            issue(kc + 5, s5);                                                 \
        }                                                                      \
        const uint32_t stb = sb + (uint32_t)s * STG;                           \
        _Pragma("unroll")                                                      \
        for (int ks = 0; ks < 2; ks++) {                                       \
            const uint32_t aR = ks ? aRel1 : aRel0;                            \
            const uint32_t bR = ks ? bRel1 : bRel0;                            \
            uint32_t a4[4][4];                                                 \
            _Pragma("unroll")                                                  \
            for (int mt = 0; mt < 4; mt++)                                     \
                LDSM4(a4[mt], stb + aR + mt * 1024);                           \
            uint32_t b4[4][2];                                                 \
            _Pragma("unroll")                                                  \
            for (int jp = 0; jp < 2; jp++) {                                   \
                uint32_t r[4];                                                 \
                LDSM4(r, stb + bR + jp * 1024);                                \
                b4[2 * jp][0] = r[0]; b4[2 * jp][1] = r[1];                    \
                b4[2 * jp + 1][0] = r[2]; b4[2 * jp + 1][1] = r[3];            \
            }                                                                  \
            _Pragma("unroll")                                                  \
            for (int mt = 0; mt < 4; mt++)                                     \
                _Pragma("unroll")                                              \
                for (int nt = 0; nt < 4; nt++)                                 \
                    mma_f16(acc[mt][nt], a4[mt], b4[nt]);                      \
        }                                                                      \
        if (++s >= NSTAGE) s = 0;                                              \
    }

// ---------------------------------------------------------------------------
// Generic fp16 GEMM + bias -> fp32 C (used for out-projection).
// ---------------------------------------------------------------------------
__global__ __launch_bounds__(256, 2)
void gemm_mma_kernel(const __half* __restrict__ A, const __half* __restrict__ B,
                     const float* __restrict__ bias, float* __restrict__ C,
                     int M, int N, int K)
{
    extern __shared__ __align__(16) char sm[];
    const int tid = threadIdx.x;
    const int w   = tid >> 5;
    const int l   = tid & 31;
    const int row0 = blockIdx.y * 128;
    const int col0 = blockIdx.x * 128;
    const int m0w = (w >> 2) * 64;
    const int n0w = (w & 3) * 32;

    GEMM_MAINLOOP_BODY

    float2 bb[4];
#pragma unroll
    for (int nt = 0; nt < 4; nt++) {
        int cg = col0 + n0w + 8 * nt + 2 * (l & 3);
        bb[nt] = make_float2(bias[cg], bias[cg + 1]);
    }
#pragma unroll
    for (int mt = 0; mt < 4; mt++) {
        int rg = row0 + m0w + 16 * mt + (l >> 2);
#pragma unroll
        for (int nt = 0; nt < 4; nt++) {
            int cg = col0 + n0w + 8 * nt + 2 * (l & 3);
            *(float2*)&C[(size_t)rg * N + cg] =
                make_float2(acc[mt][nt][0] + bb[nt].x, acc[mt][nt][1] + bb[nt].y);
            *(float2*)&C[(size_t)(rg + 8) * N + cg] =
                make_float2(acc[mt][nt][2] + bb[nt].x, acc[mt][nt][3] + bb[nt].y);
        }
    }
}

// ---------------------------------------------------------------------------
// QKV GEMM with fused bias + RoPE epilogue.
// Q tiles (col<768):   rotate, scale 1/8, write fp16 single plane qp.
// K tiles (768..1535): rotate, write fp16 hi/lo planes.
// V tiles (>=1536):    write fp32 into g_qkv (conv_v transposes later).
// ---------------------------------------------------------------------------
__global__ __launch_bounds__(256, 2)
void gemm_qkv_kernel(const __half* __restrict__ A, const __half* __restrict__ B,
                     const float* __restrict__ bias, float* __restrict__ C,
                     __half* __restrict__ qp, __half* __restrict__ khp,
                     __half* __restrict__ klp, const float2* __restrict__ rot,
                     int M, int N, int K)
{
    extern __shared__ __align__(16) char sm[];
    const int tid = threadIdx.x;
    const int w   = tid >> 5;
    const int l   = tid & 31;
    const int row0 = blockIdx.y * 128;
    const int col0 = blockIdx.x * 128;
    const int m0w = (w >> 2) * 64;
    const int n0w = (w & 3) * 32;

    GEMM_MAINLOOP_BODY

    float2 bb[4];
#pragma unroll
    for (int nt = 0; nt < 4; nt++) {
        int cg = col0 + n0w + 8 * nt + 2 * (l & 3);
        bb[nt] = make_float2(bias[cg], bias[cg + 1]);
    }

    if (col0 >= 2 * ND) {
        // V region: fp32 store into qkv
#pragma unroll
        for (int mt = 0; mt < 4; mt++) {
            int rg = row0 + m0w + 16 * mt + (l >> 2);
#pragma unroll
            for (int nt = 0; nt < 4; nt++) {
                int cg = col0 + n0w + 8 * nt + 2 * (l & 3);
                *(float2*)&C[(size_t)rg * N + cg] =
                    make_float2(acc[mt][nt][0] + bb[nt].x, acc[mt][nt][1] + bb[nt].y);
                *(float2*)&C[(size_t)(rg + 8) * N + cg] =
                    make_float2(acc[mt][nt][2] + bb[nt].x, acc[mt][nt][3] + bb[nt].y);
            }
        }
    } else {
        const bool isQ = (col0 < ND);
        const int cbase = isQ ? 0 : ND;
#pragma unroll
        for (int mt = 0; mt < 4; mt++) {
            int rg = row0 + m0w + 16 * mt + (l >> 2);
#pragma unroll
            for (int hf = 0; hf < 2; hf++) {
                int r  = rg + 8 * hf;
                int s0 = r & (NS - 1);
#pragma unroll
                for (int nt = 0; nt < 4; nt++) {
                    int cg = col0 + n0w + 8 * nt + 2 * (l & 3);
                    float v0 = acc[mt][nt][2 * hf + 0] + bb[nt].x;
                    float v1 = acc[mt][nt][2 * hf + 1] + bb[nt].y;
                    int i = (cg & 63) >> 1;
                    float2 cs = rot[s0 * 32 + i];
                    float re = v0 * cs.x - v1 * cs.y;
                    float ro = v1 * cs.x + v0 * cs.y;
                    size_t o = (size_t)r * ND + (cg - cbase);
                    if (isQ) {
                        *(__half2*)&qp[o] = __floats2half2_rn(re * 0.125f, ro * 0.125f);
                    } else {
                        __half he = __float2half_rn(re);
                        __half ho = __float2half_rn(ro);
                        *(__half2*)&khp[o] = __halves2half2(he, ho);
                        *(__half2*)&klp[o] = __floats2half2_rn(
                            re - __half2float(he), ro - __half2float(ho));
                    }
                }
            }
        }
    }
}

// ---------------------------------------------------------------------------
// conv_v: V fp32 [b*NS+s][...] -> transposed fp16 hi/lo planes [b][h][d][s].
// ---------------------------------------------------------------------------
__global__ void conv_v_kernel(const float* __restrict__ qkv,
                              __half* __restrict__ vth,
                              __half* __restrict__ vtl)
{
    __shared__ float t[32][33];
    const int s0 = blockIdx.x * 32;
    const int gy = blockIdx.y;
    const int d0 = (gy & 1) * 32;
    const int bh = gy >> 1;
    const int hh = bh % NH;
    const int b  = bh / NH;
#pragma unroll
    for (int i = 0; i < 4; i++) {
        int s = threadIdx.y + i * 8;
        t[s][threadIdx.x] = qkv[(size_t)(b * NS + s0 + s) * NQKV + 2 * ND + hh * NHD + d0 + threadIdx.x];
    }
    __syncthreads();
#pragma unroll
    for (int i = 0; i < 4; i++) {
        int d = threadIdx.y + i * 8;
        float x = t[threadIdx.x][d];
        __half h  = __float2half_rn(x);
        __half lo = __float2half_rn(x - __half2float(h));
        size_t o = ((size_t)(b * NH + hh) * NHD + d0 + d) * NS + s0 + threadIdx.x;
        vth[o] = h;
        vtl[o] = lo;
    }
}

// ---------------------------------------------------------------------------
// Tensor-core flash attention, fp16 2-pass per matmul.
// planes: 0 Qp, 1 Kh (-> P), 2 Kl, 3 Vth, 4 Vtl
// ---------------------------------------------------------------------------
#define TSROW 144
#define TPL (64 * TSROW)   // 9216 B per plane

__global__ __launch_bounds__(256)
void attn_mma_kernel(const __half* __restrict__ qp_g,
                     const __half* __restrict__ kh_g, const __half* __restrict__ kl_g,
                     const __half* __restrict__ vth_g, const __half* __restrict__ vtl_g,
                     __half* __restrict__ ao,
                     const int* __restrict__ layer_p)
{
    extern __shared__ __align__(16) char sm[];
    char* Pp = sm + TPL;                      // P reuses Kh plane
    float* Sbuf  = (float*)(sm + 5 * TPL);    // [64][68]
    float* row_m = Sbuf + 64 * 68;
    float* row_l = row_m + 64;
    float* row_s = row_l + 64;

    const int tid = threadIdx.x;
    const int w   = tid >> 5;
    const int l   = tid & 31;
    const int blk = blockIdx.x;
    const int qt  = blk & 31;
    const int hh  = (blk >> 5) % NH;
    const int b   = blk / (32 * NH);
    const bool is_global = (layer_p[0] % 3) == 0;
    const int q0 = qt * 64;

    const int mrow = (w & 3) * 16;
    const int ncol = (w >> 2) * 32;
    const uint32_t sb = smem_u32(sm);
    const uint32_t aRel = (uint32_t)(mrow + (l & 15)) * TSROW + (uint32_t)((l >> 4) * 16);
    const int bg = l >> 3;
    const uint32_t bRel = (uint32_t)(ncol + (bg >> 1) * 8 + (l & 7)) * TSROW
                        + (uint32_t)((bg & 1) * 16);

    const int fr  = tid >> 2;
    const int fs  = (tid & 3) * 2;
    const uint32_t fRel = (uint32_t)fr * TSROW + (uint32_t)fs * 16;

    // Q plane (load once)
    {
        const __half* gq = qp_g + (size_t)(b * NS + q0 + fr) * ND + hh * NHD + fs * 8;
        CP16(sb + fRel,      gq);
        CP16(sb + fRel + 16, gq + 8);
        CP_COMMIT();
    }
    if (tid < 64) { row_m[tid] = NEG_BIG; row_l[tid] = 0.f; }

    float oacc[4][4];
#pragma unroll
    for (int i = 0; i < 4; i++)
#pragma unroll
        for (int j = 0; j < 4; j++) oacc[i][j] = 0.f;

    const int kt0 = is_global ? 0 : max(0, qt - 2);
    const int kt1 = is_global ? 31 : min(31, qt + 2);

    for (int kt = kt0; kt <= kt1; kt++) {
        __syncthreads();
        {
            const __half* gkh = kh_g + (size_t)(b * NS + kt * 64 + fr) * ND + hh * NHD + fs * 8;
            const __half* gkl = kl_g + (size_t)(b * NS + kt * 64 + fr) * ND + hh * NHD + fs * 8;
            const __half* gvh = vth_g + ((size_t)(b * NH + hh) * NHD + fr) * NS + kt * 64 + fs * 8;
            const __half* gvl = vtl_g + ((size_t)(b * NH + hh) * NHD + fr) * NS + kt * 64 + fs * 8;
            CP16(sb + 1 * TPL + fRel,      gkh);
            CP16(sb + 1 * TPL + fRel + 16, gkh + 8);
            CP16(sb + 2 * TPL + fRel,      gkl);
            CP16(sb + 2 * TPL + fRel + 16, gkl + 8);
            CP16(sb + 3 * TPL + fRel,      gvh);
            CP16(sb + 3 * TPL + fRel + 16, gvh + 8);
            CP16(sb + 4 * TPL + fRel,      gvl);
            CP16(sb + 4 * TPL + fRel + 16, gvl + 8);
            CP_COMMIT();
            CP_WAIT0();
        }
        __syncthreads();

        // ---- S = Q @ (Kh + Kl)^T  (fp16 2-pass) ----
        float sa[4][4];
#pragma unroll
        for (int i = 0; i < 4; i++)
#pragma unroll
            for (int j = 0; j < 4; j++) sa[i][j] = 0.f;
#pragma unroll
        for (int ks = 0; ks < 4; ks++) {
            const uint32_t kso = (uint32_t)(ks * 32);
            uint32_t q4[4];
            LDSM4(q4, sb + aRel + kso);
            uint32_t bh[4][2], bl[4][2];
#pragma unroll
            for (int jp = 0; jp < 2; jp++) {
                uint32_t r4[4];
                LDSM4(r4, sb + 1 * TPL + bRel + jp * (16 * TSROW) + kso);
                bh[2 * jp][0] = r4[0]; bh[2 * jp][1] = r4[1];
                bh[2 * jp + 1][0] = r4[2]; bh[2 * jp + 1][1] = r4[3];
                LDSM4(r4, sb + 2 * TPL + bRel + jp * (16 * TSROW) + kso);
                bl[2 * jp][0] = r4[0]; bl[2 * jp][1] = r4[1];
                bl[2 * jp + 1][0] = r4[2]; bl[2 * jp + 1][1] = r4[3];
            }
#pragma unroll
            for (int nt = 0; nt < 4; nt++) mma_f16(sa[nt], q4, bh[nt]);
#pragma unroll
            for (int nt = 0; nt < 4; nt++) mma_f16(sa[nt], q4, bl[nt]);
        }
        {
            int fr0 = mrow + (l >> 2);
#pragma unroll
            for (int nt = 0; nt < 4; nt++) {
                int col = ncol + 8 * nt + 2 * (l & 3);
                *(float2*)&Sbuf[fr0 * 68 + col]       = make_float2(sa[nt][0], sa[nt][1]);
                *(float2*)&Sbuf[(fr0 + 8) * 68 + col] = make_float2(sa[nt][2], sa[nt][3]);
            }
        }
        __syncthreads();

        // ---- banded mask + online softmax; emit P fp16 (reuses Kh plane) ----
        {
            int r  = tid >> 2;
            int qd = tid & 3;
            float* Pr = &Sbuf[r * 68 + qd * 16];
            if (!is_global) {
#pragma unroll
                for (int c = 0; c < 16; c++) {
                    int dlt = (q0 + r) - (kt * 64 + qd * 16 + c);
                    if (dlt < 0) dlt = -dlt;
                    if (dlt > 128) Pr[c] = NEG_BIG;
                }
            }
            float mloc = NEG_BIG;
#pragma unroll
            for (int c = 0; c < 16; c++) mloc = fmaxf(mloc, Pr[c]);
            mloc = fmaxf(mloc, __shfl_xor_sync(0xffffffffu, mloc, 1));
            mloc = fmaxf(mloc, __shfl_xor_sync(0xffffffffu, mloc, 2));
            float m_old = row_m[r];
            float m_new = fmaxf(m_old, mloc);
            float ls = 0.f;
#pragma unroll
            for (int c = 0; c < 16; c += 2) {
                float e0 = __expf(Pr[c]     - m_new);
                float e1 = __expf(Pr[c + 1] - m_new);
                ls += e0 + e1;
                uint32_t off = (uint32_t)(r * TSROW + (qd * 16 + c) * 2);
                *(__half2*)(Pp + off) = __floats2half2_rn(e0, e1);
            }
            ls += __shfl_xor_sync(0xffffffffu, ls, 1);
            ls += __shfl_xor_sync(0xffffffffu, ls, 2);
            if (qd == 0) {
                float fac = __expf(m_old - m_new);
                row_s[r] = fac;
                row_m[r] = m_new;
                row_l[r] = row_l[r] * fac + ls;
            }
        }
        __syncthreads();

        // ---- rescale O; O += P @ (Vh + Vl)  (fp16 2-pass) ----
        {
            float f0 = row_s[mrow + (l >> 2)];
            float f1 = row_s[mrow + 8 + (l >> 2)];
#pragma unroll
            for (int nt = 0; nt < 4; nt++) {
                oacc[nt][0] *= f0; oacc[nt][1] *= f0;
                oacc[nt][2] *= f1; oacc[nt][3] *= f1;
            }
#pragma unroll
            for (int ks = 0; ks < 4; ks++) {
                const uint32_t kso = (uint32_t)(ks * 32);
                uint32_t p4[4];
                LDSM4(p4, sb + 1 * TPL + aRel + kso);
                uint32_t vh[4][2], vl[4][2];
#pragma unroll
                for (int jp = 0; jp < 2; jp++) {
                    uint32_t r4[4];
                    LDSM4(r4, sb + 3 * TPL + bRel + jp * (16 * TSROW) + kso);
                    vh[2 * jp][0] = r4[0]; vh[2 * jp][1] = r4[1];
                    vh[2 * jp + 1][0] = r4[2]; vh[2 * jp + 1][1] = r4[3];
                    LDSM4(r4, sb + 4 * TPL + bRel + jp * (16 * TSROW) + kso);
                    vl[2 * jp][0] = r4[0]; vl[2 * jp][1] = r4[1];
                    vl[2 * jp + 1][0] = r4[2]; vl[2 * jp + 1][1] = r4[3];
                }
#pragma unroll
                for (int nt = 0; nt < 4; nt++) mma_f16(oacc[nt], p4, vh[nt]);
#pragma unroll
                for (int nt = 0; nt < 4; nt++) mma_f16(oacc[nt], p4, vl[nt]);
            }
        }
    }

    // normalize + write single fp16 plane
    {
        float i0 = 1.f / row_l[mrow + (l >> 2)];
        float i1 = 1.f / row_l[mrow + 8 + (l >> 2)];
        size_t r0 = (size_t)(b * NS + q0 + mrow + (l >> 2)) * ND;
        size_t r1 = r0 + 8 * (size_t)ND;
#pragma unroll
        for (int nt = 0; nt < 4; nt++) {
            int col = hh * NHD + ncol + 8 * nt + 2 * (l & 3);
            *(__half2*)&ao[r0 + col] = __floats2half2_rn(oacc[nt][0] * i0, oacc[nt][1] * i0);
            *(__half2*)&ao[r1 + col] = __floats2half2_rn(oacc[nt][2] * i1, oacc[nt][3] * i1);
        }
    }
}

// ---------------------------------------------------------------------------
extern "C" void kernel_launch(void* const* d_in, const int* in_sizes, int n_in,
                              void* d_out, int out_size)
{
    const float* x     = (const float*)d_in[0];
    const float* Wqkv  = (const float*)d_in[1];
    const float* bqkv  = (const float*)d_in[2];
    const float* Wout  = (const float*)d_in[3];
    const float* bout  = (const float*)d_in[4];
    const int*   layer = (const int*)d_in[5];
    float* out = (float*)d_out;

    float *qkv;
    float2* rot;
    __half *x16, *a16, *wq, *wo, *qp, *khp, *klp, *vth, *vtl;
    cudaGetSymbolAddress((void**)&qkv, g_qkv);
    cudaGetSymbolAddress((void**)&rot, g_rot);
    cudaGetSymbolAddress((void**)&x16, g_x16);
    cudaGetSymbolAddress((void**)&a16, g_a16);
    cudaGetSymbolAddress((void**)&wq, g_wq16);
    cudaGetSymbolAddress((void**)&wo, g_wo16);
    cudaGetSymbolAddress((void**)&qp, g_qp);
    cudaGetSymbolAddress((void**)&khp, g_kh16);
    cudaGetSymbolAddress((void**)&klp, g_kl16);
    cudaGetSymbolAddress((void**)&vth, g_vth16);
    cudaGetSymbolAddress((void**)&vtl, g_vtl16);

    const int gemm_smem = NSTAGE * STG;   // 98304 B
    cudaFuncSetAttribute(gemm_mma_kernel, cudaFuncAttributeMaxDynamicSharedMemorySize, gemm_smem);
    cudaFuncSetAttribute(gemm_qkv_kernel, cudaFuncAttributeMaxDynamicSharedMemorySize, gemm_smem);
    const int attn_smem = 5 * TPL + 64 * 68 * 4 + 3 * 64 * 4;   // 64256 B
    cudaFuncSetAttribute(attn_mma_kernel, cudaFuncAttributeMaxDynamicSharedMemorySize, attn_smem);

    // 0) conversions + rot table
    conv_fp16_kernel<<<(NROWS * ND / 2 + 255) / 256, 256>>>(x, x16, NROWS * ND / 2);
    convW_kernel<<<dim3(NQKV / 32, ND / 32), dim3(32, 8)>>>(Wqkv, wq, ND, NQKV);
    convW_kernel<<<dim3(ND / 32, ND / 32), dim3(32, 8)>>>(Wout, wo, ND, ND);
    rot_kernel<<<(NS * 32) / 256, 256>>>(layer, rot);

    // 1) qkv GEMM with fused bias + RoPE epilogue (Q/K planes + V fp32)
    gemm_qkv_kernel<<<dim3(NQKV / 128, NROWS / 128), 256, gemm_smem>>>(
        x16, wq, bqkv, qkv, qp, khp, klp, rot, NROWS, NQKV, ND);
    // 2) V -> transposed fp16 hi/lo planes
    conv_v_kernel<<<dim3(NS / 32, NB * NH * 2), dim3(32, 8)>>>(qkv, vth, vtl);
    // 3) tensor-core banded attention (fp16 2-pass; writes fp16 plane)
    attn_mma_kernel<<<NB * NH * 32, 256, attn_smem>>>(qp, khp, klp, vth, vtl, a16, layer);
    // 4) out = attn @ Wout + bout   (single-pass fp16)
    gemm_mma_kernel<<<dim3(ND / 128, NROWS / 128), 256, gemm_smem>>>(
        a16, wo, bout, out, NROWS, ND, ND);
}

// round 15
// speedup vs baseline: 2.7253x; 1.1323x over previous
#include <cuda_runtime.h>
#include <cuda_fp16.h>
#include <math.h>
#include <stdint.h>

#define NB 2
#define NS 2048
#define ND 768
#define NH 12
#define NHD 64
#define NQKV 2304
#define NROWS 4096   // NB*NS

#define NEG_BIG (-1e30f)

// ---------------- scratch (device globals; allocation-free) -----------------
__device__ __half g_x16[(size_t)NROWS * ND];                  // x fp16 (A of GEMM1)
__device__ __half g_a16[(size_t)NROWS * ND];                  // attn out fp16 (A of GEMM2)
__device__ __half g_wq16[(size_t)NQKV * ND];                  // Wqkv^T fp16 [N][K]
__device__ __half g_wo16[(size_t)ND * ND];                    // Wout^T fp16 [N][K]
__device__ float2 g_rot[NS * 32];                             // cos/sin table
// attention operand planes (fp16)
__device__ __half g_qp[(size_t)NROWS * ND];                   // rotated, scaled Q
__device__ __half g_kh16[(size_t)NROWS * ND];                 // rotated K hi
__device__ __half g_kl16[(size_t)NROWS * ND];                 // rotated K lo
__device__ __half g_vth16[(size_t)NROWS * ND];                // V^T fp16 [b][h][d][s]

__device__ __forceinline__ uint32_t smem_u32(const void* p) {
    uint32_t a;
    asm("{ .reg .u64 t; cvta.to.shared.u64 t, %1; cvt.u32.u64 %0, t; }" : "=r"(a) : "l"(p));
    return a;
}

__device__ __forceinline__ void mma_f16(float c[4], const uint32_t a[4], const uint32_t b[2]) {
    asm volatile(
        "mma.sync.aligned.m16n8k16.row.col.f32.f16.f16.f32 "
        "{%0,%1,%2,%3}, {%4,%5,%6,%7}, {%8,%9}, {%0,%1,%2,%3};"
        : "+f"(c[0]), "+f"(c[1]), "+f"(c[2]), "+f"(c[3])
        : "r"(a[0]), "r"(a[1]), "r"(a[2]), "r"(a[3]), "r"(b[0]), "r"(b[1]));
}

#define LDSM4(r, addr) \
    asm volatile("ldmatrix.sync.aligned.m8n8.x4.shared.b16 {%0,%1,%2,%3}, [%4];" \
                 : "=r"((r)[0]), "=r"((r)[1]), "=r"((r)[2]), "=r"((r)[3]) : "r"(addr))

#define CP16(dst, src) \
    asm volatile("cp.async.cg.shared.global [%0], [%1], 16;" :: "r"(dst), "l"(src))
#define CP_COMMIT() asm volatile("cp.async.commit_group;")
#define CP_WAIT4()  asm volatile("cp.async.wait_group 4;")
#define CP_WAIT3()  asm volatile("cp.async.wait_group 3;")
#define CP_WAIT2()  asm volatile("cp.async.wait_group 2;")
#define CP_WAIT1()  asm volatile("cp.async.wait_group 1;")
#define CP_WAIT0()  asm volatile("cp.async.wait_group 0;")

// ---------------------------------------------------------------------------
// prep_x_rot: blocks [0,6144): x fp32->fp16; blocks [6144,6400): rot table.
// ---------------------------------------------------------------------------
__global__ void prep_x_rot_kernel(const float* __restrict__ x, __half* __restrict__ o,
                                  const int* __restrict__ layer_p, float2* __restrict__ rot)
{
    int blk = blockIdx.x;
    if (blk < 6144) {
        int i = blk * 256 + threadIdx.x;
        float2 v = ((const float2*)x)[i];
        ((__half2*)o)[i] = __floats2half2_rn(v.x, v.y);
    } else {
        int idx = (blk - 6144) * 256 + threadIdx.x;
        int i = idx & 31;
        int s = idx >> 5;
        bool is_global = (layer_p[0] % 3) == 0;
        float theta = is_global ? 160000.f : 10000.f;
        float freq  = powf(theta, -(float)(2 * i) / 64.f);
        float sn, cs;
        sincosf((float)s * freq, &sn, &cs);
        rot[idx] = make_float2(cs, sn);
    }
}

// ---------------------------------------------------------------------------
// prep_w: both weight transpose-converts in one launch (z: 0=Wqkv, 1=Wout).
// ---------------------------------------------------------------------------
__global__ void prep_w_kernel(const float* __restrict__ Wq, const float* __restrict__ Wo,
                              __half* __restrict__ oq, __half* __restrict__ oo)
{
    const float* W;
    __half* o;
    int N;
    if (blockIdx.z == 0) { W = Wq; o = oq; N = NQKV; }
    else {
        if (blockIdx.x >= ND / 32) return;
        W = Wo; o = oo; N = ND;
    }
    const int K = ND;
    __shared__ float t[32][33];
    const int n0 = blockIdx.x * 32, k0 = blockIdx.y * 32;
#pragma unroll
    for (int i = 0; i < 4; i++) {
        int k = threadIdx.y + i * 8;
        t[k][threadIdx.x] = W[(size_t)(k0 + k) * N + n0 + threadIdx.x];
    }
    __syncthreads();
#pragma unroll
    for (int i = 0; i < 4; i++) {
        int n = threadIdx.y + i * 8;
        o[(size_t)(n0 + n) * K + k0 + threadIdx.x] = __float2half_rn(t[threadIdx.x][n]);
    }
}

// ---------------------------------------------------------------------------
// Shared GEMM mainloop: 128x128, BK=32, 6-stage cp.async, 2 CTAs/SM.
// ---------------------------------------------------------------------------
#define PL 8192
#define STG (2 * PL)
#define NSTAGE 6

#define GEMM_MAINLOOP_BODY                                                     \
    float acc[4][4][4];                                                        \
    _Pragma("unroll")                                                          \
    for (int i = 0; i < 4; i++)                                                \
        _Pragma("unroll")                                                      \
        for (int j = 0; j < 4; j++)                                            \
            _Pragma("unroll")                                                  \
            for (int q = 0; q < 4; q++) acc[i][j][q] = 0.f;                    \
    const uint32_t sb = smem_u32(sm);                                          \
    const int rA   = m0w + (l & 15);                                           \
    const uint32_t selA = (uint32_t)((rA >> 1) & 3);                           \
    const uint32_t c0A  = (uint32_t)(l >> 4);                                  \
    const uint32_t aRel0 = (uint32_t)rA * 64 + ((c0A ^ selA) << 4);            \
    const uint32_t aRel1 = (uint32_t)rA * 64 + (((c0A + 2) ^ selA) << 4);      \
    const int bg = l >> 3;                                                     \
    const int rB = n0w + (bg >> 1) * 8 + (l & 7);                              \
    const uint32_t selB = (uint32_t)((rB >> 1) & 3);                           \
    const uint32_t c0B  = (uint32_t)(bg & 1);                                  \
    const uint32_t bRel0 = PL + (uint32_t)rB * 64 + ((c0B ^ selB) << 4);       \
    const uint32_t bRel1 = PL + (uint32_t)rB * 64 + (((c0B + 2) ^ selB) << 4); \
    const int fr = tid >> 1;                                                   \
    const int fc = (tid & 1) * 2;                                              \
    const uint32_t fsel = (uint32_t)((fr >> 1) & 3);                           \
    const uint32_t d0 = (uint32_t)fr * 64 + (((uint32_t)fc ^ fsel) << 4);      \
    const uint32_t d1 = (uint32_t)fr * 64 + ((((uint32_t)fc + 1) ^ fsel) << 4);\
    const __half* gA = A + (size_t)(row0 + fr) * K + fc * 8;                   \
    const __half* gB = B + (size_t)(col0 + fr) * K + fc * 8;                   \
    const int nch = K >> 5;                                                    \
    auto issue = [&](int kc, int s) {                                          \
        const int ke = kc << 5;                                                \
        const uint32_t st = sb + (uint32_t)s * STG;                            \
        CP16(st + d0,      gA + ke);                                           \
        CP16(st + d1,      gA + ke + 8);                                       \
        CP16(st + PL + d0, gB + ke);                                           \
        CP16(st + PL + d1, gB + ke + 8);                                       \
        CP_COMMIT();                                                           \
    };                                                                         \
    _Pragma("unroll")                                                          \
    for (int p = 0; p < 5; p++)                                                \
        if (p < nch) issue(p, p);                                              \
    int s = 0;                                                                 \
    for (int kc = 0; kc < nch; kc++) {                                         \
        int after = nch - 1 - kc;                                              \
        if (after > 4) after = 4;                                              \
        switch (after) {                                                       \
            case 4: CP_WAIT4(); break;                                         \
            case 3: CP_WAIT3(); break;                                         \
            case 2: CP_WAIT2(); break;                                         \
            case 1: CP_WAIT1(); break;                                         \
            default: CP_WAIT0(); break;                                        \
        }                                                                      \
        __syncthreads();                                                       \
        if (kc + 5 < nch) {                                                    \
            int s5 = s + 5; if (s5 >= NSTAGE) s5 -= NSTAGE;                    \
            issue(kc + 5, s5);                                                 \
        }                                                                      \
        const uint32_t stb = sb + (uint32_t)s * STG;                           \
        _Pragma("unroll")                                                      \
        for (int ks = 0; ks < 2; ks++) {                                       \
            const uint32_t aR = ks ? aRel1 : aRel0;                            \
            const uint32_t bR = ks ? bRel1 : bRel0;                            \
            uint32_t a4[4][4];                                                 \
            _Pragma("unroll")                                                  \
            for (int mt = 0; mt < 4; mt++)                                     \
                LDSM4(a4[mt], stb + aR + mt * 1024);                           \
            uint32_t b4[4][2];                                                 \
            _Pragma("unroll")                                                  \
            for (int jp = 0; jp < 2; jp++) {                                   \
                uint32_t r[4];                                                 \
                LDSM4(r, stb + bR + jp * 1024);                                \
                b4[2 * jp][0] = r[0]; b4[2 * jp][1] = r[1];                    \
                b4[2 * jp + 1][0] = r[2]; b4[2 * jp + 1][1] = r[3];            \
            }                                                                  \
            _Pragma("unroll")                                                  \
            for (int mt = 0; mt < 4; mt++)                                     \
                _Pragma("unroll")                                              \
                for (int nt = 0; nt < 4; nt++)                                 \
                    mma_f16(acc[mt][nt], a4[mt], b4[nt]);                      \
        }                                                                      \
        if (++s >= NSTAGE) s = 0;                                              \
    }

// ---------------------------------------------------------------------------
// Generic fp16 GEMM + bias -> fp32 C (out-projection).
// ---------------------------------------------------------------------------
__global__ __launch_bounds__(256, 2)
void gemm_mma_kernel(const __half* __restrict__ A, const __half* __restrict__ B,
                     const float* __restrict__ bias, float* __restrict__ C,
                     int M, int N, int K)
{
    extern __shared__ __align__(16) char sm[];
    const int tid = threadIdx.x;
    const int w   = tid >> 5;
    const int l   = tid & 31;
    const int row0 = blockIdx.y * 128;
    const int col0 = blockIdx.x * 128;
    const int m0w = (w >> 2) * 64;
    const int n0w = (w & 3) * 32;

    GEMM_MAINLOOP_BODY

    float2 bb[4];
#pragma unroll
    for (int nt = 0; nt < 4; nt++) {
        int cg = col0 + n0w + 8 * nt + 2 * (l & 3);
        bb[nt] = make_float2(bias[cg], bias[cg + 1]);
    }
#pragma unroll
    for (int mt = 0; mt < 4; mt++) {
        int rg = row0 + m0w + 16 * mt + (l >> 2);
#pragma unroll
        for (int nt = 0; nt < 4; nt++) {
            int cg = col0 + n0w + 8 * nt + 2 * (l & 3);
            *(float2*)&C[(size_t)rg * N + cg] =
                make_float2(acc[mt][nt][0] + bb[nt].x, acc[mt][nt][1] + bb[nt].y);
            *(float2*)&C[(size_t)(rg + 8) * N + cg] =
                make_float2(acc[mt][nt][2] + bb[nt].x, acc[mt][nt][3] + bb[nt].y);
        }
    }
}

// ---------------------------------------------------------------------------
// QKV GEMM, fully fused epilogue:
//   Q tiles: bias + RoPE + 1/8 scale -> fp16 plane qp
//   K tiles: bias + RoPE -> fp16 hi/lo planes
//   V tiles: bias -> fp16, smem transpose -> vth [b][h][d][s]
// ---------------------------------------------------------------------------
__global__ __launch_bounds__(256, 2)
void gemm_qkv_kernel(const __half* __restrict__ A, const __half* __restrict__ B,
                     const float* __restrict__ bias,
                     __half* __restrict__ qp, __half* __restrict__ khp,
                     __half* __restrict__ klp, __half* __restrict__ vth,
                     const float2* __restrict__ rot,
                     int M, int N, int K)
{
    extern __shared__ __align__(16) char sm[];
    const int tid = threadIdx.x;
    const int w   = tid >> 5;
    const int l   = tid & 31;
    const int row0 = blockIdx.y * 128;
    const int col0 = blockIdx.x * 128;
    const int m0w = (w >> 2) * 64;
    const int n0w = (w & 3) * 32;

    GEMM_MAINLOOP_BODY

    float2 bb[4];
#pragma unroll
    for (int nt = 0; nt < 4; nt++) {
        int cg = col0 + n0w + 8 * nt + 2 * (l & 3);
        bb[nt] = make_float2(bias[cg], bias[cg + 1]);
    }

    if (col0 < 2 * ND) {
        const bool isQ = (col0 < ND);
        const int cbase = isQ ? 0 : ND;
#pragma unroll
        for (int mt = 0; mt < 4; mt++) {
            int rg = row0 + m0w + 16 * mt + (l >> 2);
#pragma unroll
            for (int hf = 0; hf < 2; hf++) {
                int r  = rg + 8 * hf;
                int s0 = r & (NS - 1);
#pragma unroll
                for (int nt = 0; nt < 4; nt++) {
                    int cg = col0 + n0w + 8 * nt + 2 * (l & 3);
                    float v0 = acc[mt][nt][2 * hf + 0] + bb[nt].x;
                    float v1 = acc[mt][nt][2 * hf + 1] + bb[nt].y;
                    int i = (cg & 63) >> 1;
                    float2 cs = rot[s0 * 32 + i];
                    float re = v0 * cs.x - v1 * cs.y;
                    float ro = v1 * cs.x + v0 * cs.y;
                    size_t o = (size_t)r * ND + (cg - cbase);
                    if (isQ) {
                        *(__half2*)&qp[o] = __floats2half2_rn(re * 0.125f, ro * 0.125f);
                    } else {
                        __half he = __float2half_rn(re);
                        __half ho = __float2half_rn(ro);
                        *(__half2*)&khp[o] = __halves2half2(he, ho);
                        *(__half2*)&klp[o] = __floats2half2_rn(
                            re - __half2float(he), ro - __half2float(ho));
                    }
                }
            }
        }
    } else {
        // V: bias + fp16, smem transpose, write [b][h][d][s] plane
        __half* smT = (__half*)sm;        // [128 cols][136 rows-stride]
        __syncthreads();                   // mainloop smem consumers done
#pragma unroll
        for (int mt = 0; mt < 4; mt++) {
#pragma unroll
            for (int hf = 0; hf < 2; hf++) {
                int rloc = m0w + 16 * mt + (l >> 2) + 8 * hf;
#pragma unroll
                for (int nt = 0; nt < 4; nt++) {
                    int cloc = n0w + 8 * nt + 2 * (l & 3);
                    smT[(cloc) * 136 + rloc] =
                        __float2half_rn(acc[mt][nt][2 * hf + 0] + bb[nt].x);
                    smT[(cloc + 1) * 136 + rloc] =
                        __float2half_rn(acc[mt][nt][2 * hf + 1] + bb[nt].y);
                }
            }
        }
        __syncthreads();
        int c  = tid >> 1;
        int hf = tid & 1;
        int d  = col0 - 2 * ND + c;
        int hh = d >> 6, dd = d & 63;
        int b  = row0 >> 11;
        int s0 = row0 & (NS - 1);
        size_t base = ((size_t)(b * NH + hh) * NHD + dd) * NS + s0 + hf * 64;
#pragma unroll
        for (int j = 0; j < 64; j += 8) {
            uint4 v = *(uint4*)&smT[c * 136 + hf * 64 + j];
            *(uint4*)&vth[base + j] = v;
        }
    }
}

// ---------------------------------------------------------------------------
// Tensor-core flash attention: S fp16 2-pass, PV fp16 single-pass.
// planes: 0 Qp, 1 Kh (-> P), 2 Kl, 3 Vth
// ---------------------------------------------------------------------------
#define TSROW 144
#define TPL (64 * TSROW)   // 9216 B per plane

__global__ __launch_bounds__(256)
void attn_mma_kernel(const __half* __restrict__ qp_g,
                     const __half* __restrict__ kh_g, const __half* __restrict__ kl_g,
                     const __half* __restrict__ vth_g,
                     __half* __restrict__ ao,
                     const int* __restrict__ layer_p)
{
    extern __shared__ __align__(16) char sm[];
    char* Pp = sm + TPL;                      // P reuses Kh plane
    float* Sbuf  = (float*)(sm + 4 * TPL);    // [64][68]
    float* row_m = Sbuf + 64 * 68;
    float* row_l = row_m + 64;
    float* row_s = row_l + 64;

    const int tid = threadIdx.x;
    const int w   = tid >> 5;
    const int l   = tid & 31;
    const int blk = blockIdx.x;
    const int qt  = blk & 31;
    const int hh  = (blk >> 5) % NH;
    const int b   = blk / (32 * NH);
    const bool is_global = (layer_p[0] % 3) == 0;
    const int q0 = qt * 64;

    const int mrow = (w & 3) * 16;
    const int ncol = (w >> 2) * 32;
    const uint32_t sb = smem_u32(sm);
    const uint32_t aRel = (uint32_t)(mrow + (l & 15)) * TSROW + (uint32_t)((l >> 4) * 16);
    const int bg = l >> 3;
    const uint32_t bRel = (uint32_t)(ncol + (bg >> 1) * 8 + (l & 7)) * TSROW
                        + (uint32_t)((bg & 1) * 16);

    const int fr  = tid >> 2;
    const int fs  = (tid & 3) * 2;
    const uint32_t fRel = (uint32_t)fr * TSROW + (uint32_t)fs * 16;

    // Q plane (load once)
    {
        const __half* gq = qp_g + (size_t)(b * NS + q0 + fr) * ND + hh * NHD + fs * 8;
        CP16(sb + fRel,      gq);
        CP16(sb + fRel + 16, gq + 8);
        CP_COMMIT();
    }
    if (tid < 64) { row_m[tid] = NEG_BIG; row_l[tid] = 0.f; }

    float oacc[4][4];
#pragma unroll
    for (int i = 0; i < 4; i++)
#pragma unroll
        for (int j = 0; j < 4; j++) oacc[i][j] = 0.f;

    const int kt0 = is_global ? 0 : max(0, qt - 2);
    const int kt1 = is_global ? 31 : min(31, qt + 2);

    for (int kt = kt0; kt <= kt1; kt++) {
        __syncthreads();
        {
            const __half* gkh = kh_g + (size_t)(b * NS + kt * 64 + fr) * ND + hh * NHD + fs * 8;
            const __half* gkl = kl_g + (size_t)(b * NS + kt * 64 + fr) * ND + hh * NHD + fs * 8;
            const __half* gvh = vth_g + ((size_t)(b * NH + hh) * NHD + fr) * NS + kt * 64 + fs * 8;
            CP16(sb + 1 * TPL + fRel,      gkh);
            CP16(sb + 1 * TPL + fRel + 16, gkh + 8);
            CP16(sb + 2 * TPL + fRel,      gkl);
            CP16(sb + 2 * TPL + fRel + 16, gkl + 8);
            CP16(sb + 3 * TPL + fRel,      gvh);
            CP16(sb + 3 * TPL + fRel + 16, gvh + 8);
            CP_COMMIT();
            CP_WAIT0();
        }
        __syncthreads();

        // ---- S = Q @ (Kh + Kl)^T  (fp16 2-pass) ----
        float sa[4][4];
#pragma unroll
        for (int i = 0; i < 4; i++)
#pragma unroll
            for (int j = 0; j < 4; j++) sa[i][j] = 0.f;
#pragma unroll
        for (int ks = 0; ks < 4; ks++) {
            const uint32_t kso = (uint32_t)(ks * 32);
            uint32_t q4[4];
            LDSM4(q4, sb + aRel + kso);
            uint32_t bh[4][2], bl[4][2];
#pragma unroll
            for (int jp = 0; jp < 2; jp++) {
                uint32_t r4[4];
                LDSM4(r4, sb + 1 * TPL + bRel + jp * (16 * TSROW) + kso);
                bh[2 * jp][0] = r4[0]; bh[2 * jp][1] = r4[1];
                bh[2 * jp + 1][0] = r4[2]; bh[2 * jp + 1][1] = r4[3];
                LDSM4(r4, sb + 2 * TPL + bRel + jp * (16 * TSROW) + kso);
                bl[2 * jp][0] = r4[0]; bl[2 * jp][1] = r4[1];
                bl[2 * jp + 1][0] = r4[2]; bl[2 * jp + 1][1] = r4[3];
            }
#pragma unroll
            for (int nt = 0; nt < 4; nt++) mma_f16(sa[nt], q4, bh[nt]);
#pragma unroll
            for (int nt = 0; nt < 4; nt++) mma_f16(sa[nt], q4, bl[nt]);
        }
        {
            int fr0 = mrow + (l >> 2);
#pragma unroll
            for (int nt = 0; nt < 4; nt++) {
                int col = ncol + 8 * nt + 2 * (l & 3);
                *(float2*)&Sbuf[fr0 * 68 + col]       = make_float2(sa[nt][0], sa[nt][1]);
                *(float2*)&Sbuf[(fr0 + 8) * 68 + col] = make_float2(sa[nt][2], sa[nt][3]);
            }
        }
        __syncthreads();

        // ---- banded mask + online softmax; emit P fp16 (reuses Kh plane) ----
        {
            int r  = tid >> 2;
            int qd = tid & 3;
            float* Pr = &Sbuf[r * 68 + qd * 16];
            if (!is_global) {
#pragma unroll
                for (int c = 0; c < 16; c++) {
                    int dlt = (q0 + r) - (kt * 64 + qd * 16 + c);
                    if (dlt < 0) dlt = -dlt;
                    if (dlt > 128) Pr[c] = NEG_BIG;
                }
            }
            float mloc = NEG_BIG;
#pragma unroll
            for (int c = 0; c < 16; c++) mloc = fmaxf(mloc, Pr[c]);
            mloc = fmaxf(mloc, __shfl_xor_sync(0xffffffffu, mloc, 1));
            mloc = fmaxf(mloc, __shfl_xor_sync(0xffffffffu, mloc, 2));
            float m_old = row_m[r];
            float m_new = fmaxf(m_old, mloc);
            float ls = 0.f;
#pragma unroll
            for (int c = 0; c < 16; c += 2) {
                float e0 = __expf(Pr[c]     - m_new);
                float e1 = __expf(Pr[c + 1] - m_new);
                ls += e0 + e1;
                uint32_t off = (uint32_t)(r * TSROW + (qd * 16 + c) * 2);
                *(__half2*)(Pp + off) = __floats2half2_rn(e0, e1);
            }
            ls += __shfl_xor_sync(0xffffffffu, ls, 1);
            ls += __shfl_xor_sync(0xffffffffu, ls, 2);
            if (qd == 0) {
                float fac = __expf(m_old - m_new);
                row_s[r] = fac;
                row_m[r] = m_new;
                row_l[r] = row_l[r] * fac + ls;
            }
        }
        __syncthreads();

        // ---- rescale O; O += P @ Vh  (fp16 single-pass) ----
        {
            float f0 = row_s[mrow + (l >> 2)];
            float f1 = row_s[mrow + 8 + (l >> 2)];
#pragma unroll
            for (int nt = 0; nt < 4; nt++) {
                oacc[nt][0] *= f0; oacc[nt][1] *= f0;
                oacc[nt][2] *= f1; oacc[nt][3] *= f1;
            }
#pragma unroll
            for (int ks = 0; ks < 4; ks++) {
                const uint32_t kso = (uint32_t)(ks * 32);
                uint32_t p4[4];
                LDSM4(p4, sb + 1 * TPL + aRel + kso);
                uint32_t vh[4][2];
#pragma unroll
                for (int jp = 0; jp < 2; jp++) {
                    uint32_t r4[4];
                    LDSM4(r4, sb + 3 * TPL + bRel + jp * (16 * TSROW) + kso);
                    vh[2 * jp][0] = r4[0]; vh[2 * jp][1] = r4[1];
                    vh[2 * jp + 1][0] = r4[2]; vh[2 * jp + 1][1] = r4[3];
                }
#pragma unroll
                for (int nt = 0; nt < 4; nt++) mma_f16(oacc[nt], p4, vh[nt]);
            }
        }
    }

    // normalize + write single fp16 plane
    {
        float i0 = 1.f / row_l[mrow + (l >> 2)];
        float i1 = 1.f / row_l[mrow + 8 + (l >> 2)];
        size_t r0 = (size_t)(b * NS + q0 + mrow + (l >> 2)) * ND;
        size_t r1 = r0 + 8 * (size_t)ND;
#pragma unroll
        for (int nt = 0; nt < 4; nt++) {
            int col = hh * NHD + ncol + 8 * nt + 2 * (l & 3);
            *(__half2*)&ao[r0 + col] = __floats2half2_rn(oacc[nt][0] * i0, oacc[nt][1] * i0);
            *(__half2*)&ao[r1 + col] = __floats2half2_rn(oacc[nt][2] * i1, oacc[nt][3] * i1);
        }
    }
}

// ---------------------------------------------------------------------------
extern "C" void kernel_launch(void* const* d_in, const int* in_sizes, int n_in,
                              void* d_out, int out_size)
{
    const float* x     = (const float*)d_in[0];
    const float* Wqkv  = (const float*)d_in[1];
    const float* bqkv  = (const float*)d_in[2];
    const float* Wout  = (const float*)d_in[3];
    const float* bout  = (const float*)d_in[4];
    const int*   layer = (const int*)d_in[5];
    float* out = (float*)d_out;

    float2* rot;
    __half *x16, *a16, *wq, *wo, *qp, *khp, *klp, *vth;
    cudaGetSymbolAddress((void**)&rot, g_rot);
    cudaGetSymbolAddress((void**)&x16, g_x16);
    cudaGetSymbolAddress((void**)&a16, g_a16);
    cudaGetSymbolAddress((void**)&wq, g_wq16);
    cudaGetSymbolAddress((void**)&wo, g_wo16);
    cudaGetSymbolAddress((void**)&qp, g_qp);
    cudaGetSymbolAddress((void**)&khp, g_kh16);
    cudaGetSymbolAddress((void**)&klp, g_kl16);
    cudaGetSymbolAddress((void**)&vth, g_vth16);

    const int gemm_smem = NSTAGE * STG;   // 98304 B
    cudaFuncSetAttribute(gemm_mma_kernel, cudaFuncAttributeMaxDynamicSharedMemorySize, gemm_smem);
    cudaFuncSetAttribute(gemm_qkv_kernel, cudaFuncAttributeMaxDynamicSharedMemorySize, gemm_smem);
    const int attn_smem = 4 * TPL + 64 * 68 * 4 + 3 * 64 * 4;   // 54272 B
    cudaFuncSetAttribute(attn_mma_kernel, cudaFuncAttributeMaxDynamicSharedMemorySize, attn_smem);

    // 0) prep: x->fp16 + rot table; both weight transposes
    prep_x_rot_kernel<<<6400, 256>>>(x, x16, layer, rot);
    prep_w_kernel<<<dim3(NQKV / 32, ND / 32, 2), dim3(32, 8)>>>(Wqkv, Wout, wq, wo);

    // 1) qkv GEMM, fully fused epilogue (Q/K rope planes, V transposed plane)
    gemm_qkv_kernel<<<dim3(NQKV / 128, NROWS / 128), 256, gemm_smem>>>(
        x16, wq, bqkv, qp, khp, klp, vth, rot, NROWS, NQKV, ND);
    // 2) tensor-core banded attention
    attn_mma_kernel<<<NB * NH * 32, 256, attn_smem>>>(qp, khp, klp, vth, a16, layer);
    // 3) out = attn @ Wout + bout
    gemm_mma_kernel<<<dim3(ND / 128, NROWS / 128), 256, gemm_smem>>>(
        a16, wo, bout, out, NROWS, ND, ND);
}

// round 16
// speedup vs baseline: 2.7258x; 1.0002x over previous
#include <cuda_runtime.h>
#include <cuda_fp16.h>
#include <math.h>
#include <stdint.h>

#define NB 2
#define NS 2048
#define ND 768
#define NH 12
#define NHD 64
#define NQKV 2304
#define NROWS 4096   // NB*NS

#define NEG_BIG (-1e30f)

// ---------------- scratch (device globals; allocation-free) -----------------
__device__ __half g_x16[(size_t)NROWS * ND];                  // x fp16 (A of GEMM1)
__device__ __half g_a16[(size_t)NROWS * ND];                  // attn out fp16 (A of GEMM2)
__device__ __half g_wq16[(size_t)NQKV * ND];                  // Wqkv^T fp16 [N][K]
__device__ __half g_wo16[(size_t)ND * ND];                    // Wout^T fp16 [N][K]
__device__ float2 g_rot[NS * 32];                             // cos/sin table
// attention operand planes (fp16)
__device__ __half g_qp[(size_t)NROWS * ND];                   // rotated, scaled Q
__device__ __half g_kh16[(size_t)NROWS * ND];                 // rotated K hi
__device__ __half g_kl16[(size_t)NROWS * ND];                 // rotated K lo
__device__ __half g_vth16[(size_t)NROWS * ND];                // V^T fp16 [b][h][d][s]

__device__ __forceinline__ uint32_t smem_u32(const void* p) {
    uint32_t a;
    asm("{ .reg .u64 t; cvta.to.shared.u64 t, %1; cvt.u32.u64 %0, t; }" : "=r"(a) : "l"(p));
    return a;
}

__device__ __forceinline__ void mma_f16(float c[4], const uint32_t a[4], const uint32_t b[2]) {
    asm volatile(
        "mma.sync.aligned.m16n8k16.row.col.f32.f16.f16.f32 "
        "{%0,%1,%2,%3}, {%4,%5,%6,%7}, {%8,%9}, {%0,%1,%2,%3};"
        : "+f"(c[0]), "+f"(c[1]), "+f"(c[2]), "+f"(c[3])
        : "r"(a[0]), "r"(a[1]), "r"(a[2]), "r"(a[3]), "r"(b[0]), "r"(b[1]));
}

#define LDSM4(r, addr) \
    asm volatile("ldmatrix.sync.aligned.m8n8.x4.shared.b16 {%0,%1,%2,%3}, [%4];" \
                 : "=r"((r)[0]), "=r"((r)[1]), "=r"((r)[2]), "=r"((r)[3]) : "r"(addr))

#define CP16(dst, src) \
    asm volatile("cp.async.cg.shared.global [%0], [%1], 16;" :: "r"(dst), "l"(src))
#define CP_COMMIT() asm volatile("cp.async.commit_group;")
#define CP_WAIT4()  asm volatile("cp.async.wait_group 4;")
#define CP_WAIT3()  asm volatile("cp.async.wait_group 3;")
#define CP_WAIT2()  asm volatile("cp.async.wait_group 2;")
#define CP_WAIT1()  asm volatile("cp.async.wait_group 1;")
#define CP_WAIT0()  asm volatile("cp.async.wait_group 0;")

// ---------------------------------------------------------------------------
// prep_x_rot: blocks [0,6144): x fp32->fp16; blocks [6144,6400): rot table.
// ---------------------------------------------------------------------------
__global__ void prep_x_rot_kernel(const float* __restrict__ x, __half* __restrict__ o,
                                  const int* __restrict__ layer_p, float2* __restrict__ rot)
{
    int blk = blockIdx.x;
    if (blk < 6144) {
        int i = blk * 256 + threadIdx.x;
        float2 v = ((const float2*)x)[i];
        ((__half2*)o)[i] = __floats2half2_rn(v.x, v.y);
    } else {
        int idx = (blk - 6144) * 256 + threadIdx.x;
        int i = idx & 31;
        int s = idx >> 5;
        bool is_global = (layer_p[0] % 3) == 0;
        float theta = is_global ? 160000.f : 10000.f;
        float freq  = powf(theta, -(float)(2 * i) / 64.f);
        float sn, cs;
        sincosf((float)s * freq, &sn, &cs);
        rot[idx] = make_float2(cs, sn);
    }
}

// ---------------------------------------------------------------------------
// prep_w: both weight transpose-converts in one launch (z: 0=Wqkv, 1=Wout).
// ---------------------------------------------------------------------------
__global__ void prep_w_kernel(const float* __restrict__ Wq, const float* __restrict__ Wo,
                              __half* __restrict__ oq, __half* __restrict__ oo)
{
    const float* W;
    __half* o;
    int N;
    if (blockIdx.z == 0) { W = Wq; o = oq; N = NQKV; }
    else {
        if (blockIdx.x >= ND / 32) return;
        W = Wo; o = oo; N = ND;
    }
    const int K = ND;
    __shared__ float t[32][33];
    const int n0 = blockIdx.x * 32, k0 = blockIdx.y * 32;
#pragma unroll
    for (int i = 0; i < 4; i++) {
        int k = threadIdx.y + i * 8;
        t[k][threadIdx.x] = W[(size_t)(k0 + k) * N + n0 + threadIdx.x];
    }
    __syncthreads();
#pragma unroll
    for (int i = 0; i < 4; i++) {
        int n = threadIdx.y + i * 8;
        o[(size_t)(n0 + n) * K + k0 + threadIdx.x] = __float2half_rn(t[threadIdx.x][n]);
    }
}

// ---------------------------------------------------------------------------
// Shared GEMM mainloop: 128x128, BK=32, 6-stage cp.async, 2 CTAs/SM.
// ---------------------------------------------------------------------------
#define PL 8192
#define STG (2 * PL)
#define NSTAGE 6

#define GEMM_MAINLOOP_BODY                                                     \
    float acc[4][4][4];                                                        \
    _Pragma("unroll")                                                          \
    for (int i = 0; i < 4; i++)                                                \
        _Pragma("unroll")                                                      \
        for (int j = 0; j < 4; j++)                                            \
            _Pragma("unroll")                                                  \
            for (int q = 0; q < 4; q++) acc[i][j][q] = 0.f;                    \
    const uint32_t sb = smem_u32(sm);                                          \
    const int rA   = m0w + (l & 15);                                           \
    const uint32_t selA = (uint32_t)((rA >> 1) & 3);                           \
    const uint32_t c0A  = (uint32_t)(l >> 4);                                  \
    const uint32_t aRel0 = (uint32_t)rA * 64 + ((c0A ^ selA) << 4);            \
    const uint32_t aRel1 = (uint32_t)rA * 64 + (((c0A + 2) ^ selA) << 4);      \
    const int bg = l >> 3;                                                     \
    const int rB = n0w + (bg >> 1) * 8 + (l & 7);                              \
    const uint32_t selB = (uint32_t)((rB >> 1) & 3);                           \
    const uint32_t c0B  = (uint32_t)(bg & 1);                                  \
    const uint32_t bRel0 = PL + (uint32_t)rB * 64 + ((c0B ^ selB) << 4);       \
    const uint32_t bRel1 = PL + (uint32_t)rB * 64 + (((c0B + 2) ^ selB) << 4); \
    const int fr = tid >> 1;                                                   \
    const int fc = (tid & 1) * 2;                                              \
    const uint32_t fsel = (uint32_t)((fr >> 1) & 3);                           \
    const uint32_t d0 = (uint32_t)fr * 64 + (((uint32_t)fc ^ fsel) << 4);      \
    const uint32_t d1 = (uint32_t)fr * 64 + ((((uint32_t)fc + 1) ^ fsel) << 4);\
    const __half* gA = A + (size_t)(row0 + fr) * K + fc * 8;                   \
    const __half* gB = B + (size_t)(col0 + fr) * K + fc * 8;                   \
    const int nch = K >> 5;                                                    \
    auto issue = [&](int kc, int s) {                                          \
        const int ke = kc << 5;                                                \
        const uint32_t st = sb + (uint32_t)s * STG;                            \
        CP16(st + d0,      gA + ke);                                           \
        CP16(st + d1,      gA + ke + 8);                                       \
        CP16(st + PL + d0, gB + ke);                                           \
        CP16(st + PL + d1, gB + ke + 8);                                       \
        CP_COMMIT();                                                           \
    };                                                                         \
    _Pragma("unroll")                                                          \
    for (int p = 0; p < 5; p++)                                                \
        if (p < nch) issue(p, p);                                              \
    int s = 0;                                                                 \
    for (int kc = 0; kc < nch; kc++) {                                         \
        int after = nch - 1 - kc;                                              \
        if (after > 4) after = 4;                                              \
        switch (after) {                                                       \
            case 4: CP_WAIT4(); break;                                         \
            case 3: CP_WAIT3(); break;                                         \
            case 2: CP_WAIT2(); break;                                         \
            case 1: CP_WAIT1(); break;                                         \
            default: CP_WAIT0(); break;                                        \
        }                                                                      \
        __syncthreads();                                                       \
        if (kc + 5 < nch) {                                                    \
            int s5 = s + 5; if (s5 >= NSTAGE) s5 -= NSTAGE;                    \
            issue(kc + 5, s5);                                                 \
        }                                                                      \
        const uint32_t stb = sb + (uint32_t)s * STG;                           \
        _Pragma("unroll")                                                      \
        for (int ks = 0; ks < 2; ks++) {                                       \
            const uint32_t aR = ks ? aRel1 : aRel0;                            \
            const uint32_t bR = ks ? bRel1 : bRel0;                            \
            uint32_t a4[4][4];                                                 \
            _Pragma("unroll")                                                  \
            for (int mt = 0; mt < 4; mt++)                                     \
                LDSM4(a4[mt], stb + aR + mt * 1024);                           \
            uint32_t b4[4][2];                                                 \
            _Pragma("unroll")                                                  \
            for (int jp = 0; jp < 2; jp++) {                                   \
                uint32_t r[4];                                                 \
                LDSM4(r, stb + bR + jp * 1024);                                \
                b4[2 * jp][0] = r[0]; b4[2 * jp][1] = r[1];                    \
                b4[2 * jp + 1][0] = r[2]; b4[2 * jp + 1][1] = r[3];            \
            }                                                                  \
            _Pragma("unroll")                                                  \
            for (int mt = 0; mt < 4; mt++)                                     \
                _Pragma("unroll")                                              \
                for (int nt = 0; nt < 4; nt++)                                 \
                    mma_f16(acc[mt][nt], a4[mt], b4[nt]);                      \
        }                                                                      \
        if (++s >= NSTAGE) s = 0;                                              \
    }

// ---------------------------------------------------------------------------
// Generic fp16 GEMM + bias -> fp32 C (out-projection).
// ---------------------------------------------------------------------------
__global__ __launch_bounds__(256, 2)
void gemm_mma_kernel(const __half* __restrict__ A, const __half* __restrict__ B,
                     const float* __restrict__ bias, float* __restrict__ C,
                     int M, int N, int K)
{
    extern __shared__ __align__(16) char sm[];
    const int tid = threadIdx.x;
    const int w   = tid >> 5;
    const int l   = tid & 31;
    const int row0 = blockIdx.y * 128;
    const int col0 = blockIdx.x * 128;
    const int m0w = (w >> 2) * 64;
    const int n0w = (w & 3) * 32;

    GEMM_MAINLOOP_BODY

    float2 bb[4];
#pragma unroll
    for (int nt = 0; nt < 4; nt++) {
        int cg = col0 + n0w + 8 * nt + 2 * (l & 3);
        bb[nt] = make_float2(bias[cg], bias[cg + 1]);
    }
#pragma unroll
    for (int mt = 0; mt < 4; mt++) {
        int rg = row0 + m0w + 16 * mt + (l >> 2);
#pragma unroll
        for (int nt = 0; nt < 4; nt++) {
            int cg = col0 + n0w + 8 * nt + 2 * (l & 3);
            *(float2*)&C[(size_t)rg * N + cg] =
                make_float2(acc[mt][nt][0] + bb[nt].x, acc[mt][nt][1] + bb[nt].y);
            *(float2*)&C[(size_t)(rg + 8) * N + cg] =
                make_float2(acc[mt][nt][2] + bb[nt].x, acc[mt][nt][3] + bb[nt].y);
        }
    }
}

// ---------------------------------------------------------------------------
// QKV GEMM, fully fused epilogue:
//   Q tiles: bias + RoPE + 1/8 scale -> fp16 plane qp
//   K tiles: bias + RoPE -> fp16 hi/lo planes
//   V tiles: bias -> fp16, smem transpose -> vth [b][h][d][s]
// ---------------------------------------------------------------------------
__global__ __launch_bounds__(256, 2)
void gemm_qkv_kernel(const __half* __restrict__ A, const __half* __restrict__ B,
                     const float* __restrict__ bias,
                     __half* __restrict__ qp, __half* __restrict__ khp,
                     __half* __restrict__ klp, __half* __restrict__ vth,
                     const float2* __restrict__ rot,
                     int M, int N, int K)
{
    extern __shared__ __align__(16) char sm[];
    const int tid = threadIdx.x;
    const int w   = tid >> 5;
    const int l   = tid & 31;
    const int row0 = blockIdx.y * 128;
    const int col0 = blockIdx.x * 128;
    const int m0w = (w >> 2) * 64;
    const int n0w = (w & 3) * 32;

    GEMM_MAINLOOP_BODY

    float2 bb[4];
#pragma unroll
    for (int nt = 0; nt < 4; nt++) {
        int cg = col0 + n0w + 8 * nt + 2 * (l & 3);
        bb[nt] = make_float2(bias[cg], bias[cg + 1]);
    }

    if (col0 < 2 * ND) {
        const bool isQ = (col0 < ND);
        const int cbase = isQ ? 0 : ND;
#pragma unroll
        for (int mt = 0; mt < 4; mt++) {
            int rg = row0 + m0w + 16 * mt + (l >> 2);
#pragma unroll
            for (int hf = 0; hf < 2; hf++) {
                int r  = rg + 8 * hf;
                int s0 = r & (NS - 1);
#pragma unroll
                for (int nt = 0; nt < 4; nt++) {
                    int cg = col0 + n0w + 8 * nt + 2 * (l & 3);
                    float v0 = acc[mt][nt][2 * hf + 0] + bb[nt].x;
                    float v1 = acc[mt][nt][2 * hf + 1] + bb[nt].y;
                    int i = (cg & 63) >> 1;
                    float2 cs = rot[s0 * 32 + i];
                    float re = v0 * cs.x - v1 * cs.y;
                    float ro = v1 * cs.x + v0 * cs.y;
                    size_t o = (size_t)r * ND + (cg - cbase);
                    if (isQ) {
                        *(__half2*)&qp[o] = __floats2half2_rn(re * 0.125f, ro * 0.125f);
                    } else {
                        __half he = __float2half_rn(re);
                        __half ho = __float2half_rn(ro);
                        *(__half2*)&khp[o] = __halves2half2(he, ho);
                        *(__half2*)&klp[o] = __floats2half2_rn(
                            re - __half2float(he), ro - __half2float(ho));
                    }
                }
            }
        }
    } else {
        // V: bias + fp16, smem transpose, write [b][h][d][s] plane
        __half* smT = (__half*)sm;        // [128 cols][136 rows-stride]
        __syncthreads();                   // mainloop smem consumers done
#pragma unroll
        for (int mt = 0; mt < 4; mt++) {
#pragma unroll
            for (int hf = 0; hf < 2; hf++) {
                int rloc = m0w + 16 * mt + (l >> 2) + 8 * hf;
#pragma unroll
                for (int nt = 0; nt < 4; nt++) {
                    int cloc = n0w + 8 * nt + 2 * (l & 3);
                    smT[(cloc) * 136 + rloc] =
                        __float2half_rn(acc[mt][nt][2 * hf + 0] + bb[nt].x);
                    smT[(cloc + 1) * 136 + rloc] =
                        __float2half_rn(acc[mt][nt][2 * hf + 1] + bb[nt].y);
                }
            }
        }
        __syncthreads();
        int c  = tid >> 1;
        int hf = tid & 1;
        int d  = col0 - 2 * ND + c;
        int hh = d >> 6, dd = d & 63;
        int b  = row0 >> 11;
        int s0 = row0 & (NS - 1);
        size_t base = ((size_t)(b * NH + hh) * NHD + dd) * NS + s0 + hf * 64;
#pragma unroll
        for (int j = 0; j < 64; j += 8) {
            uint4 v = *(uint4*)&smT[c * 136 + hf * 64 + j];
            *(uint4*)&vth[base + j] = v;
        }
    }
}

// ---------------------------------------------------------------------------
// Tensor-core flash attention: S fp16 2-pass, PV fp16 single-pass.
// Double-buffered K/V tiles (2 stages), dedicated P plane.
// planes: 0 Qp, 1 P, then stage s in {0,1}: (2+3s) Kh, (3+3s) Kl, (4+3s) Vth
// ---------------------------------------------------------------------------
#define TSROW 144
#define TPL (64 * TSROW)   // 9216 B per plane

__global__ __launch_bounds__(256, 2)
void attn_mma_kernel(const __half* __restrict__ qp_g,
                     const __half* __restrict__ kh_g, const __half* __restrict__ kl_g,
                     const __half* __restrict__ vth_g,
                     __half* __restrict__ ao,
                     const int* __restrict__ layer_p)
{
    extern __shared__ __align__(16) char sm[];
    char* Pp = sm + TPL;                      // dedicated P plane
    float* Sbuf  = (float*)(sm + 8 * TPL);    // [64][68]
    float* row_m = Sbuf + 64 * 68;
    float* row_l = row_m + 64;
    float* row_s = row_l + 64;

    const int tid = threadIdx.x;
    const int w   = tid >> 5;
    const int l   = tid & 31;
    const int blk = blockIdx.x;
    const int qt  = blk & 31;
    const int hh  = (blk >> 5) % NH;
    const int b   = blk / (32 * NH);
    const bool is_global = (layer_p[0] % 3) == 0;
    const int q0 = qt * 64;

    const int mrow = (w & 3) * 16;
    const int ncol = (w >> 2) * 32;
    const uint32_t sb = smem_u32(sm);
    const uint32_t aRel = (uint32_t)(mrow + (l & 15)) * TSROW + (uint32_t)((l >> 4) * 16);
    const int bg = l >> 3;
    const uint32_t bRelB = (uint32_t)(ncol + (bg >> 1) * 8 + (l & 7)) * TSROW
                         + (uint32_t)((bg & 1) * 16);   // plane-relative

    const int fr  = tid >> 2;
    const int fs  = (tid & 3) * 2;
    const uint32_t fRel = (uint32_t)fr * TSROW + (uint32_t)fs * 16;

    const int kt0 = is_global ? 0 : max(0, qt - 2);
    const int kt1 = is_global ? 31 : min(31, qt + 2);

    // issue K/V tile loads for a kt into a stage
    auto issue_kv = [&](int kt, int st) {
        const uint32_t so = sb + (uint32_t)(2 + 3 * st) * TPL;
        const __half* gkh = kh_g + (size_t)(b * NS + kt * 64 + fr) * ND + hh * NHD + fs * 8;
        const __half* gkl = kl_g + (size_t)(b * NS + kt * 64 + fr) * ND + hh * NHD + fs * 8;
        const __half* gvh = vth_g + ((size_t)(b * NH + hh) * NHD + fr) * NS + kt * 64 + fs * 8;
        CP16(so + fRel,                gkh);
        CP16(so + fRel + 16,           gkh + 8);
        CP16(so + TPL + fRel,          gkl);
        CP16(so + TPL + fRel + 16,     gkl + 8);
        CP16(so + 2 * TPL + fRel,      gvh);
        CP16(so + 2 * TPL + fRel + 16, gvh + 8);
        CP_COMMIT();
    };

    // Q plane + first K/V stage
    {
        const __half* gq = qp_g + (size_t)(b * NS + q0 + fr) * ND + hh * NHD + fs * 8;
        CP16(sb + fRel,      gq);
        CP16(sb + fRel + 16, gq + 8);
        CP_COMMIT();
        issue_kv(kt0, 0);
    }
    if (tid < 64) { row_m[tid] = NEG_BIG; row_l[tid] = 0.f; }

    float oacc[4][4];
#pragma unroll
    for (int i = 0; i < 4; i++)
#pragma unroll
        for (int j = 0; j < 4; j++) oacc[i][j] = 0.f;

    for (int kt = kt0; kt <= kt1; kt++) {
        const int st = (kt - kt0) & 1;
        const uint32_t so = sb + (uint32_t)(2 + 3 * st) * TPL;

        CP_WAIT0();          // current stage resident
        __syncthreads();     // visibility + prior-iter PV reads of other stage done
        if (kt + 1 <= kt1) issue_kv(kt + 1, st ^ 1);   // overlaps all compute below

        // ---- S = Q @ (Kh + Kl)^T  (fp16 2-pass) ----
        float sa[4][4];
#pragma unroll
        for (int i = 0; i < 4; i++)
#pragma unroll
            for (int j = 0; j < 4; j++) sa[i][j] = 0.f;
#pragma unroll
        for (int ks = 0; ks < 4; ks++) {
            const uint32_t kso = (uint32_t)(ks * 32);
            uint32_t q4[4];
            LDSM4(q4, sb + aRel + kso);
            uint32_t bh[4][2], bl[4][2];
#pragma unroll
            for (int jp = 0; jp < 2; jp++) {
                uint32_t r4[4];
                LDSM4(r4, so + bRelB + jp * (16 * TSROW) + kso);
                bh[2 * jp][0] = r4[0]; bh[2 * jp][1] = r4[1];
                bh[2 * jp + 1][0] = r4[2]; bh[2 * jp + 1][1] = r4[3];
                LDSM4(r4, so + TPL + bRelB + jp * (16 * TSROW) + kso);
                bl[2 * jp][0] = r4[0]; bl[2 * jp][1] = r4[1];
                bl[2 * jp + 1][0] = r4[2]; bl[2 * jp + 1][1] = r4[3];
            }
#pragma unroll
            for (int nt = 0; nt < 4; nt++) mma_f16(sa[nt], q4, bh[nt]);
#pragma unroll
            for (int nt = 0; nt < 4; nt++) mma_f16(sa[nt], q4, bl[nt]);
        }
        {
            int fr0 = mrow + (l >> 2);
#pragma unroll
            for (int nt = 0; nt < 4; nt++) {
                int col = ncol + 8 * nt + 2 * (l & 3);
                *(float2*)&Sbuf[fr0 * 68 + col]       = make_float2(sa[nt][0], sa[nt][1]);
                *(float2*)&Sbuf[(fr0 + 8) * 68 + col] = make_float2(sa[nt][2], sa[nt][3]);
            }
        }
        __syncthreads();

        // ---- banded mask + online softmax; emit P fp16 (dedicated plane) ----
        {
            int r  = tid >> 2;
            int qd = tid & 3;
            float* Pr = &Sbuf[r * 68 + qd * 16];
            if (!is_global) {
#pragma unroll
                for (int c = 0; c < 16; c++) {
                    int dlt = (q0 + r) - (kt * 64 + qd * 16 + c);
                    if (dlt < 0) dlt = -dlt;
                    if (dlt > 128) Pr[c] = NEG_BIG;
                }
            }
            float mloc = NEG_BIG;
#pragma unroll
            for (int c = 0; c < 16; c++) mloc = fmaxf(mloc, Pr[c]);
            mloc = fmaxf(mloc, __shfl_xor_sync(0xffffffffu, mloc, 1));
            mloc = fmaxf(mloc, __shfl_xor_sync(0xffffffffu, mloc, 2));
            float m_old = row_m[r];
            float m_new = fmaxf(m_old, mloc);
            float ls = 0.f;
#pragma unroll
            for (int c = 0; c < 16; c += 2) {
                float e0 = __expf(Pr[c]     - m_new);
                float e1 = __expf(Pr[c + 1] - m_new);
                ls += e0 + e1;
                uint32_t off = (uint32_t)(r * TSROW + (qd * 16 + c) * 2);
                *(__half2*)(Pp + off) = __floats2half2_rn(e0, e1);
            }
            ls += __shfl_xor_sync(0xffffffffu, ls, 1);
            ls += __shfl_xor_sync(0xffffffffu, ls, 2);
            if (qd == 0) {
                float fac = __expf(m_old - m_new);
                row_s[r] = fac;
                row_m[r] = m_new;
                row_l[r] = row_l[r] * fac + ls;
            }
        }
        __syncthreads();

        // ---- rescale O; O += P @ Vh  (fp16 single-pass) ----
        {
            float f0 = row_s[mrow + (l >> 2)];
            float f1 = row_s[mrow + 8 + (l >> 2)];
#pragma unroll
            for (int nt = 0; nt < 4; nt++) {
                oacc[nt][0] *= f0; oacc[nt][1] *= f0;
                oacc[nt][2] *= f1; oacc[nt][3] *= f1;
            }
#pragma unroll
            for (int ks = 0; ks < 4; ks++) {
                const uint32_t kso = (uint32_t)(ks * 32);
                uint32_t p4[4];
                LDSM4(p4, sb + TPL + aRel + kso);
                uint32_t vh[4][2];
#pragma unroll
                for (int jp = 0; jp < 2; jp++) {
                    uint32_t r4[4];
                    LDSM4(r4, so + 2 * TPL + bRelB + jp * (16 * TSROW) + kso);
                    vh[2 * jp][0] = r4[0]; vh[2 * jp][1] = r4[1];
                    vh[2 * jp + 1][0] = r4[2]; vh[2 * jp + 1][1] = r4[3];
                }
#pragma unroll
                for (int nt = 0; nt < 4; nt++) mma_f16(oacc[nt], p4, vh[nt]);
            }
        }
    }

    // normalize + write single fp16 plane
    {
        float i0 = 1.f / row_l[mrow + (l >> 2)];
        float i1 = 1.f / row_l[mrow + 8 + (l >> 2)];
        size_t r0 = (size_t)(b * NS + q0 + mrow + (l >> 2)) * ND;
        size_t r1 = r0 + 8 * (size_t)ND;
#pragma unroll
        for (int nt = 0; nt < 4; nt++) {
            int col = hh * NHD + ncol + 8 * nt + 2 * (l & 3);
            *(__half2*)&ao[r0 + col] = __floats2half2_rn(oacc[nt][0] * i0, oacc[nt][1] * i0);
            *(__half2*)&ao[r1 + col] = __floats2half2_rn(oacc[nt][2] * i1, oacc[nt][3] * i1);
        }
    }
}

// ---------------------------------------------------------------------------
extern "C" void kernel_launch(void* const* d_in, const int* in_sizes, int n_in,
                              void* d_out, int out_size)
{
    const float* x     = (const float*)d_in[0];
    const float* Wqkv  = (const float*)d_in[1];
    const float* bqkv  = (const float*)d_in[2];
    const float* Wout  = (const float*)d_in[3];
    const float* bout  = (const float*)d_in[4];
    const int*   layer = (const int*)d_in[5];
    float* out = (float*)d_out;

    float2* rot;
    __half *x16, *a16, *wq, *wo, *qp, *khp, *klp, *vth;
    cudaGetSymbolAddress((void**)&rot, g_rot);
    cudaGetSymbolAddress((void**)&x16, g_x16);
    cudaGetSymbolAddress((void**)&a16, g_a16);
    cudaGetSymbolAddress((void**)&wq, g_wq16);
    cudaGetSymbolAddress((void**)&wo, g_wo16);
    cudaGetSymbolAddress((void**)&qp, g_qp);
    cudaGetSymbolAddress((void**)&khp, g_kh16);
    cudaGetSymbolAddress((void**)&klp, g_kl16);
    cudaGetSymbolAddress((void**)&vth, g_vth16);

    const int gemm_smem = NSTAGE * STG;   // 98304 B
    cudaFuncSetAttribute(gemm_mma_kernel, cudaFuncAttributeMaxDynamicSharedMemorySize, gemm_smem);
    cudaFuncSetAttribute(gemm_qkv_kernel, cudaFuncAttributeMaxDynamicSharedMemorySize, gemm_smem);
    const int attn_smem = 8 * TPL + 64 * 68 * 4 + 3 * 64 * 4;   // 91904 B
    cudaFuncSetAttribute(attn_mma_kernel, cudaFuncAttributeMaxDynamicSharedMemorySize, attn_smem);

    // 0) prep: x->fp16 + rot table; both weight transposes
    prep_x_rot_kernel<<<6400, 256>>>(x, x16, layer, rot);
    prep_w_kernel<<<dim3(NQKV / 32, ND / 32, 2), dim3(32, 8)>>>(Wqkv, Wout, wq, wo);

    // 1) qkv GEMM, fully fused epilogue (Q/K rope planes, V transposed plane)
    gemm_qkv_kernel<<<dim3(NQKV / 128, NROWS / 128), 256, gemm_smem>>>(
        x16, wq, bqkv, qp, khp, klp, vth, rot, NROWS, NQKV, ND);
    // 2) tensor-core banded attention (double-buffered K/V)
    attn_mma_kernel<<<NB * NH * 32, 256, attn_smem>>>(qp, khp, klp, vth, a16, layer);
    // 3) out = attn @ Wout + bout
    gemm_mma_kernel<<<dim3(ND / 128, NROWS / 128), 256, gemm_smem>>>(
        a16, wo, bout, out, NROWS, ND, ND);
}

// round 17
// speedup vs baseline: 2.8780x; 1.0558x over previous
#include <cuda_runtime.h>
#include <cuda_fp16.h>
#include <math.h>
#include <stdint.h>

#define NB 2
#define NS 2048
#define ND 768
#define NH 12
#define NHD 64
#define NQKV 2304
#define NROWS 4096   // NB*NS

#define NEG_BIG (-1e30f)

// ---------------- scratch (device globals; allocation-free) -----------------
__device__ __half g_x16[(size_t)NROWS * ND];                  // x fp16 (A of GEMM1)
__device__ __half g_a16[(size_t)NROWS * ND];                  // attn out fp16 (A of GEMM2)
__device__ __half g_wq16[(size_t)NQKV * ND];                  // Wqkv^T fp16 [N][K]
__device__ __half g_wo16[(size_t)ND * ND];                    // Wout^T fp16 [N][K]
__device__ float2 g_rot[NS * 32];                             // cos/sin table
// attention operand planes (fp16)
__device__ __half g_qp[(size_t)NROWS * ND];                   // rotated, scaled Q
__device__ __half g_kh16[(size_t)NROWS * ND];                 // rotated K hi
__device__ __half g_kl16[(size_t)NROWS * ND];                 // rotated K lo
__device__ __half g_vth16[(size_t)NROWS * ND];                // V^T fp16 [b][h][d][s]

__device__ __forceinline__ uint32_t smem_u32(const void* p) {
    uint32_t a;
    asm("{ .reg .u64 t; cvta.to.shared.u64 t, %1; cvt.u32.u64 %0, t; }" : "=r"(a) : "l"(p));
    return a;
}

__device__ __forceinline__ void mma_f16(float c[4], const uint32_t a[4], const uint32_t b[2]) {
    asm volatile(
        "mma.sync.aligned.m16n8k16.row.col.f32.f16.f16.f32 "
        "{%0,%1,%2,%3}, {%4,%5,%6,%7}, {%8,%9}, {%0,%1,%2,%3};"
        : "+f"(c[0]), "+f"(c[1]), "+f"(c[2]), "+f"(c[3])
        : "r"(a[0]), "r"(a[1]), "r"(a[2]), "r"(a[3]), "r"(b[0]), "r"(b[1]));
}

#define LDSM4(r, addr) \
    asm volatile("ldmatrix.sync.aligned.m8n8.x4.shared.b16 {%0,%1,%2,%3}, [%4];" \
                 : "=r"((r)[0]), "=r"((r)[1]), "=r"((r)[2]), "=r"((r)[3]) : "r"(addr))

#define CP16(dst, src) \
    asm volatile("cp.async.cg.shared.global [%0], [%1], 16;" :: "r"(dst), "l"(src))
#define CP_COMMIT() asm volatile("cp.async.commit_group;")
#define CP_WAIT4()  asm volatile("cp.async.wait_group 4;")
#define CP_WAIT3()  asm volatile("cp.async.wait_group 3;")
#define CP_WAIT2()  asm volatile("cp.async.wait_group 2;")
#define CP_WAIT1()  asm volatile("cp.async.wait_group 1;")
#define CP_WAIT0()  asm volatile("cp.async.wait_group 0;")

// ---------------------------------------------------------------------------
// prep_x_rot: blocks [0,6144): x fp32->fp16; blocks [6144,6400): rot table.
// ---------------------------------------------------------------------------
__global__ void prep_x_rot_kernel(const float* __restrict__ x, __half* __restrict__ o,
                                  const int* __restrict__ layer_p, float2* __restrict__ rot)
{
    int blk = blockIdx.x;
    if (blk < 6144) {
        int i = blk * 256 + threadIdx.x;
        float2 v = ((const float2*)x)[i];
        ((__half2*)o)[i] = __floats2half2_rn(v.x, v.y);
    } else {
        int idx = (blk - 6144) * 256 + threadIdx.x;
        int i = idx & 31;
        int s = idx >> 5;
        bool is_global = (layer_p[0] % 3) == 0;
        float theta = is_global ? 160000.f : 10000.f;
        float freq  = powf(theta, -(float)(2 * i) / 64.f);
        float sn, cs;
        sincosf((float)s * freq, &sn, &cs);
        rot[idx] = make_float2(cs, sn);
    }
}

// ---------------------------------------------------------------------------
// prep_w: both weight transpose-converts in one launch (z: 0=Wqkv, 1=Wout).
// ---------------------------------------------------------------------------
__global__ void prep_w_kernel(const float* __restrict__ Wq, const float* __restrict__ Wo,
                              __half* __restrict__ oq, __half* __restrict__ oo)
{
    const float* W;
    __half* o;
    int N;
    if (blockIdx.z == 0) { W = Wq; o = oq; N = NQKV; }
    else {
        if (blockIdx.x >= ND / 32) return;
        W = Wo; o = oo; N = ND;
    }
    const int K = ND;
    __shared__ float t[32][33];
    const int n0 = blockIdx.x * 32, k0 = blockIdx.y * 32;
#pragma unroll
    for (int i = 0; i < 4; i++) {
        int k = threadIdx.y + i * 8;
        t[k][threadIdx.x] = W[(size_t)(k0 + k) * N + n0 + threadIdx.x];
    }
    __syncthreads();
#pragma unroll
    for (int i = 0; i < 4; i++) {
        int n = threadIdx.y + i * 8;
        o[(size_t)(n0 + n) * K + k0 + threadIdx.x] = __float2half_rn(t[threadIdx.x][n]);
    }
}

// ---------------------------------------------------------------------------
// Shared GEMM mainloop: 128x128, BK=32, 6-stage cp.async, 2 CTAs/SM.
// ---------------------------------------------------------------------------
#define PL 8192
#define STG (2 * PL)
#define NSTAGE 6

#define GEMM_MAINLOOP_BODY                                                     \
    float acc[4][4][4];                                                        \
    _Pragma("unroll")                                                          \
    for (int i = 0; i < 4; i++)                                                \
        _Pragma("unroll")                                                      \
        for (int j = 0; j < 4; j++)                                            \
            _Pragma("unroll")                                                  \
            for (int q = 0; q < 4; q++) acc[i][j][q] = 0.f;                    \
    const uint32_t sb = smem_u32(sm);                                          \
    const int rA   = m0w + (l & 15);                                           \
    const uint32_t selA = (uint32_t)((rA >> 1) & 3);                           \
    const uint32_t c0A  = (uint32_t)(l >> 4);                                  \
    const uint32_t aRel0 = (uint32_t)rA * 64 + ((c0A ^ selA) << 4);            \
    const uint32_t aRel1 = (uint32_t)rA * 64 + (((c0A + 2) ^ selA) << 4);      \
    const int bg = l >> 3;                                                     \
    const int rB = n0w + (bg >> 1) * 8 + (l & 7);                              \
    const uint32_t selB = (uint32_t)((rB >> 1) & 3);                           \
    const uint32_t c0B  = (uint32_t)(bg & 1);                                  \
    const uint32_t bRel0 = PL + (uint32_t)rB * 64 + ((c0B ^ selB) << 4);       \
    const uint32_t bRel1 = PL + (uint32_t)rB * 64 + (((c0B + 2) ^ selB) << 4); \
    const int fr = tid >> 1;                                                   \
    const int fc = (tid & 1) * 2;                                              \
    const uint32_t fsel = (uint32_t)((fr >> 1) & 3);                           \
    const uint32_t d0 = (uint32_t)fr * 64 + (((uint32_t)fc ^ fsel) << 4);      \
    const uint32_t d1 = (uint32_t)fr * 64 + ((((uint32_t)fc + 1) ^ fsel) << 4);\
    const __half* gA = A + (size_t)(row0 + fr) * K + fc * 8;                   \
    const __half* gB = B + (size_t)(col0 + fr) * K + fc * 8;                   \
    const int nch = K >> 5;                                                    \
    auto issue = [&](int kc, int s) {                                          \
        const int ke = kc << 5;                                                \
        const uint32_t st = sb + (uint32_t)s * STG;                            \
        CP16(st + d0,      gA + ke);                                           \
        CP16(st + d1,      gA + ke + 8);                                       \
        CP16(st + PL + d0, gB + ke);                                           \
        CP16(st + PL + d1, gB + ke + 8);                                       \
        CP_COMMIT();                                                           \
    };                                                                         \
    _Pragma("unroll")                                                          \
    for (int p = 0; p < 5; p++)                                                \
        if (p < nch) issue(p, p);                                              \
    int s = 0;                                                                 \
    for (int kc = 0; kc < nch; kc++) {                                         \
        int after = nch - 1 - kc;                                              \
        if (after > 4) after = 4;                                              \
        switch (after) {                                                       \
            case 4: CP_WAIT4(); break;                                         \
            case 3: CP_WAIT3(); break;                                         \
            case 2: CP_WAIT2(); break;                                         \
            case 1: CP_WAIT1(); break;                                         \
            default: CP_WAIT0(); break;                                        \
        }                                                                      \
        __syncthreads();                                                       \
        if (kc + 5 < nch) {                                                    \
            int s5 = s + 5; if (s5 >= NSTAGE) s5 -= NSTAGE;                    \
            issue(kc + 5, s5);                                                 \
        }                                                                      \
        const uint32_t stb = sb + (uint32_t)s * STG;                           \
        _Pragma("unroll")                                                      \
        for (int ks = 0; ks < 2; ks++) {                                       \
            const uint32_t aR = ks ? aRel1 : aRel0;                            \
            const uint32_t bR = ks ? bRel1 : bRel0;                            \
            uint32_t a4[4][4];                                                 \
            _Pragma("unroll")                                                  \
            for (int mt = 0; mt < 4; mt++)                                     \
                LDSM4(a4[mt], stb + aR + mt * 1024);                           \
            uint32_t b4[4][2];                                                 \
            _Pragma("unroll")                                                  \
            for (int jp = 0; jp < 2; jp++) {                                   \
                uint32_t r[4];                                                 \
                LDSM4(r, stb + bR + jp * 1024);                                \
                b4[2 * jp][0] = r[0]; b4[2 * jp][1] = r[1];                    \
                b4[2 * jp + 1][0] = r[2]; b4[2 * jp + 1][1] = r[3];            \
            }                                                                  \
            _Pragma("unroll")                                                  \
            for (int mt = 0; mt < 4; mt++)                                     \
                _Pragma("unroll")                                              \
                for (int nt = 0; nt < 4; nt++)                                 \
                    mma_f16(acc[mt][nt], a4[mt], b4[nt]);                      \
        }                                                                      \
        if (++s >= NSTAGE) s = 0;                                              \
    }

// ---------------------------------------------------------------------------
// Generic fp16 GEMM + bias -> fp32 C (out-projection).
// ---------------------------------------------------------------------------
__global__ __launch_bounds__(256, 2)
void gemm_mma_kernel(const __half* __restrict__ A, const __half* __restrict__ B,
                     const float* __restrict__ bias, float* __restrict__ C,
                     int M, int N, int K)
{
    extern __shared__ __align__(16) char sm[];
    const int tid = threadIdx.x;
    const int w   = tid >> 5;
    const int l   = tid & 31;
    const int row0 = blockIdx.y * 128;
    const int col0 = blockIdx.x * 128;
    const int m0w = (w >> 2) * 64;
    const int n0w = (w & 3) * 32;

    GEMM_MAINLOOP_BODY

    float2 bb[4];
#pragma unroll
    for (int nt = 0; nt < 4; nt++) {
        int cg = col0 + n0w + 8 * nt + 2 * (l & 3);
        bb[nt] = make_float2(bias[cg], bias[cg + 1]);
    }
#pragma unroll
    for (int mt = 0; mt < 4; mt++) {
        int rg = row0 + m0w + 16 * mt + (l >> 2);
#pragma unroll
        for (int nt = 0; nt < 4; nt++) {
            int cg = col0 + n0w + 8 * nt + 2 * (l & 3);
            *(float2*)&C[(size_t)rg * N + cg] =
                make_float2(acc[mt][nt][0] + bb[nt].x, acc[mt][nt][1] + bb[nt].y);
            *(float2*)&C[(size_t)(rg + 8) * N + cg] =
                make_float2(acc[mt][nt][2] + bb[nt].x, acc[mt][nt][3] + bb[nt].y);
        }
    }
}

// ---------------------------------------------------------------------------
// QKV GEMM, fully fused epilogue:
//   Q tiles: bias + RoPE + 1/8 scale -> fp16 plane qp
//   K tiles: bias + RoPE -> fp16 hi/lo planes
//   V tiles: bias -> fp16, smem transpose -> vth [b][h][d][s]
// ---------------------------------------------------------------------------
__global__ __launch_bounds__(256, 2)
void gemm_qkv_kernel(const __half* __restrict__ A, const __half* __restrict__ B,
                     const float* __restrict__ bias,
                     __half* __restrict__ qp, __half* __restrict__ khp,
                     __half* __restrict__ klp, __half* __restrict__ vth,
                     const float2* __restrict__ rot,
                     int M, int N, int K)
{
    extern __shared__ __align__(16) char sm[];
    const int tid = threadIdx.x;
    const int w   = tid >> 5;
    const int l   = tid & 31;
    const int row0 = blockIdx.y * 128;
    const int col0 = blockIdx.x * 128;
    const int m0w = (w >> 2) * 64;
    const int n0w = (w & 3) * 32;

    GEMM_MAINLOOP_BODY

    float2 bb[4];
#pragma unroll
    for (int nt = 0; nt < 4; nt++) {
        int cg = col0 + n0w + 8 * nt + 2 * (l & 3);
        bb[nt] = make_float2(bias[cg], bias[cg + 1]);
    }

    if (col0 < 2 * ND) {
        const bool isQ = (col0 < ND);
        const int cbase = isQ ? 0 : ND;
#pragma unroll
        for (int mt = 0; mt < 4; mt++) {
            int rg = row0 + m0w + 16 * mt + (l >> 2);
#pragma unroll
            for (int hf = 0; hf < 2; hf++) {
                int r  = rg + 8 * hf;
                int s0 = r & (NS - 1);
#pragma unroll
                for (int nt = 0; nt < 4; nt++) {
                    int cg = col0 + n0w + 8 * nt + 2 * (l & 3);
                    float v0 = acc[mt][nt][2 * hf + 0] + bb[nt].x;
                    float v1 = acc[mt][nt][2 * hf + 1] + bb[nt].y;
                    int i = (cg & 63) >> 1;
                    float2 cs = rot[s0 * 32 + i];
                    float re = v0 * cs.x - v1 * cs.y;
                    float ro = v1 * cs.x + v0 * cs.y;
                    size_t o = (size_t)r * ND + (cg - cbase);
                    if (isQ) {
                        *(__half2*)&qp[o] = __floats2half2_rn(re * 0.125f, ro * 0.125f);
                    } else {
                        __half he = __float2half_rn(re);
                        __half ho = __float2half_rn(ro);
                        *(__half2*)&khp[o] = __halves2half2(he, ho);
                        *(__half2*)&klp[o] = __floats2half2_rn(
                            re - __half2float(he), ro - __half2float(ho));
                    }
                }
            }
        }
    } else {
        // V: bias + fp16, smem transpose, write [b][h][d][s] plane
        __half* smT = (__half*)sm;        // [128 cols][136 rows-stride]
        __syncthreads();                   // mainloop smem consumers done
#pragma unroll
        for (int mt = 0; mt < 4; mt++) {
#pragma unroll
            for (int hf = 0; hf < 2; hf++) {
                int rloc = m0w + 16 * mt + (l >> 2) + 8 * hf;
#pragma unroll
                for (int nt = 0; nt < 4; nt++) {
                    int cloc = n0w + 8 * nt + 2 * (l & 3);
                    smT[(cloc) * 136 + rloc] =
                        __float2half_rn(acc[mt][nt][2 * hf + 0] + bb[nt].x);
                    smT[(cloc + 1) * 136 + rloc] =
                        __float2half_rn(acc[mt][nt][2 * hf + 1] + bb[nt].y);
                }
            }
        }
        __syncthreads();
        int c  = tid >> 1;
        int hf = tid & 1;
        int d  = col0 - 2 * ND + c;
        int hh = d >> 6, dd = d & 63;
        int b  = row0 >> 11;
        int s0 = row0 & (NS - 1);
        size_t base = ((size_t)(b * NH + hh) * NHD + dd) * NS + s0 + hf * 64;
#pragma unroll
        for (int j = 0; j < 64; j += 8) {
            uint4 v = *(uint4*)&smT[c * 136 + hf * 64 + j];
            *(uint4*)&vth[base + j] = v;
        }
    }
}

// ---------------------------------------------------------------------------
// Tensor-core flash attention, fragment-resident softmax (FA2 style).
// planes: 0 Qp, 1 Kh, 2 Kl (-> partner P half), 3 Vth.
// Warp w: S/O rows mrow..mrow+15; S cols (keys) ncol..ncol+31; O cols (d)
// ncol..ncol+31 with full k=64 (2 k-steps from registers, 2 from P plane).
// ---------------------------------------------------------------------------
#define TSROW 144
#define TPL (64 * TSROW)   // 9216 B per plane

__global__ __launch_bounds__(256, 4)
void attn_mma_kernel(const __half* __restrict__ qp_g,
                     const __half* __restrict__ kh_g, const __half* __restrict__ kl_g,
                     const __half* __restrict__ vth_g,
                     __half* __restrict__ ao,
                     const int* __restrict__ layer_p)
{
    extern __shared__ __align__(16) char sm[];
    char* Pp = sm + 2 * TPL;                  // P overwrites Kl after S phase
    float* row_m  = (float*)(sm + 4 * TPL);   // [64]
    float* row_l  = row_m + 64;               // [64]
    float* red_mx = row_l + 64;               // [2][64]
    float* red_sm = red_mx + 128;             // [2][64]

    const int tid = threadIdx.x;
    const int w   = tid >> 5;
    const int l   = tid & 31;
    const int blk = blockIdx.x;
    const int qt  = blk & 31;
    const int hh  = (blk >> 5) % NH;
    const int b   = blk / (32 * NH);
    const bool is_global = (layer_p[0] % 3) == 0;
    const int q0 = qt * 64;

    const int mrow = (w & 3) * 16;
    const int ncol = (w >> 2) * 32;
    const int grp  = w >> 2;
    const int r0   = mrow + (l >> 2);
    const int r1   = r0 + 8;
    const uint32_t sb = smem_u32(sm);
    const uint32_t aRel = (uint32_t)(mrow + (l & 15)) * TSROW + (uint32_t)((l >> 4) * 16);
    const int bg = l >> 3;
    const uint32_t bRelB = (uint32_t)(ncol + (bg >> 1) * 8 + (l & 7)) * TSROW
                         + (uint32_t)((bg & 1) * 16);   // plane-relative

    const int fr  = tid >> 2;
    const int fs  = (tid & 3) * 2;
    const uint32_t fRel = (uint32_t)fr * TSROW + (uint32_t)fs * 16;

    // Q plane (load once)
    {
        const __half* gq = qp_g + (size_t)(b * NS + q0 + fr) * ND + hh * NHD + fs * 8;
        CP16(sb + fRel,      gq);
        CP16(sb + fRel + 16, gq + 8);
        CP_COMMIT();
    }
    if (tid < 64) { row_m[tid] = NEG_BIG; row_l[tid] = 0.f; }

    float oacc[4][4];
#pragma unroll
    for (int i = 0; i < 4; i++)
#pragma unroll
        for (int j = 0; j < 4; j++) oacc[i][j] = 0.f;

    const int kt0 = is_global ? 0 : max(0, qt - 2);
    const int kt1 = is_global ? 31 : min(31, qt + 2);
    const int own0 = ncol >> 4;   // warp's first PV k-step held in registers

    for (int kt = kt0; kt <= kt1; kt++) {
        __syncthreads();   // prior PV reads of Pp/V done; init done (iter 0)
        {
            const __half* gkh = kh_g + (size_t)(b * NS + kt * 64 + fr) * ND + hh * NHD + fs * 8;
            const __half* gkl = kl_g + (size_t)(b * NS + kt * 64 + fr) * ND + hh * NHD + fs * 8;
            const __half* gvh = vth_g + ((size_t)(b * NH + hh) * NHD + fr) * NS + kt * 64 + fs * 8;
            CP16(sb + 1 * TPL + fRel,      gkh);
            CP16(sb + 1 * TPL + fRel + 16, gkh + 8);
            CP16(sb + 2 * TPL + fRel,      gkl);
            CP16(sb + 2 * TPL + fRel + 16, gkl + 8);
            CP16(sb + 3 * TPL + fRel,      gvh);
            CP16(sb + 3 * TPL + fRel + 16, gvh + 8);
            CP_COMMIT();
            CP_WAIT0();
        }
        __syncthreads();

        // ---- S = Q @ (Kh + Kl)^T  (fp16 2-pass), fragments only ----
        float sa[4][4];
#pragma unroll
        for (int i = 0; i < 4; i++)
#pragma unroll
            for (int j = 0; j < 4; j++) sa[i][j] = 0.f;
#pragma unroll
        for (int ks = 0; ks < 4; ks++) {
            const uint32_t kso = (uint32_t)(ks * 32);
            uint32_t q4[4];
            LDSM4(q4, sb + aRel + kso);
            uint32_t bh[4][2], bl[4][2];
#pragma unroll
            for (int jp = 0; jp < 2; jp++) {
                uint32_t r4[4];
                LDSM4(r4, sb + 1 * TPL + bRelB + jp * (16 * TSROW) + kso);
                bh[2 * jp][0] = r4[0]; bh[2 * jp][1] = r4[1];
                bh[2 * jp + 1][0] = r4[2]; bh[2 * jp + 1][1] = r4[3];
                LDSM4(r4, sb + 2 * TPL + bRelB + jp * (16 * TSROW) + kso);
                bl[2 * jp][0] = r4[0]; bl[2 * jp][1] = r4[1];
                bl[2 * jp + 1][0] = r4[2]; bl[2 * jp + 1][1] = r4[3];
            }
#pragma unroll
            for (int nt = 0; nt < 4; nt++) mma_f16(sa[nt], q4, bh[nt]);
#pragma unroll
            for (int nt = 0; nt < 4; nt++) mma_f16(sa[nt], q4, bl[nt]);
        }

        // ---- in-register band mask ----
        if (!is_global) {
#pragma unroll
            for (int nt = 0; nt < 4; nt++) {
                int kc = kt * 64 + ncol + 8 * nt + 2 * (l & 3);
#pragma unroll
                for (int jj = 0; jj < 2; jj++) {
                    int d0a = (q0 + r0) - (kc + jj); if (d0a < 0) d0a = -d0a;
                    int d1a = (q0 + r1) - (kc + jj); if (d1a < 0) d1a = -d1a;
                    if (d0a > 128) sa[nt][jj] = NEG_BIG;
                    if (d1a > 128) sa[nt][2 + jj] = NEG_BIG;
                }
            }
        }

        // ---- row max: quad shuffle + cross-warp-pair exchange ----
        float pm0 = NEG_BIG, pm1 = NEG_BIG;
#pragma unroll
        for (int nt = 0; nt < 4; nt++) {
            pm0 = fmaxf(pm0, fmaxf(sa[nt][0], sa[nt][1]));
            pm1 = fmaxf(pm1, fmaxf(sa[nt][2], sa[nt][3]));
        }
        pm0 = fmaxf(pm0, __shfl_xor_sync(0xffffffffu, pm0, 1));
        pm0 = fmaxf(pm0, __shfl_xor_sync(0xffffffffu, pm0, 2));
        pm1 = fmaxf(pm1, __shfl_xor_sync(0xffffffffu, pm1, 1));
        pm1 = fmaxf(pm1, __shfl_xor_sync(0xffffffffu, pm1, 2));
        if ((l & 3) == 0) {
            red_mx[grp * 64 + r0] = pm0;
            red_mx[grp * 64 + r1] = pm1;
        }
        __syncthreads();

        // ---- exp on fragments, pack P fp16 (regs + partner half to plane) ----
        float mo0 = row_m[r0], mo1 = row_m[r1];
        float mn0 = fmaxf(mo0, fmaxf(red_mx[r0], red_mx[64 + r0]));
        float mn1 = fmaxf(mo1, fmaxf(red_mx[r1], red_mx[64 + r1]));
        float fac0 = __expf(mo0 - mn0), fac1 = __expf(mo1 - mn1);
        float ps0 = 0.f, ps1 = 0.f;
        uint32_t pa[2][4];
#pragma unroll
        for (int nt = 0; nt < 4; nt++) {
            float e0 = __expf(sa[nt][0] - mn0);
            float e1 = __expf(sa[nt][1] - mn0);
            float e2 = __expf(sa[nt][2] - mn1);
            float e3 = __expf(sa[nt][3] - mn1);
            ps0 += e0 + e1;
            ps1 += e2 + e3;
            __half2 h01 = __floats2half2_rn(e0, e1);
            __half2 h23 = __floats2half2_rn(e2, e3);
            int lk = nt >> 1;
            int sl = (nt & 1) * 2;
            pa[lk][sl]     = *(uint32_t*)&h01;
            pa[lk][sl + 1] = *(uint32_t*)&h23;
            uint32_t off = (uint32_t)(r0 * TSROW + (ncol + 8 * nt + 2 * (l & 3)) * 2);
            *(__half2*)(Pp + off)             = h01;
            *(__half2*)(Pp + off + 8 * TSROW) = h23;
        }
        ps0 += __shfl_xor_sync(0xffffffffu, ps0, 1);
        ps0 += __shfl_xor_sync(0xffffffffu, ps0, 2);
        ps1 += __shfl_xor_sync(0xffffffffu, ps1, 1);
        ps1 += __shfl_xor_sync(0xffffffffu, ps1, 2);
        if ((l & 3) == 0) {
            red_sm[grp * 64 + r0] = ps0;
            red_sm[grp * 64 + r1] = ps1;
        }
        __syncthreads();   // P plane + sums visible

        if (grp == 0 && (l & 3) == 0) {
            row_l[r0] = row_l[r0] * fac0 + red_sm[r0] + red_sm[64 + r0];
            row_l[r1] = row_l[r1] * fac1 + red_sm[r1] + red_sm[64 + r1];
            row_m[r0] = mn0;
            row_m[r1] = mn1;
        }

        // ---- rescale O; O += P @ Vh (2 k-steps regs, 2 from plane) ----
#pragma unroll
        for (int nt = 0; nt < 4; nt++) {
            oacc[nt][0] *= fac0; oacc[nt][1] *= fac0;
            oacc[nt][2] *= fac1; oacc[nt][3] *= fac1;
        }
#pragma unroll
        for (int ks = 0; ks < 4; ks++) {
            const uint32_t kso = (uint32_t)(ks * 32);
            uint32_t a4[4];
            if (ks == own0) {
                a4[0] = pa[0][0]; a4[1] = pa[0][1]; a4[2] = pa[0][2]; a4[3] = pa[0][3];
            } else if (ks == own0 + 1) {
                a4[0] = pa[1][0]; a4[1] = pa[1][1]; a4[2] = pa[1][2]; a4[3] = pa[1][3];
            } else {
                LDSM4(a4, sb + 2 * TPL + aRel + kso);
            }
            uint32_t vh[4][2];
#pragma unroll
            for (int jp = 0; jp < 2; jp++) {
                uint32_t r4[4];
                LDSM4(r4, sb + 3 * TPL + bRelB + jp * (16 * TSROW) + kso);
                vh[2 * jp][0] = r4[0]; vh[2 * jp][1] = r4[1];
                vh[2 * jp + 1][0] = r4[2]; vh[2 * jp + 1][1] = r4[3];
            }
#pragma unroll
            for (int nt = 0; nt < 4; nt++) mma_f16(oacc[nt], a4, vh[nt]);
        }
    }

    __syncthreads();   // final row_l updates visible

    // normalize + write single fp16 plane
    {
        float i0 = 1.f / row_l[r0];
        float i1 = 1.f / row_l[r1];
        size_t ro0 = (size_t)(b * NS + q0 + r0) * ND;
        size_t ro1 = (size_t)(b * NS + q0 + r1) * ND;
#pragma unroll
        for (int nt = 0; nt < 4; nt++) {
            int col = hh * NHD + ncol + 8 * nt + 2 * (l & 3);
            *(__half2*)&ao[ro0 + col] = __floats2half2_rn(oacc[nt][0] * i0, oacc[nt][1] * i0);
            *(__half2*)&ao[ro1 + col] = __floats2half2_rn(oacc[nt][2] * i1, oacc[nt][3] * i1);
        }
    }
}

// ---------------------------------------------------------------------------
extern "C" void kernel_launch(void* const* d_in, const int* in_sizes, int n_in,
                              void* d_out, int out_size)
{
    const float* x     = (const float*)d_in[0];
    const float* Wqkv  = (const float*)d_in[1];
    const float* bqkv  = (const float*)d_in[2];
    const float* Wout  = (const float*)d_in[3];
    const float* bout  = (const float*)d_in[4];
    const int*   layer = (const int*)d_in[5];
    float* out = (float*)d_out;

    float2* rot;
    __half *x16, *a16, *wq, *wo, *qp, *khp, *klp, *vth;
    cudaGetSymbolAddress((void**)&rot, g_rot);
    cudaGetSymbolAddress((void**)&x16, g_x16);
    cudaGetSymbolAddress((void**)&a16, g_a16);
    cudaGetSymbolAddress((void**)&wq, g_wq16);
    cudaGetSymbolAddress((void**)&wo, g_wo16);
    cudaGetSymbolAddress((void**)&qp, g_qp);
    cudaGetSymbolAddress((void**)&khp, g_kh16);
    cudaGetSymbolAddress((void**)&klp, g_kl16);
    cudaGetSymbolAddress((void**)&vth, g_vth16);

    const int gemm_smem = NSTAGE * STG;   // 98304 B
    cudaFuncSetAttribute(gemm_mma_kernel, cudaFuncAttributeMaxDynamicSharedMemorySize, gemm_smem);
    cudaFuncSetAttribute(gemm_qkv_kernel, cudaFuncAttributeMaxDynamicSharedMemorySize, gemm_smem);
    const int attn_smem = 4 * TPL + (64 * 2 + 128 * 2) * (int)sizeof(float);   // 38400 B
    cudaFuncSetAttribute(attn_mma_kernel, cudaFuncAttributeMaxDynamicSharedMemorySize, attn_smem);

    // 0) prep: x->fp16 + rot table; both weight transposes
    prep_x_rot_kernel<<<6400, 256>>>(x, x16, layer, rot);
    prep_w_kernel<<<dim3(NQKV / 32, ND / 32, 2), dim3(32, 8)>>>(Wqkv, Wout, wq, wo);

    // 1) qkv GEMM, fully fused epilogue (Q/K rope planes, V transposed plane)
    gemm_qkv_kernel<<<dim3(NQKV / 128, NROWS / 128), 256, gemm_smem>>>(
        x16, wq, bqkv, qp, khp, klp, vth, rot, NROWS, NQKV, ND);
    // 2) tensor-core banded attention (fragment-resident softmax)
    attn_mma_kernel<<<NB * NH * 32, 256, attn_smem>>>(qp, khp, klp, vth, a16, layer);
    // 3) out = attn @ Wout + bout
    gemm_mma_kernel<<<dim3(ND / 128, NROWS / 128), 256, gemm_smem>>>(
        a16, wo, bout, out, NROWS, ND, ND);
}